// round 1
// baseline (speedup 1.0000x reference)
#include <cuda_runtime.h>
#include <math.h>

#define BATCH   2
#define SEQ     2048
#define DMODEL  1024
#define NHEADS  16
#define DKV     64
#define INNER   1024
#define NTOK    (BATCH*SEQ)          // 4096
#define RBR     (2*SEQ-1)            // 4095 relative distances

// -------- scratch (device globals: no allocation allowed) --------
__device__ float g_Q[NTOK*INNER];
__device__ float g_K[NTOK*INNER];
__device__ float g_V[NTOK*INNER];
__device__ float g_C[NTOK*INNER];
__device__ float g_RB[RBR*NHEADS];   // bias per (relative distance, head)

// =============================================================
// Relative-position bias table: g_RB[(rel+SEQ-1)*NHEADS + h]
// Faithful port of T5 _relative_position_bucket (bidirectional,
// num_buckets=32 -> 16 per direction, max_exact=8, max_distance=128)
// =============================================================
__global__ void bias_table_kernel(const float* __restrict__ table)
{
    int idx = blockIdx.x * blockDim.x + threadIdx.x;
    if (idx >= RBR * NHEADS) return;
    int rel = idx / NHEADS - (SEQ - 1);   // -2047..2047  (= k - q)
    int h   = idx % NHEADS;

    int bucket = (rel > 0) ? 16 : 0;
    int rp = rel < 0 ? -rel : rel;
    int v;
    if (rp < 8) {
        v = rp;
    } else {
        // jnp: 8 + trunc( log(rp/8)/log(16) * 8 ), then min(.,15)
        float f = logf((float)rp * 0.125f) / 2.772588722239781f * 8.0f;
        v = 8 + (int)f;
        if (v > 15) v = 15;
    }
    bucket += v;
    g_RB[idx] = table[bucket * NHEADS + h];
}

// =============================================================
// SGEMM: C[M,N] = A[M,K] @ B[K,N], all row-major fp32.
// 128x128 block, BK=8, 256 threads, 8x8 per thread.
// Requires M%128==0, N%128==0, K%8==0 (true for all calls here).
// =============================================================
__global__ __launch_bounds__(256)
void sgemm_kernel(const float* __restrict__ A, const float* __restrict__ B,
                  float* __restrict__ C, int M, int N, int K)
{
    __shared__ float As[8][128];   // A transposed: As[k][m]
    __shared__ float Bs[8][128];

    const int t  = threadIdx.x;
    const int bm = blockIdx.y * 128;
    const int bn = blockIdx.x * 128;
    const int tx = t & 15;
    const int ty = t >> 4;

    const int arow = t >> 1;         // 0..127
    const int acol = (t & 1) * 4;    // 0 or 4
    const int brow = t >> 5;         // 0..7
    const int bcol = (t & 31) * 4;   // 0..124

    float acc[8][8];
    #pragma unroll
    for (int i = 0; i < 8; i++)
        #pragma unroll
        for (int j = 0; j < 8; j++) acc[i][j] = 0.0f;

    const float* Aptr = A + (long)(bm + arow) * K + acol;
    const float* Bptr = B + (long)brow * N + bn + bcol;

    for (int k0 = 0; k0 < K; k0 += 8) {
        float4 av = *(const float4*)(Aptr + k0);
        float4 bv = *(const float4*)(Bptr + (long)k0 * N);
        As[acol + 0][arow] = av.x;
        As[acol + 1][arow] = av.y;
        As[acol + 2][arow] = av.z;
        As[acol + 3][arow] = av.w;
        *(float4*)&Bs[brow][bcol] = bv;
        __syncthreads();

        #pragma unroll
        for (int kk = 0; kk < 8; kk++) {
            float ra[8], rb[8];
            *(float4*)(ra)     = *(float4*)&As[kk][ty * 8];
            *(float4*)(ra + 4) = *(float4*)&As[kk][ty * 8 + 4];
            *(float4*)(rb)     = *(float4*)&Bs[kk][tx * 8];
            *(float4*)(rb + 4) = *(float4*)&Bs[kk][tx * 8 + 4];
            #pragma unroll
            for (int i = 0; i < 8; i++)
                #pragma unroll
                for (int j = 0; j < 8; j++)
                    acc[i][j] += ra[i] * rb[j];
        }
        __syncthreads();
    }

    #pragma unroll
    for (int i = 0; i < 8; i++) {
        float* cp = C + (long)(bm + ty * 8 + i) * N + bn + tx * 8;
        *(float4*)(cp)     = make_float4(acc[i][0], acc[i][1], acc[i][2], acc[i][3]);
        *(float4*)(cp + 4) = make_float4(acc[i][4], acc[i][5], acc[i][6], acc[i][7]);
    }
}

// =============================================================
// Flash-style attention, fp32 SIMT.
// Grid: (SEQ/64, BATCH*NHEADS). Block: 256 threads (16x16).
// Each CTA: 64 q-rows of one (b,h); streams 64-key tiles.
// Thread (tx,ty) owns q rows ty*4..+3 and d/k cols tx*4..+3.
// =============================================================
#define VS_STRIDE 68   // padded strides (multiple-of-16B, bank-conflict-free)
#define PS_STRIDE 68

__global__ __launch_bounds__(256)
void attn_kernel()
{
    extern __shared__ float sm[];
    float* Qst = sm;                     // [64][64]  Qst[d][q]
    float* Kst = Qst + 64 * 64;          // [64][64]  Kst[d][k]
    float* Vs  = Kst + 64 * 64;          // [64][VS_STRIDE]  Vs[k][d]
    float* Pst = Vs  + 64 * VS_STRIDE;   // [64][PS_STRIDE]  Pst[q][k]
    float* rbs = Pst + 64 * PS_STRIDE;   // [127] bias slice

    const int t  = threadIdx.x;
    const int tx = t & 15;
    const int ty = t >> 4;
    const int bh = blockIdx.y;           // 0..31
    const int b  = bh >> 4;
    const int h  = bh & 15;
    const int q0 = blockIdx.x * 64;

    const int r  = t & 63;               // row within tile (load role)
    const int c4 = (t >> 6) * 4;         // starting col (load role)

    // ---- load Q tile transposed into Qst[d][q] ----
    {
        const float* qg = g_Q + (long)(b * SEQ + q0 + r) * INNER + h * DKV;
        #pragma unroll
        for (int i = 0; i < 4; i++) {
            int d = c4 + i * 16;
            float4 v = *(const float4*)(qg + d);
            Qst[(d + 0) * 64 + r] = v.x;
            Qst[(d + 1) * 64 + r] = v.y;
            Qst[(d + 2) * 64 + r] = v.z;
            Qst[(d + 3) * 64 + r] = v.w;
        }
    }

    float m[4], l[4], o[4][4];
    #pragma unroll
    for (int i = 0; i < 4; i++) {
        m[i] = -3.0e38f;
        l[i] = 0.0f;
        #pragma unroll
        for (int j = 0; j < 4; j++) o[i][j] = 0.0f;
    }

    for (int kt = 0; kt < SEQ / 64; kt++) {
        const int k0 = kt * 64;
        __syncthreads();   // prev PV done; safe to overwrite tiles

        // ---- load K (transposed) and V tiles ----
        {
            const float* kg = g_K + (long)(b * SEQ + k0 + r) * INNER + h * DKV;
            const float* vg = g_V + (long)(b * SEQ + k0 + r) * INNER + h * DKV;
            #pragma unroll
            for (int i = 0; i < 4; i++) {
                int d = c4 + i * 16;
                float4 kv = *(const float4*)(kg + d);
                Kst[(d + 0) * 64 + r] = kv.x;
                Kst[(d + 1) * 64 + r] = kv.y;
                Kst[(d + 2) * 64 + r] = kv.z;
                Kst[(d + 3) * 64 + r] = kv.w;
                float4 vv = *(const float4*)(vg + d);
                *(float4*)&Vs[r * VS_STRIDE + d] = vv;
            }
        }
        // bias slice: rel = (k0-q0) + (t-63), t in [0,126]
        if (t < 127) {
            int rel = (k0 - q0) + t - 63;
            rbs[t] = g_RB[(rel + SEQ - 1) * NHEADS + h];
        }
        __syncthreads();

        // ---- S = Q @ K^T + bias (4x4 micro-tile) ----
        float s[4][4];
        #pragma unroll
        for (int i = 0; i < 4; i++)
            #pragma unroll
            for (int j = 0; j < 4; j++) s[i][j] = 0.0f;

        #pragma unroll 16
        for (int d = 0; d < 64; d++) {
            float a[4], bb[4];
            *(float4*)a  = *(float4*)&Qst[d * 64 + ty * 4];
            *(float4*)bb = *(float4*)&Kst[d * 64 + tx * 4];
            #pragma unroll
            for (int i = 0; i < 4; i++)
                #pragma unroll
                for (int j = 0; j < 4; j++)
                    s[i][j] += a[i] * bb[j];
        }
        #pragma unroll
        for (int i = 0; i < 4; i++)
            #pragma unroll
            for (int j = 0; j < 4; j++)
                s[i][j] += rbs[(tx * 4 + j) - (ty * 4 + i) + 63];

        // ---- online softmax (row stats reduced over the 16 tx lanes) ----
        #pragma unroll
        for (int i = 0; i < 4; i++) {
            float tm = fmaxf(fmaxf(s[i][0], s[i][1]), fmaxf(s[i][2], s[i][3]));
            #pragma unroll
            for (int msk = 8; msk >= 1; msk >>= 1)
                tm = fmaxf(tm, __shfl_xor_sync(0xffffffffu, tm, msk, 16));
            float newm  = fmaxf(m[i], tm);
            float scale = expf(m[i] - newm);
            float ls = 0.0f;
            #pragma unroll
            for (int j = 0; j < 4; j++) {
                s[i][j] = expf(s[i][j] - newm);
                ls += s[i][j];
            }
            #pragma unroll
            for (int msk = 8; msk >= 1; msk >>= 1)
                ls += __shfl_xor_sync(0xffffffffu, ls, msk, 16);
            l[i] = l[i] * scale + ls;
            m[i] = newm;
            #pragma unroll
            for (int j = 0; j < 4; j++) o[i][j] *= scale;
        }

        // ---- stage P into smem, then O += P @ V ----
        #pragma unroll
        for (int i = 0; i < 4; i++)
            *(float4*)&Pst[(ty * 4 + i) * PS_STRIDE + tx * 4] =
                make_float4(s[i][0], s[i][1], s[i][2], s[i][3]);
        __syncthreads();

        #pragma unroll 8
        for (int k = 0; k < 64; k++) {
            float a[4], bb[4];
            #pragma unroll
            for (int i = 0; i < 4; i++)
                a[i] = Pst[(ty * 4 + i) * PS_STRIDE + k];
            *(float4*)bb = *(float4*)&Vs[k * VS_STRIDE + tx * 4];
            #pragma unroll
            for (int i = 0; i < 4; i++)
                #pragma unroll
                for (int j = 0; j < 4; j++)
                    o[i][j] += a[i] * bb[j];
        }
    }

    // ---- normalize and write ctx (layout [B,S,H*DKV]) ----
    #pragma unroll
    for (int i = 0; i < 4; i++) {
        float inv = 1.0f / l[i];
        float* cp = g_C + (long)(b * SEQ + q0 + ty * 4 + i) * INNER + h * DKV + tx * 4;
        *(float4*)cp = make_float4(o[i][0] * inv, o[i][1] * inv,
                                   o[i][2] * inv, o[i][3] * inv);
    }
}

// =============================================================
// Host launcher
// =============================================================
extern "C" void kernel_launch(void* const* d_in, const int* in_sizes, int n_in,
                              void* d_out, int out_size)
{
    const float* X   = (const float*)d_in[0];  // hidden_states [2,2048,1024]
    const float* wq  = (const float*)d_in[1];  // [1024,1024]
    const float* wk  = (const float*)d_in[2];
    const float* wv  = (const float*)d_in[3];
    const float* wo  = (const float*)d_in[4];
    const float* rbt = (const float*)d_in[5];  // [32,16]
    float* out = (float*)d_out;                // [2,2048,1024]

    float *Q, *K, *V, *C;
    cudaGetSymbolAddress((void**)&Q, g_Q);
    cudaGetSymbolAddress((void**)&K, g_K);
    cudaGetSymbolAddress((void**)&V, g_V);
    cudaGetSymbolAddress((void**)&C, g_C);

    // bias table (cheap, recomputed every call for determinism)
    bias_table_kernel<<<(RBR * NHEADS + 255) / 256, 256>>>(rbt);

    // QKV projections
    dim3 gp(INNER / 128, NTOK / 128);
    sgemm_kernel<<<gp, 256>>>(X, wq, Q, NTOK, INNER, DMODEL);
    sgemm_kernel<<<gp, 256>>>(X, wk, K, NTOK, INNER, DMODEL);
    sgemm_kernel<<<gp, 256>>>(X, wv, V, NTOK, INNER, DMODEL);

    // attention
    const int smem_bytes = (64 * 64 * 2 + 64 * VS_STRIDE + 64 * PS_STRIDE + 128)
                           * (int)sizeof(float);
    cudaFuncSetAttribute(attn_kernel,
                         cudaFuncAttributeMaxDynamicSharedMemorySize, smem_bytes);
    attn_kernel<<<dim3(SEQ / 64, BATCH * NHEADS), 256, smem_bytes>>>();

    // output projection
    dim3 go(DMODEL / 128, NTOK / 128);
    sgemm_kernel<<<go, 256>>>(C, wo, out, NTOK, DMODEL, INNER);
}

// round 3
// speedup vs baseline: 1.4225x; 1.4225x over previous
#include <cuda_runtime.h>
#include <math.h>
#include <stdint.h>

#define BATCH   2
#define SEQ     2048
#define DMODEL  1024
#define NHEADS  16
#define DKV     64
#define INNER   1024
#define NTOK    (BATCH*SEQ)          // 4096
#define RBR     (2*SEQ-1)            // 4095

// -------- scratch (device globals: no allocation allowed) --------
__device__ float g_Q[NTOK*INNER];
__device__ float g_K[NTOK*INNER];
__device__ float g_V[NTOK*INNER];
__device__ float g_C[NTOK*INNER];
__device__ float g_X[NTOK*DMODEL];       // tf32-rounded hidden states
__device__ float g_WT[4*DMODEL*INNER];   // transposed + tf32-rounded weights
__device__ float g_RB[RBR*NHEADS];

// ============================================================
// helpers
// ============================================================
__device__ __forceinline__ uint32_t smem_u32(const void* p) {
    uint32_t a;
    asm("{ .reg .u64 t; cvta.to.shared.u64 t, %1; cvt.u32.u64 %0, t; }" : "=r"(a) : "l"(p));
    return a;
}
__device__ __forceinline__ float tf32_rna(float x) {
    uint32_t r; asm("cvt.rna.tf32.f32 %0, %1;" : "=r"(r) : "f"(x));
    return __uint_as_float(r);
}
__device__ __forceinline__ void cp_async16(uint32_t dst, const void* src) {
    asm volatile("cp.async.cg.shared.global [%0], [%1], 16;\n" :: "r"(dst), "l"(src) : "memory");
}
#define CP_ASYNC_COMMIT() asm volatile("cp.async.commit_group;\n" ::: "memory")
#define CP_ASYNC_WAIT(n)  asm volatile("cp.async.wait_group %0;\n" :: "n"(n) : "memory")

__device__ __forceinline__ void ldmatrix_x4(uint32_t* r, uint32_t addr) {
    asm volatile("ldmatrix.sync.aligned.m8n8.x4.shared.b16 {%0,%1,%2,%3}, [%4];"
                 : "=r"(r[0]), "=r"(r[1]), "=r"(r[2]), "=r"(r[3]) : "r"(addr));
}
__device__ __forceinline__ void mma_tf32(float* d, const uint32_t* a, const uint32_t* b) {
    asm volatile(
        "mma.sync.aligned.m16n8k8.row.col.f32.tf32.tf32.f32 "
        "{%0,%1,%2,%3}, {%4,%5,%6,%7}, {%8,%9}, {%0,%1,%2,%3};"
        : "+f"(d[0]), "+f"(d[1]), "+f"(d[2]), "+f"(d[3])
        : "r"(a[0]), "r"(a[1]), "r"(a[2]), "r"(a[3]), "r"(b[0]), "r"(b[1]));
}

// =============================================================
// Pre-processing kernels
// =============================================================
__global__ void round_tf32_kernel(const float4* __restrict__ in, float4* __restrict__ out, int n4)
{
    int i = blockIdx.x * blockDim.x + threadIdx.x;
    if (i < n4) {
        float4 v = in[i];
        out[i] = make_float4(tf32_rna(v.x), tf32_rna(v.y), tf32_rna(v.z), tf32_rna(v.w));
    }
}

// out[n][k] = rna(in[k][n]), 1024x1024
__global__ void transpose_rna_kernel(const float* __restrict__ in, float* __restrict__ out)
{
    __shared__ float tile[32][33];
    int bx = blockIdx.x * 32, by = blockIdx.y * 32;
    int x = bx + threadIdx.x;
    #pragma unroll
    for (int i = 0; i < 32; i += 8)
        tile[threadIdx.y + i][threadIdx.x] = in[(by + threadIdx.y + i) * DMODEL + x];
    __syncthreads();
    x = by + threadIdx.x;
    #pragma unroll
    for (int i = 0; i < 32; i += 8)
        out[(bx + threadIdx.y + i) * DMODEL + x] = tf32_rna(tile[threadIdx.x][threadIdx.y + i]);
}

__global__ void bias_table_kernel(const float* __restrict__ table)
{
    int idx = blockIdx.x * blockDim.x + threadIdx.x;
    if (idx >= RBR * NHEADS) return;
    int rel = idx / NHEADS - (SEQ - 1);
    int h   = idx % NHEADS;
    int bucket = (rel > 0) ? 16 : 0;
    int rp = rel < 0 ? -rel : rel;
    int v;
    if (rp < 8) {
        v = rp;
    } else {
        float f = logf((float)rp * 0.125f) / 2.772588722239781f * 8.0f;
        v = 8 + (int)f;
        if (v > 15) v = 15;
    }
    g_RB[idx] = table[(bucket + v) * NHEADS + h];
}

// =============================================================
// tf32 mma.sync GEMM: C[M,1024] = A[M,1024] @ B^T, B is K-major
// WT[n][k]. CTA tile 128x128, BK=16, 256 threads (8 warps 2x4),
// warp tile 64x32, m16n8k8 fragments, 2-stage cp.async pipeline.
// =============================================================
#define BK 16
#define APAD 20                 // floats per smem row (16 + 4 pad)
#define TILE_FLOATS (128 * APAD)
#define NITER (DMODEL / BK)     // 64

__global__ __launch_bounds__(256)
void tf32_gemm_kernel(const float* __restrict__ A, const float* __restrict__ B,
                      float* __restrict__ C)
{
    __shared__ float sA[2][TILE_FLOATS];
    __shared__ float sB[2][TILE_FLOATS];

    const int tid  = threadIdx.x;
    const int wid  = tid >> 5;
    const int lane = tid & 31;
    const int wr   = wid & 1;        // warp row: 2 x 64
    const int wc   = wid >> 1;       // warp col: 4 x 32
    const long bm  = blockIdx.y * 128;
    const long bn  = blockIdx.x * 128;

    const uint32_t sA0 = smem_u32(&sA[0][0]);
    const uint32_t sB0 = smem_u32(&sB[0][0]);

    float acc[4][4][4];
    #pragma unroll
    for (int i = 0; i < 4; i++)
        #pragma unroll
        for (int j = 0; j < 4; j++)
            #pragma unroll
            for (int k = 0; k < 4; k++) acc[i][j][k] = 0.0f;

    // per-iteration loader: 4 x cp.async16 per thread
    auto load_tiles = [&](int it, int stage) {
        int k0 = it * BK;
        uint32_t da = sA0 + stage * (TILE_FLOATS * 4);
        uint32_t db = sB0 + stage * (TILE_FLOATS * 4);
        #pragma unroll
        for (int i = 0; i < 2; i++) {
            int idx = tid + i * 256;       // 0..511
            int row = idx >> 2;            // 0..127
            int c4  = idx & 3;             // 16B chunk
            uint32_t off = row * (APAD * 4) + c4 * 16;
            cp_async16(da + off, A + (bm + row) * DMODEL + k0 + c4 * 4);
            cp_async16(db + off, B + (bn + row) * DMODEL + k0 + c4 * 4);
        }
        CP_ASYNC_COMMIT();
    };

    // ldmatrix source row/col for A fragments (per lane, tile-invariant part)
    const int lrow = (lane & 7) + ((lane & 8) ? 8 : 0);   // row within 16
    const int lcol = (lane & 16) ? 4 : 0;                 // k offset within 8

    load_tiles(0, 0);

    for (int it = 0; it < NITER; it++) {
        const int buf = it & 1;
        if (it + 1 < NITER) { load_tiles(it + 1, buf ^ 1); CP_ASYNC_WAIT(1); }
        else                { CP_ASYNC_WAIT(0); }
        __syncthreads();

        const uint32_t ab = sA0 + buf * (TILE_FLOATS * 4);
        const float*  Bs  = &sB[buf][0];

        #pragma unroll
        for (int kk = 0; kk < BK; kk += 8) {
            uint32_t afrag[4][4];
            #pragma unroll
            for (int mt = 0; mt < 4; mt++) {
                int m = wr * 64 + mt * 16 + lrow;
                ldmatrix_x4(afrag[mt], ab + (m * APAD + kk + lcol) * 4);
            }
            uint32_t bfrag[4][2];
            #pragma unroll
            for (int nt = 0; nt < 4; nt++) {
                int n = wc * 32 + nt * 8 + (lane >> 2);
                bfrag[nt][0] = __float_as_uint(Bs[n * APAD + kk + (lane & 3)]);
                bfrag[nt][1] = __float_as_uint(Bs[n * APAD + kk + 4 + (lane & 3)]);
            }
            #pragma unroll
            for (int mt = 0; mt < 4; mt++)
                #pragma unroll
                for (int nt = 0; nt < 4; nt++)
                    mma_tf32(acc[mt][nt], afrag[mt], bfrag[nt]);
        }
        __syncthreads();
    }

    // epilogue: C fragment -> gmem (float2 stores)
    #pragma unroll
    for (int mt = 0; mt < 4; mt++) {
        long m0 = bm + wr * 64 + mt * 16 + (lane >> 2);
        #pragma unroll
        for (int nt = 0; nt < 4; nt++) {
            long n0 = bn + wc * 32 + nt * 8 + (lane & 3) * 2;
            *(float2*)(C + m0 * 1024 + n0)       = make_float2(acc[mt][nt][0], acc[mt][nt][1]);
            *(float2*)(C + (m0 + 8) * 1024 + n0) = make_float2(acc[mt][nt][2], acc[mt][nt][3]);
        }
    }
}

// =============================================================
// Flash-style attention, fp32 SIMT (tf32-rounded epilogue so the
// O-projection GEMM sees exactly-representable tf32 inputs).
// =============================================================
#define VS_STRIDE 68
#define PS_STRIDE 68

__global__ __launch_bounds__(256)
void attn_kernel()
{
    extern __shared__ float sm[];
    float* Qst = sm;
    float* Kst = Qst + 64 * 64;
    float* Vs  = Kst + 64 * 64;
    float* Pst = Vs  + 64 * VS_STRIDE;
    float* rbs = Pst + 64 * PS_STRIDE;

    const int t  = threadIdx.x;
    const int tx = t & 15;
    const int ty = t >> 4;
    const int bh = blockIdx.y;
    const int b  = bh >> 4;
    const int h  = bh & 15;
    const int q0 = blockIdx.x * 64;

    const int r  = t & 63;
    const int c4 = (t >> 6) * 4;

    {
        const float* qg = g_Q + (long)(b * SEQ + q0 + r) * INNER + h * DKV;
        #pragma unroll
        for (int i = 0; i < 4; i++) {
            int d = c4 + i * 16;
            float4 v = *(const float4*)(qg + d);
            Qst[(d + 0) * 64 + r] = v.x;
            Qst[(d + 1) * 64 + r] = v.y;
            Qst[(d + 2) * 64 + r] = v.z;
            Qst[(d + 3) * 64 + r] = v.w;
        }
    }

    float m[4], l[4], o[4][4];
    #pragma unroll
    for (int i = 0; i < 4; i++) {
        m[i] = -3.0e38f;
        l[i] = 0.0f;
        #pragma unroll
        for (int j = 0; j < 4; j++) o[i][j] = 0.0f;
    }

    for (int kt = 0; kt < SEQ / 64; kt++) {
        const int k0 = kt * 64;
        __syncthreads();

        {
            const float* kg = g_K + (long)(b * SEQ + k0 + r) * INNER + h * DKV;
            const float* vg = g_V + (long)(b * SEQ + k0 + r) * INNER + h * DKV;
            #pragma unroll
            for (int i = 0; i < 4; i++) {
                int d = c4 + i * 16;
                float4 kv = *(const float4*)(kg + d);
                Kst[(d + 0) * 64 + r] = kv.x;
                Kst[(d + 1) * 64 + r] = kv.y;
                Kst[(d + 2) * 64 + r] = kv.z;
                Kst[(d + 3) * 64 + r] = kv.w;
                float4 vv = *(const float4*)(vg + d);
                *(float4*)&Vs[r * VS_STRIDE + d] = vv;
            }
        }
        if (t < 127) {
            int rel = (k0 - q0) + t - 63;
            rbs[t] = g_RB[(rel + SEQ - 1) * NHEADS + h];
        }
        __syncthreads();

        float s[4][4];
        #pragma unroll
        for (int i = 0; i < 4; i++)
            #pragma unroll
            for (int j = 0; j < 4; j++) s[i][j] = 0.0f;

        #pragma unroll 16
        for (int d = 0; d < 64; d++) {
            float a[4], bb[4];
            *(float4*)a  = *(float4*)&Qst[d * 64 + ty * 4];
            *(float4*)bb = *(float4*)&Kst[d * 64 + tx * 4];
            #pragma unroll
            for (int i = 0; i < 4; i++)
                #pragma unroll
                for (int j = 0; j < 4; j++)
                    s[i][j] += a[i] * bb[j];
        }
        #pragma unroll
        for (int i = 0; i < 4; i++)
            #pragma unroll
            for (int j = 0; j < 4; j++)
                s[i][j] += rbs[(tx * 4 + j) - (ty * 4 + i) + 63];

        #pragma unroll
        for (int i = 0; i < 4; i++) {
            float tm = fmaxf(fmaxf(s[i][0], s[i][1]), fmaxf(s[i][2], s[i][3]));
            #pragma unroll
            for (int msk = 8; msk >= 1; msk >>= 1)
                tm = fmaxf(tm, __shfl_xor_sync(0xffffffffu, tm, msk, 16));
            float newm  = fmaxf(m[i], tm);
            float scale = expf(m[i] - newm);
            float ls = 0.0f;
            #pragma unroll
            for (int j = 0; j < 4; j++) {
                s[i][j] = expf(s[i][j] - newm);
                ls += s[i][j];
            }
            #pragma unroll
            for (int msk = 8; msk >= 1; msk >>= 1)
                ls += __shfl_xor_sync(0xffffffffu, ls, msk, 16);
            l[i] = l[i] * scale + ls;
            m[i] = newm;
            #pragma unroll
            for (int j = 0; j < 4; j++) o[i][j] *= scale;
        }

        #pragma unroll
        for (int i = 0; i < 4; i++)
            *(float4*)&Pst[(ty * 4 + i) * PS_STRIDE + tx * 4] =
                make_float4(s[i][0], s[i][1], s[i][2], s[i][3]);
        __syncthreads();

        #pragma unroll 8
        for (int k = 0; k < 64; k++) {
            float a[4], bb[4];
            #pragma unroll
            for (int i = 0; i < 4; i++)
                a[i] = Pst[(ty * 4 + i) * PS_STRIDE + k];
            *(float4*)bb = *(float4*)&Vs[k * VS_STRIDE + tx * 4];
            #pragma unroll
            for (int i = 0; i < 4; i++)
                #pragma unroll
                for (int j = 0; j < 4; j++)
                    o[i][j] += a[i] * bb[j];
        }
    }

    #pragma unroll
    for (int i = 0; i < 4; i++) {
        float inv = 1.0f / l[i];
        float* cp = g_C + (long)(b * SEQ + q0 + ty * 4 + i) * INNER + h * DKV + tx * 4;
        *(float4*)cp = make_float4(tf32_rna(o[i][0] * inv), tf32_rna(o[i][1] * inv),
                                   tf32_rna(o[i][2] * inv), tf32_rna(o[i][3] * inv));
    }
}

// =============================================================
// Host launcher
// =============================================================
extern "C" void kernel_launch(void* const* d_in, const int* in_sizes, int n_in,
                              void* d_out, int out_size)
{
    const float* X   = (const float*)d_in[0];
    const float* wq  = (const float*)d_in[1];
    const float* wk  = (const float*)d_in[2];
    const float* wv  = (const float*)d_in[3];
    const float* wo  = (const float*)d_in[4];
    const float* rbt = (const float*)d_in[5];
    float* out = (float*)d_out;

    float *Q, *K, *V, *C, *Xr, *WT;
    cudaGetSymbolAddress((void**)&Q,  g_Q);
    cudaGetSymbolAddress((void**)&K,  g_K);
    cudaGetSymbolAddress((void**)&V,  g_V);
    cudaGetSymbolAddress((void**)&C,  g_C);
    cudaGetSymbolAddress((void**)&Xr, g_X);
    cudaGetSymbolAddress((void**)&WT, g_WT);

    // pre-processing
    bias_table_kernel<<<(RBR * NHEADS + 255) / 256, 256>>>(rbt);
    round_tf32_kernel<<<(NTOK * DMODEL / 4 + 255) / 256, 256>>>(
        (const float4*)X, (float4*)Xr, NTOK * DMODEL / 4);
    dim3 tb(32, 8), tg(32, 32);
    transpose_rna_kernel<<<tg, tb>>>(wq, WT + 0l * DMODEL * INNER);
    transpose_rna_kernel<<<tg, tb>>>(wk, WT + 1l * DMODEL * INNER);
    transpose_rna_kernel<<<tg, tb>>>(wv, WT + 2l * DMODEL * INNER);
    transpose_rna_kernel<<<tg, tb>>>(wo, WT + 3l * DMODEL * INNER);

    // tf32 tensor-core projections
    dim3 gg(INNER / 128, NTOK / 128);   // (8, 32)
    tf32_gemm_kernel<<<gg, 256>>>(Xr, WT + 0l * DMODEL * INNER, Q);
    tf32_gemm_kernel<<<gg, 256>>>(Xr, WT + 1l * DMODEL * INNER, K);
    tf32_gemm_kernel<<<gg, 256>>>(Xr, WT + 2l * DMODEL * INNER, V);

    // attention (fp32 SIMT)
    const int smem_bytes = (64 * 64 * 2 + 64 * VS_STRIDE + 64 * PS_STRIDE + 128)
                           * (int)sizeof(float);
    cudaFuncSetAttribute(attn_kernel,
                         cudaFuncAttributeMaxDynamicSharedMemorySize, smem_bytes);
    attn_kernel<<<dim3(SEQ / 64, BATCH * NHEADS), 256, smem_bytes>>>();

    // output projection
    tf32_gemm_kernel<<<gg, 256>>>(C, WT + 3l * DMODEL * INNER, out);
}

// round 4
// speedup vs baseline: 2.4349x; 1.7117x over previous
#include <cuda_runtime.h>
#include <cuda_fp16.h>
#include <math.h>
#include <stdint.h>

#define BATCH   2
#define SEQ     2048
#define DMODEL  1024
#define NHEADS  16
#define DKV     64
#define INNER   1024
#define NTOK    (BATCH*SEQ)          // 4096
#define RBR     (2*SEQ-1)            // 4095

// -------- scratch (device globals: no allocation allowed) --------
__device__ __half g_Xhi[NTOK*DMODEL],  g_Xlo[NTOK*DMODEL];
__device__ __half g_Whi[4*DMODEL*INNER], g_Wlo[4*DMODEL*INNER];
__device__ __half g_Qhi[NTOK*INNER],  g_Qlo[NTOK*INNER];
__device__ __half g_Khi[NTOK*INNER],  g_Klo[NTOK*INNER];
__device__ __half g_Vthi[NTOK*INNER], g_Vtlo[NTOK*INNER];   // transposed [n][token]
__device__ __half g_Chi[NTOK*INNER],  g_Clo[NTOK*INNER];
__device__ float  g_RB[RBR*NHEADS];

// ============================================================
// helpers
// ============================================================
__device__ __forceinline__ uint32_t smem_u32(const void* p) {
    uint32_t a;
    asm("{ .reg .u64 t; cvta.to.shared.u64 t, %1; cvt.u32.u64 %0, t; }" : "=r"(a) : "l"(p));
    return a;
}
__device__ __forceinline__ void cp_async16(uint32_t dst, const void* src) {
    asm volatile("cp.async.cg.shared.global [%0], [%1], 16;\n" :: "r"(dst), "l"(src) : "memory");
}
#define CP_ASYNC_COMMIT() asm volatile("cp.async.commit_group;\n" ::: "memory")
#define CP_ASYNC_WAIT(n)  asm volatile("cp.async.wait_group %0;\n" :: "n"(n) : "memory")

__device__ __forceinline__ void ldmatrix_x4(uint32_t* r, uint32_t addr) {
    asm volatile("ldmatrix.sync.aligned.m8n8.x4.shared.b16 {%0,%1,%2,%3}, [%4];"
                 : "=r"(r[0]), "=r"(r[1]), "=r"(r[2]), "=r"(r[3]) : "r"(addr));
}
__device__ __forceinline__ void mma_f16(float* d, const uint32_t* a, const uint32_t* b) {
    asm volatile(
        "mma.sync.aligned.m16n8k16.row.col.f32.f16.f16.f32 "
        "{%0,%1,%2,%3}, {%4,%5,%6,%7}, {%8,%9}, {%0,%1,%2,%3};"
        : "+f"(d[0]), "+f"(d[1]), "+f"(d[2]), "+f"(d[3])
        : "r"(a[0]), "r"(a[1]), "r"(a[2]), "r"(a[3]), "r"(b[0]), "r"(b[1]));
}
// split fp32 pair -> packed half2 (hi) + packed half2 (lo residual)
__device__ __forceinline__ void split2(float f0, float f1, uint32_t& hi, uint32_t& lo) {
    __half h0 = __float2half_rn(f0), h1 = __float2half_rn(f1);
    __half l0 = __float2half_rn(f0 - __half2float(h0));
    __half l1 = __float2half_rn(f1 - __half2float(h1));
    hi = (uint32_t)__half_as_ushort(h0) | ((uint32_t)__half_as_ushort(h1) << 16);
    lo = (uint32_t)__half_as_ushort(l0) | ((uint32_t)__half_as_ushort(l1) << 16);
}

// =============================================================
// Pre-processing
// =============================================================
__global__ void split_kernel(const float4* __restrict__ in,
                             __half* __restrict__ hi, __half* __restrict__ lo, int n4)
{
    int i = blockIdx.x * blockDim.x + threadIdx.x;
    if (i < n4) {
        float4 v = in[i];
        uint32_t h0, l0, h1, l1;
        split2(v.x, v.y, h0, l0);
        split2(v.z, v.w, h1, l1);
        *(uint2*)(hi + 4l * i) = make_uint2(h0, h1);
        *(uint2*)(lo + 4l * i) = make_uint2(l0, l1);
    }
}

// out_hi/lo[n][k] = split(in[k][n]), 1024x1024
__global__ void transpose_split_kernel(const float* __restrict__ in,
                                       __half* __restrict__ hi, __half* __restrict__ lo)
{
    __shared__ float tile[32][33];
    int bx = blockIdx.x * 32, by = blockIdx.y * 32;
    int x = bx + threadIdx.x;
    #pragma unroll
    for (int i = 0; i < 32; i += 8)
        tile[threadIdx.y + i][threadIdx.x] = in[(by + threadIdx.y + i) * DMODEL + x];
    __syncthreads();
    x = by + threadIdx.x;
    #pragma unroll
    for (int i = 0; i < 32; i += 8) {
        float v = tile[threadIdx.x][threadIdx.y + i];
        __half h = __float2half_rn(v);
        __half l = __float2half_rn(v - __half2float(h));
        long idx = (long)(bx + threadIdx.y + i) * DMODEL + x;
        hi[idx] = h;
        lo[idx] = l;
    }
}

__global__ void bias_table_kernel(const float* __restrict__ table)
{
    int idx = blockIdx.x * blockDim.x + threadIdx.x;
    if (idx >= RBR * NHEADS) return;
    int rel = idx / NHEADS - (SEQ - 1);
    int h   = idx % NHEADS;
    int bucket = (rel > 0) ? 16 : 0;
    int rp = rel < 0 ? -rel : rel;
    int v;
    if (rp < 8) {
        v = rp;
    } else {
        float f = logf((float)rp * 0.125f) / 2.772588722239781f * 8.0f;
        v = 8 + (int)f;
        if (v > 15) v = 15;
    }
    g_RB[idx] = table[(bucket + v) * NHEADS + h];
}

// =============================================================
// fp16-split GEMM: C[M,1024] = A[M,1024] @ B^T  (B K-major [n][k])
// 3-MMA emulation (hihi + hilo + lohi) ~ fp32 accuracy.
// CTA 128x128, BK=16, 256 thr (8 warps 2x4), warp tile 64x32.
// MODE: 0 = half hi/lo out [m][n];  1 = half hi/lo out transposed [n][m];
//       2 = float out [m][n]
// =============================================================
#define HPAD 24                    // halfs per smem row (16 + 8 pad, 48B)
#define HTILE (128 * HPAD)         // halfs per tile per stage (3072)
#define HGEMM_SMEM (8 * HTILE * 2) // bytes: 4 tiles x 2 stages x 6144B = 49152

template<int MODE>
__global__ __launch_bounds__(256)
void hgemm_kernel(const __half* __restrict__ Ahi, const __half* __restrict__ Alo,
                  const __half* __restrict__ Bhi, const __half* __restrict__ Blo,
                  __half* __restrict__ Chi, __half* __restrict__ Clo,
                  float* __restrict__ Cf)
{
    extern __shared__ __half hsm[];
    // half-index regions (2 stages each of HTILE): Ahi 0, Alo 6144, Bhi 12288, Blo 18432
    const int tid  = threadIdx.x;
    const int wid  = tid >> 5;
    const int lane = tid & 31;
    const int wr   = wid & 1;
    const int wc   = wid >> 1;
    const long bm  = blockIdx.y * 128;
    const long bn  = blockIdx.x * 128;
    const uint32_t s0 = smem_u32(hsm);

    float acc[4][4][4];
    #pragma unroll
    for (int i = 0; i < 4; i++)
        #pragma unroll
        for (int j = 0; j < 4; j++)
            #pragma unroll
            for (int k = 0; k < 4; k++) acc[i][j][k] = 0.0f;

    auto load_tiles = [&](int it, int stage) {
        int k0 = it * 16;
        int row = tid >> 1, c = tid & 1;
        uint32_t off = stage * (HTILE * 2) + row * (HPAD * 2) + c * 16;  // bytes
        long asrc = (bm + row) * (long)DMODEL + k0 + c * 8;
        long bsrc = (bn + row) * (long)DMODEL + k0 + c * 8;
        cp_async16(s0 + off,         Ahi + asrc);
        cp_async16(s0 + 12288 + off, Alo + asrc);
        cp_async16(s0 + 24576 + off, Bhi + bsrc);
        cp_async16(s0 + 36864 + off, Blo + bsrc);
        CP_ASYNC_COMMIT();
    };

    const int lrow  = lane & 15;
    const int lcolB = (lane >= 16) ? 16 : 0;   // +8 halfs for k-high matrices

    load_tiles(0, 0);

    for (int it = 0; it < DMODEL / 16; it++) {
        const int buf = it & 1;
        if (it + 1 < DMODEL / 16) { load_tiles(it + 1, buf ^ 1); CP_ASYNC_WAIT(1); }
        else                      { CP_ASYNC_WAIT(0); }
        __syncthreads();

        const uint32_t ah = s0 + buf * (HTILE * 2);
        const uint32_t al = ah + 12288;
        const __half*  bh = hsm + buf * HTILE + 12288;
        const __half*  bl = hsm + buf * HTILE + 18432;

        uint32_t afh[4][4], afl[4][4];
        #pragma unroll
        for (int mt = 0; mt < 4; mt++) {
            int m = wr * 64 + mt * 16 + lrow;
            ldmatrix_x4(afh[mt], ah + m * (HPAD * 2) + lcolB);
            ldmatrix_x4(afl[mt], al + m * (HPAD * 2) + lcolB);
        }
        uint32_t bfh[4][2], bfl[4][2];
        #pragma unroll
        for (int nt = 0; nt < 4; nt++) {
            int n = wc * 32 + nt * 8 + (lane >> 2);
            int o = n * HPAD + (lane & 3) * 2;
            bfh[nt][0] = *(const uint32_t*)(bh + o);
            bfh[nt][1] = *(const uint32_t*)(bh + o + 8);
            bfl[nt][0] = *(const uint32_t*)(bl + o);
            bfl[nt][1] = *(const uint32_t*)(bl + o + 8);
        }
        #pragma unroll
        for (int mt = 0; mt < 4; mt++)
            #pragma unroll
            for (int nt = 0; nt < 4; nt++) {
                mma_f16(acc[mt][nt], afh[mt], bfh[nt]);
                mma_f16(acc[mt][nt], afh[mt], bfl[nt]);
                mma_f16(acc[mt][nt], afl[mt], bfh[nt]);
            }
        __syncthreads();
    }

    // epilogue
    #pragma unroll
    for (int mt = 0; mt < 4; mt++) {
        long m0 = bm + wr * 64 + mt * 16 + (lane >> 2);
        #pragma unroll
        for (int nt = 0; nt < 4; nt++) {
            long n0 = bn + wc * 32 + nt * 8 + (lane & 3) * 2;
            float* a = acc[mt][nt];
            if (MODE == 2) {
                *(float2*)(Cf + m0 * INNER + n0)       = make_float2(a[0], a[1]);
                *(float2*)(Cf + (m0 + 8) * INNER + n0) = make_float2(a[2], a[3]);
            } else if (MODE == 0) {
                uint32_t h, l;
                split2(a[0], a[1], h, l);
                *(uint32_t*)(Chi + m0 * INNER + n0) = h;
                *(uint32_t*)(Clo + m0 * INNER + n0) = l;
                split2(a[2], a[3], h, l);
                *(uint32_t*)(Chi + (m0 + 8) * INNER + n0) = h;
                *(uint32_t*)(Clo + (m0 + 8) * INNER + n0) = l;
            } else {   // MODE 1: transposed output [n][m]
                #pragma unroll
                for (int e = 0; e < 4; e++) {
                    long m = m0 + ((e >= 2) ? 8 : 0);
                    long n = n0 + (e & 1);
                    __half h = __float2half_rn(a[e]);
                    __half l = __float2half_rn(a[e] - __half2float(h));
                    Chi[n * NTOK + m] = h;
                    Clo[n * NTOK + m] = l;
                }
            }
        }
    }
}

// =============================================================
// fp16-split flash attention.
// Grid (SEQ/128, 32), 256 thr (8 warps). Warp tile 16q x 64k.
// Q frags held in registers for all 32 k-tiles; V pre-transposed.
// S fragment layout == PV A-fragment layout (no smem for P).
// =============================================================
#define KSTAGE 36864                 // bytes per K/V stage (Khi,Klo,Vhi,Vlo x 9216)
#define ATT_SMEM (2*KSTAGE + 191*4)  // + bias slice
#define KROWB 144                    // bytes per smem row (64 halfs + pad, 72 halfs)

__global__ __launch_bounds__(256)
void attn_kernel(const __half* __restrict__ Qhi, const __half* __restrict__ Qlo,
                 const __half* __restrict__ Khi, const __half* __restrict__ Klo,
                 const __half* __restrict__ Vthi, const __half* __restrict__ Vtlo,
                 __half* __restrict__ Chi, __half* __restrict__ Clo)
{
    extern __shared__ char smraw[];
    float* rbs = (float*)(smraw + 2 * KSTAGE);
    const int tid  = threadIdx.x;
    const int w    = tid >> 5;
    const int lane = tid & 31;
    const int bh   = blockIdx.y;
    const int b    = bh >> 4;
    const int h    = bh & 15;
    const int q0   = blockIdx.x * 128;
    const uint32_t sb = smem_u32(smraw);
    const int grow = lane >> 2;
    const int gc   = (lane & 3) * 2;

    auto load_kv = [&](int t, int stage) {
        int k0 = t * 64;
        uint32_t sbase = sb + stage * KSTAGE;
        #pragma unroll
        for (int i = 0; i < 8; i++) {
            int id  = tid + i * 256;
            int sel = id >> 9;            // 0 Khi, 1 Klo, 2 Vhi, 3 Vlo
            int wi  = id & 511;
            int row = wi >> 3, c = wi & 7;
            uint32_t dst = sbase + sel * 9216 + row * KROWB + c * 16;
            const __half* src;
            if (sel < 2) {
                const __half* base = sel ? Klo : Khi;
                src = base + (long)(b * SEQ + k0 + row) * INNER + h * DKV + c * 8;
            } else {
                const __half* base = (sel == 3) ? Vtlo : Vthi;
                src = base + (long)(h * DKV + row) * NTOK + b * SEQ + k0 + c * 8;
            }
            cp_async16(dst, src);
        }
        CP_ASYNC_COMMIT();
    };

    // ---- prologue: Q tile -> stage1 region, KV tile 0 -> stage0 ----
    #pragma unroll
    for (int i = 0; i < 8; i++) {
        int id  = tid + i * 256;
        int sel = id >> 10;               // 0 hi, 1 lo
        int wi  = id & 1023;
        int row = wi >> 3, c = wi & 7;
        uint32_t dst = sb + KSTAGE + sel * 18432 + row * KROWB + c * 16;
        const __half* src = (sel ? Qlo : Qhi) +
                            (long)(b * SEQ + q0 + row) * INNER + h * DKV + c * 8;
        cp_async16(dst, src);
    }
    load_kv(0, 0);
    CP_ASYNC_WAIT(0);
    __syncthreads();

    uint32_t qh[4][4], ql[4][4];
    {
        uint32_t qbh = sb + KSTAGE;
        uint32_t qbl = qbh + 18432;
        int r = w * 16 + (lane & 15);
        int cofs = (lane >= 16) ? 16 : 0;
        #pragma unroll
        for (int ks = 0; ks < 4; ks++) {
            ldmatrix_x4(qh[ks], qbh + r * KROWB + ks * 32 + cofs);
            ldmatrix_x4(ql[ks], qbl + r * KROWB + ks * 32 + cofs);
        }
    }

    float m0 = -3.0e38f, m1 = -3.0e38f, l0 = 0.0f, l1 = 0.0f;
    float o[8][4];
    #pragma unroll
    for (int nt = 0; nt < 8; nt++)
        #pragma unroll
        for (int e = 0; e < 4; e++) o[nt][e] = 0.0f;

    const int rbase0 = 127 - (w * 16 + grow);

    for (int t = 0; t < SEQ / 64; t++) {
        __syncthreads();   // prev compute done; stage (t+1)&1 free; KV_t + rbs hazards clear
        if (t + 1 < SEQ / 64) { load_kv(t + 1, (t + 1) & 1); CP_ASYNC_WAIT(1); }
        else                  { CP_ASYNC_WAIT(0); }
        if (tid < 191)
            rbs[tid] = g_RB[(t * 64 - q0 + tid - 127 + SEQ - 1) * NHEADS + h];
        __syncthreads();   // KV_t + rbs visible

        const char* kp = smraw + (t & 1) * KSTAGE;
        const char* vp = kp + 18432;

        // ---- S = Q @ K^T (fp16-split, 3 mma) ----
        float s[8][4];
        #pragma unroll
        for (int nt = 0; nt < 8; nt++)
            #pragma unroll
            for (int e = 0; e < 4; e++) s[nt][e] = 0.0f;

        #pragma unroll
        for (int ks = 0; ks < 4; ks++) {
            #pragma unroll
            for (int nt = 0; nt < 8; nt++) {
                uint32_t off = (nt * 8 + grow) * KROWB + ks * 32 + gc * 2;
                uint32_t bh_[2], bl_[2];
                bh_[0] = *(const uint32_t*)(kp + off);
                bh_[1] = *(const uint32_t*)(kp + off + 16);
                bl_[0] = *(const uint32_t*)(kp + 9216 + off);
                bl_[1] = *(const uint32_t*)(kp + 9216 + off + 16);
                mma_f16(s[nt], qh[ks], bh_);
                mma_f16(s[nt], qh[ks], bl_);
                mma_f16(s[nt], ql[ks], bh_);
            }
        }

        // ---- + bias ----
        #pragma unroll
        for (int nt = 0; nt < 8; nt++) {
            int cb = nt * 8 + gc;
            s[nt][0] += rbs[cb + rbase0];
            s[nt][1] += rbs[cb + 1 + rbase0];
            s[nt][2] += rbs[cb + rbase0 - 8];
            s[nt][3] += rbs[cb + 1 + rbase0 - 8];
        }

        // ---- online softmax (rows grow, grow+8; reduce over 4-lane group) ----
        float tm0 = -3.0e38f, tm1 = -3.0e38f;
        #pragma unroll
        for (int nt = 0; nt < 8; nt++) {
            tm0 = fmaxf(tm0, fmaxf(s[nt][0], s[nt][1]));
            tm1 = fmaxf(tm1, fmaxf(s[nt][2], s[nt][3]));
        }
        tm0 = fmaxf(tm0, __shfl_xor_sync(0xffffffffu, tm0, 1));
        tm0 = fmaxf(tm0, __shfl_xor_sync(0xffffffffu, tm0, 2));
        tm1 = fmaxf(tm1, __shfl_xor_sync(0xffffffffu, tm1, 1));
        tm1 = fmaxf(tm1, __shfl_xor_sync(0xffffffffu, tm1, 2));
        float nm0 = fmaxf(m0, tm0), nm1 = fmaxf(m1, tm1);
        float sc0 = __expf(m0 - nm0), sc1 = __expf(m1 - nm1);
        float ls0 = 0.0f, ls1 = 0.0f;
        #pragma unroll
        for (int nt = 0; nt < 8; nt++) {
            s[nt][0] = __expf(s[nt][0] - nm0); ls0 += s[nt][0];
            s[nt][1] = __expf(s[nt][1] - nm0); ls0 += s[nt][1];
            s[nt][2] = __expf(s[nt][2] - nm1); ls1 += s[nt][2];
            s[nt][3] = __expf(s[nt][3] - nm1); ls1 += s[nt][3];
        }
        ls0 += __shfl_xor_sync(0xffffffffu, ls0, 1);
        ls0 += __shfl_xor_sync(0xffffffffu, ls0, 2);
        ls1 += __shfl_xor_sync(0xffffffffu, ls1, 1);
        ls1 += __shfl_xor_sync(0xffffffffu, ls1, 2);
        l0 = l0 * sc0 + ls0;  l1 = l1 * sc1 + ls1;
        m0 = nm0;  m1 = nm1;
        #pragma unroll
        for (int nt = 0; nt < 8; nt++) {
            o[nt][0] *= sc0; o[nt][1] *= sc0;
            o[nt][2] *= sc1; o[nt][3] *= sc1;
        }

        // ---- O += P @ V (P frags straight from S registers) ----
        #pragma unroll
        for (int ks = 0; ks < 4; ks++) {
            uint32_t ph[4], pl[4];
            split2(s[2*ks][0],   s[2*ks][1],   ph[0], pl[0]);
            split2(s[2*ks][2],   s[2*ks][3],   ph[1], pl[1]);
            split2(s[2*ks+1][0], s[2*ks+1][1], ph[2], pl[2]);
            split2(s[2*ks+1][2], s[2*ks+1][3], ph[3], pl[3]);
            #pragma unroll
            for (int nt = 0; nt < 8; nt++) {
                uint32_t off = (nt * 8 + grow) * KROWB + ks * 32 + gc * 2;
                uint32_t vh_[2], vl_[2];
                vh_[0] = *(const uint32_t*)(vp + off);
                vh_[1] = *(const uint32_t*)(vp + off + 16);
                vl_[0] = *(const uint32_t*)(vp + 9216 + off);
                vl_[1] = *(const uint32_t*)(vp + 9216 + off + 16);
                mma_f16(o[nt], ph, vh_);
                mma_f16(o[nt], ph, vl_);
                mma_f16(o[nt], pl, vh_);
            }
        }
    }

    // ---- epilogue: normalize, split, store ctx hi/lo [token][1024] ----
    float i0 = 1.0f / l0, i1 = 1.0f / l1;
    long tok0 = (long)b * SEQ + q0 + w * 16 + grow;
    #pragma unroll
    for (int nt = 0; nt < 8; nt++) {
        long col = h * DKV + nt * 8 + gc;
        uint32_t hh, ll;
        split2(o[nt][0] * i0, o[nt][1] * i0, hh, ll);
        *(uint32_t*)(Chi + tok0 * INNER + col) = hh;
        *(uint32_t*)(Clo + tok0 * INNER + col) = ll;
        split2(o[nt][2] * i1, o[nt][3] * i1, hh, ll);
        *(uint32_t*)(Chi + (tok0 + 8) * INNER + col) = hh;
        *(uint32_t*)(Clo + (tok0 + 8) * INNER + col) = ll;
    }
}

// =============================================================
// Host launcher
// =============================================================
extern "C" void kernel_launch(void* const* d_in, const int* in_sizes, int n_in,
                              void* d_out, int out_size)
{
    const float* X   = (const float*)d_in[0];
    const float* wq  = (const float*)d_in[1];
    const float* wk  = (const float*)d_in[2];
    const float* wv  = (const float*)d_in[3];
    const float* wo  = (const float*)d_in[4];
    const float* rbt = (const float*)d_in[5];
    float* out = (float*)d_out;

    __half *Xhi, *Xlo, *Whi, *Wlo, *Qhi, *Qlo, *Khi, *Klo, *Vthi, *Vtlo, *Chi, *Clo;
    cudaGetSymbolAddress((void**)&Xhi,  g_Xhi);   cudaGetSymbolAddress((void**)&Xlo,  g_Xlo);
    cudaGetSymbolAddress((void**)&Whi,  g_Whi);   cudaGetSymbolAddress((void**)&Wlo,  g_Wlo);
    cudaGetSymbolAddress((void**)&Qhi,  g_Qhi);   cudaGetSymbolAddress((void**)&Qlo,  g_Qlo);
    cudaGetSymbolAddress((void**)&Khi,  g_Khi);   cudaGetSymbolAddress((void**)&Klo,  g_Klo);
    cudaGetSymbolAddress((void**)&Vthi, g_Vthi);  cudaGetSymbolAddress((void**)&Vtlo, g_Vtlo);
    cudaGetSymbolAddress((void**)&Chi,  g_Chi);   cudaGetSymbolAddress((void**)&Clo,  g_Clo);

    const long WOFF = (long)DMODEL * INNER;

    // preprocessing
    bias_table_kernel<<<(RBR * NHEADS + 255) / 256, 256>>>(rbt);
    split_kernel<<<(NTOK * DMODEL / 4 + 255) / 256, 256>>>(
        (const float4*)X, Xhi, Xlo, NTOK * DMODEL / 4);
    dim3 tb(32, 8), tg(32, 32);
    transpose_split_kernel<<<tg, tb>>>(wq, Whi + 0 * WOFF, Wlo + 0 * WOFF);
    transpose_split_kernel<<<tg, tb>>>(wk, Whi + 1 * WOFF, Wlo + 1 * WOFF);
    transpose_split_kernel<<<tg, tb>>>(wv, Whi + 2 * WOFF, Wlo + 2 * WOFF);
    transpose_split_kernel<<<tg, tb>>>(wo, Whi + 3 * WOFF, Wlo + 3 * WOFF);

    // fp16-split projections
    cudaFuncSetAttribute(hgemm_kernel<0>, cudaFuncAttributeMaxDynamicSharedMemorySize, HGEMM_SMEM);
    cudaFuncSetAttribute(hgemm_kernel<1>, cudaFuncAttributeMaxDynamicSharedMemorySize, HGEMM_SMEM);
    cudaFuncSetAttribute(hgemm_kernel<2>, cudaFuncAttributeMaxDynamicSharedMemorySize, HGEMM_SMEM);
    dim3 gg(INNER / 128, NTOK / 128);   // (8, 32)
    hgemm_kernel<0><<<gg, 256, HGEMM_SMEM>>>(Xhi, Xlo, Whi + 0*WOFF, Wlo + 0*WOFF, Qhi, Qlo, nullptr);
    hgemm_kernel<0><<<gg, 256, HGEMM_SMEM>>>(Xhi, Xlo, Whi + 1*WOFF, Wlo + 1*WOFF, Khi, Klo, nullptr);
    hgemm_kernel<1><<<gg, 256, HGEMM_SMEM>>>(Xhi, Xlo, Whi + 2*WOFF, Wlo + 2*WOFF, Vthi, Vtlo, nullptr);

    // attention
    cudaFuncSetAttribute(attn_kernel, cudaFuncAttributeMaxDynamicSharedMemorySize, ATT_SMEM);
    attn_kernel<<<dim3(SEQ / 128, BATCH * NHEADS), 256, ATT_SMEM>>>(
        Qhi, Qlo, Khi, Klo, Vthi, Vtlo, Chi, Clo);

    // output projection (float out)
    hgemm_kernel<2><<<gg, 256, HGEMM_SMEM>>>(Chi, Clo, Whi + 3*WOFF, Wlo + 3*WOFF,
                                             nullptr, nullptr, out);
}

// round 5
// speedup vs baseline: 2.5448x; 1.0451x over previous
#include <cuda_runtime.h>
#include <cuda_fp16.h>
#include <math.h>
#include <stdint.h>

#define BATCH   2
#define SEQ     2048
#define DMODEL  1024
#define NHEADS  16
#define DKV     64
#define INNER   1024
#define NTOK    (BATCH*SEQ)          // 4096
#define RBR     (2*SEQ-1)            // 4095

// -------- scratch (device globals: no allocation allowed) --------
__device__ __half g_Xhi[NTOK*DMODEL],  g_Xlo[NTOK*DMODEL];
__device__ __half g_Whi[4*DMODEL*INNER], g_Wlo[4*DMODEL*INNER];
__device__ __half g_Qhi[NTOK*INNER],  g_Qlo[NTOK*INNER];
__device__ __half g_Khi[NTOK*INNER],  g_Klo[NTOK*INNER];
__device__ __half g_Vthi[NTOK*INNER], g_Vtlo[NTOK*INNER];   // transposed [n][token]
__device__ __half g_Chi[NTOK*INNER],  g_Clo[NTOK*INNER];
__device__ float  g_RB[RBR*NHEADS];

// ============================================================
// helpers
// ============================================================
__device__ __forceinline__ uint32_t smem_u32(const void* p) {
    uint32_t a;
    asm("{ .reg .u64 t; cvta.to.shared.u64 t, %1; cvt.u32.u64 %0, t; }" : "=r"(a) : "l"(p));
    return a;
}
__device__ __forceinline__ void cp_async16(uint32_t dst, const void* src) {
    asm volatile("cp.async.cg.shared.global [%0], [%1], 16;\n" :: "r"(dst), "l"(src) : "memory");
}
#define CP_ASYNC_COMMIT() asm volatile("cp.async.commit_group;\n" ::: "memory")
#define CP_ASYNC_WAIT(n)  asm volatile("cp.async.wait_group %0;\n" :: "n"(n) : "memory")

__device__ __forceinline__ void ldmatrix_x4(uint32_t* r, uint32_t addr) {
    asm volatile("ldmatrix.sync.aligned.m8n8.x4.shared.b16 {%0,%1,%2,%3}, [%4];"
                 : "=r"(r[0]), "=r"(r[1]), "=r"(r[2]), "=r"(r[3]) : "r"(addr));
}
__device__ __forceinline__ void mma_f16(float* d, const uint32_t* a, const uint32_t* b) {
    asm volatile(
        "mma.sync.aligned.m16n8k16.row.col.f32.f16.f16.f32 "
        "{%0,%1,%2,%3}, {%4,%5,%6,%7}, {%8,%9}, {%0,%1,%2,%3};"
        : "+f"(d[0]), "+f"(d[1]), "+f"(d[2]), "+f"(d[3])
        : "r"(a[0]), "r"(a[1]), "r"(a[2]), "r"(a[3]), "r"(b[0]), "r"(b[1]));
}
// split fp32 pair -> packed half2 (hi) + packed half2 (lo residual)
__device__ __forceinline__ void split2(float f0, float f1, uint32_t& hi, uint32_t& lo) {
    __half h0 = __float2half_rn(f0), h1 = __float2half_rn(f1);
    __half l0 = __float2half_rn(f0 - __half2float(h0));
    __half l1 = __float2half_rn(f1 - __half2float(h1));
    hi = (uint32_t)__half_as_ushort(h0) | ((uint32_t)__half_as_ushort(h1) << 16);
    lo = (uint32_t)__half_as_ushort(l0) | ((uint32_t)__half_as_ushort(l1) << 16);
}

// =============================================================
// Pre-processing
// =============================================================
__global__ void split_kernel(const float4* __restrict__ in,
                             __half* __restrict__ hi, __half* __restrict__ lo, int n4)
{
    int i = blockIdx.x * blockDim.x + threadIdx.x;
    if (i < n4) {
        float4 v = in[i];
        uint32_t h0, l0, h1, l1;
        split2(v.x, v.y, h0, l0);
        split2(v.z, v.w, h1, l1);
        *(uint2*)(hi + 4l * i) = make_uint2(h0, h1);
        *(uint2*)(lo + 4l * i) = make_uint2(l0, l1);
    }
}

// out_hi/lo[n][k] = split(in[k][n]), 1024x1024
__global__ void transpose_split_kernel(const float* __restrict__ in,
                                       __half* __restrict__ hi, __half* __restrict__ lo)
{
    __shared__ float tile[32][33];
    int bx = blockIdx.x * 32, by = blockIdx.y * 32;
    int x = bx + threadIdx.x;
    #pragma unroll
    for (int i = 0; i < 32; i += 8)
        tile[threadIdx.y + i][threadIdx.x] = in[(by + threadIdx.y + i) * DMODEL + x];
    __syncthreads();
    x = by + threadIdx.x;
    #pragma unroll
    for (int i = 0; i < 32; i += 8) {
        float v = tile[threadIdx.x][threadIdx.y + i];
        __half h = __float2half_rn(v);
        __half l = __float2half_rn(v - __half2float(h));
        long idx = (long)(bx + threadIdx.y + i) * DMODEL + x;
        hi[idx] = h;
        lo[idx] = l;
    }
}

__global__ void bias_table_kernel(const float* __restrict__ table)
{
    int idx = blockIdx.x * blockDim.x + threadIdx.x;
    if (idx >= RBR * NHEADS) return;
    int rel = idx / NHEADS - (SEQ - 1);
    int h   = idx % NHEADS;
    int bucket = (rel > 0) ? 16 : 0;
    int rp = rel < 0 ? -rel : rel;
    int v;
    if (rp < 8) {
        v = rp;
    } else {
        float f = logf((float)rp * 0.125f) / 2.772588722239781f * 8.0f;
        v = 8 + (int)f;
        if (v > 15) v = 15;
    }
    g_RB[idx] = table[(bucket + v) * NHEADS + h];
}

// =============================================================
// fp16-split GEMM (unchanged from round 4): C = A @ B^T
// =============================================================
#define HPAD 24
#define HTILE (128 * HPAD)
#define HGEMM_SMEM (8 * HTILE * 2)

template<int MODE>
__global__ __launch_bounds__(256)
void hgemm_kernel(const __half* __restrict__ Ahi, const __half* __restrict__ Alo,
                  const __half* __restrict__ Bhi, const __half* __restrict__ Blo,
                  __half* __restrict__ Chi, __half* __restrict__ Clo,
                  float* __restrict__ Cf)
{
    extern __shared__ __half hsm[];
    const int tid  = threadIdx.x;
    const int wid  = tid >> 5;
    const int lane = tid & 31;
    const int wr   = wid & 1;
    const int wc   = wid >> 1;
    const long bm  = blockIdx.y * 128;
    const long bn  = blockIdx.x * 128;
    const uint32_t s0 = smem_u32(hsm);

    float acc[4][4][4];
    #pragma unroll
    for (int i = 0; i < 4; i++)
        #pragma unroll
        for (int j = 0; j < 4; j++)
            #pragma unroll
            for (int k = 0; k < 4; k++) acc[i][j][k] = 0.0f;

    auto load_tiles = [&](int it, int stage) {
        int k0 = it * 16;
        int row = tid >> 1, c = tid & 1;
        uint32_t off = stage * (HTILE * 2) + row * (HPAD * 2) + c * 16;
        long asrc = (bm + row) * (long)DMODEL + k0 + c * 8;
        long bsrc = (bn + row) * (long)DMODEL + k0 + c * 8;
        cp_async16(s0 + off,         Ahi + asrc);
        cp_async16(s0 + 12288 + off, Alo + asrc);
        cp_async16(s0 + 24576 + off, Bhi + bsrc);
        cp_async16(s0 + 36864 + off, Blo + bsrc);
        CP_ASYNC_COMMIT();
    };

    const int lrow  = lane & 15;
    const int lcolB = (lane >= 16) ? 16 : 0;

    load_tiles(0, 0);

    for (int it = 0; it < DMODEL / 16; it++) {
        const int buf = it & 1;
        if (it + 1 < DMODEL / 16) { load_tiles(it + 1, buf ^ 1); CP_ASYNC_WAIT(1); }
        else                      { CP_ASYNC_WAIT(0); }
        __syncthreads();

        const uint32_t ah = s0 + buf * (HTILE * 2);
        const uint32_t al = ah + 12288;
        const __half*  bh = hsm + buf * HTILE + 12288;
        const __half*  bl = hsm + buf * HTILE + 18432;

        uint32_t afh[4][4], afl[4][4];
        #pragma unroll
        for (int mt = 0; mt < 4; mt++) {
            int m = wr * 64 + mt * 16 + lrow;
            ldmatrix_x4(afh[mt], ah + m * (HPAD * 2) + lcolB);
            ldmatrix_x4(afl[mt], al + m * (HPAD * 2) + lcolB);
        }
        uint32_t bfh[4][2], bfl[4][2];
        #pragma unroll
        for (int nt = 0; nt < 4; nt++) {
            int n = wc * 32 + nt * 8 + (lane >> 2);
            int o = n * HPAD + (lane & 3) * 2;
            bfh[nt][0] = *(const uint32_t*)(bh + o);
            bfh[nt][1] = *(const uint32_t*)(bh + o + 8);
            bfl[nt][0] = *(const uint32_t*)(bl + o);
            bfl[nt][1] = *(const uint32_t*)(bl + o + 8);
        }
        #pragma unroll
        for (int mt = 0; mt < 4; mt++)
            #pragma unroll
            for (int nt = 0; nt < 4; nt++) {
                mma_f16(acc[mt][nt], afh[mt], bfh[nt]);
                mma_f16(acc[mt][nt], afh[mt], bfl[nt]);
                mma_f16(acc[mt][nt], afl[mt], bfh[nt]);
            }
        __syncthreads();
    }

    #pragma unroll
    for (int mt = 0; mt < 4; mt++) {
        long m0 = bm + wr * 64 + mt * 16 + (lane >> 2);
        #pragma unroll
        for (int nt = 0; nt < 4; nt++) {
            long n0 = bn + wc * 32 + nt * 8 + (lane & 3) * 2;
            float* a = acc[mt][nt];
            if (MODE == 2) {
                *(float2*)(Cf + m0 * INNER + n0)       = make_float2(a[0], a[1]);
                *(float2*)(Cf + (m0 + 8) * INNER + n0) = make_float2(a[2], a[3]);
            } else if (MODE == 0) {
                uint32_t h, l;
                split2(a[0], a[1], h, l);
                *(uint32_t*)(Chi + m0 * INNER + n0) = h;
                *(uint32_t*)(Clo + m0 * INNER + n0) = l;
                split2(a[2], a[3], h, l);
                *(uint32_t*)(Chi + (m0 + 8) * INNER + n0) = h;
                *(uint32_t*)(Clo + (m0 + 8) * INNER + n0) = l;
            } else {
                #pragma unroll
                for (int e = 0; e < 4; e++) {
                    long m = m0 + ((e >= 2) ? 8 : 0);
                    long n = n0 + (e & 1);
                    __half h = __float2half_rn(a[e]);
                    __half l = __float2half_rn(a[e] - __half2float(h));
                    Chi[n * NTOK + m] = h;
                    Clo[n * NTOK + m] = l;
                }
            }
        }
    }
}

// =============================================================
// fp16-split flash attention v2.
// Grid (SEQ/128, 32), 128 thr (4 warps). Warp tile 32q x 64k
// (two 16-row halves sharing every K/V fragment -> 6 mma per
// 4-LDS b-frag load, halving smem traffic vs round 4).
// =============================================================
#define KSTAGE 36864                 // Khi,Klo,Vhi,Vlo x 9216 bytes
#define ATT_SMEM (2*KSTAGE + 191*4)
#define KROWB 144                    // 64 halfs + 16B pad per row

__global__ __launch_bounds__(128, 2)
void attn_kernel(const __half* __restrict__ Qhi, const __half* __restrict__ Qlo,
                 const __half* __restrict__ Khi, const __half* __restrict__ Klo,
                 const __half* __restrict__ Vthi, const __half* __restrict__ Vtlo,
                 __half* __restrict__ Chi, __half* __restrict__ Clo)
{
    extern __shared__ char smraw[];
    float* rbs = (float*)(smraw + 2 * KSTAGE);
    const int tid  = threadIdx.x;
    const int w    = tid >> 5;
    const int lane = tid & 31;
    const int bh   = blockIdx.y;
    const int b    = bh >> 4;
    const int h    = bh & 15;
    const int q0   = blockIdx.x * 128;
    const uint32_t sb = smem_u32(smraw);
    const int grow = lane >> 2;
    const int gc   = (lane & 3) * 2;

    auto load_kv = [&](int t, int stage) {
        int k0 = t * 64;
        uint32_t sbase = sb + stage * KSTAGE;
        #pragma unroll
        for (int i = 0; i < 16; i++) {
            int id  = tid + i * 128;
            int sel = id >> 9;            // 0 Khi, 1 Klo, 2 Vhi, 3 Vlo
            int wi  = id & 511;
            int row = wi >> 3, c = wi & 7;
            uint32_t dst = sbase + sel * 9216 + row * KROWB + c * 16;
            const __half* src;
            if (sel < 2) {
                const __half* base = sel ? Klo : Khi;
                src = base + (long)(b * SEQ + k0 + row) * INNER + h * DKV + c * 8;
            } else {
                const __half* base = (sel == 3) ? Vtlo : Vthi;
                src = base + (long)(h * DKV + row) * NTOK + b * SEQ + k0 + c * 8;
            }
            cp_async16(dst, src);
        }
        CP_ASYNC_COMMIT();
    };

    // ---- prologue: Q tile (128 rows hi+lo) -> stage1 region; KV tile 0 -> stage0 ----
    #pragma unroll
    for (int i = 0; i < 16; i++) {
        int id  = tid + i * 128;
        int sel = id >> 10;               // 0 hi, 1 lo
        int wi  = id & 1023;
        int row = wi >> 3, c = wi & 7;
        uint32_t dst = sb + KSTAGE + sel * 18432 + row * KROWB + c * 16;
        const __half* src = (sel ? Qlo : Qhi) +
                            (long)(b * SEQ + q0 + row) * INNER + h * DKV + c * 8;
        cp_async16(dst, src);
    }
    load_kv(0, 0);
    CP_ASYNC_WAIT(0);
    __syncthreads();

    // Q fragments for both 16-row halves (persist whole kernel)
    uint32_t qh[2][4][4], ql[2][4][4];
    {
        uint32_t qbh = sb + KSTAGE;
        uint32_t qbl = qbh + 18432;
        int cofs = (lane >= 16) ? 16 : 0;
        #pragma unroll
        for (int hf = 0; hf < 2; hf++) {
            int r = w * 32 + hf * 16 + (lane & 15);
            #pragma unroll
            for (int ks = 0; ks < 4; ks++) {
                ldmatrix_x4(qh[hf][ks], qbh + r * KROWB + ks * 32 + cofs);
                ldmatrix_x4(ql[hf][ks], qbl + r * KROWB + ks * 32 + cofs);
            }
        }
    }

    float m[2][2], l[2][2];
    float o[2][8][4];
    #pragma unroll
    for (int hf = 0; hf < 2; hf++) {
        m[hf][0] = m[hf][1] = -3.0e38f;
        l[hf][0] = l[hf][1] = 0.0f;
        #pragma unroll
        for (int nt = 0; nt < 8; nt++)
            #pragma unroll
            for (int e = 0; e < 4; e++) o[hf][nt][e] = 0.0f;
    }

    for (int t = 0; t < SEQ / 64; t++) {
        __syncthreads();
        if (t + 1 < SEQ / 64) { load_kv(t + 1, (t + 1) & 1); CP_ASYNC_WAIT(1); }
        else                  { CP_ASYNC_WAIT(0); }
        for (int i = tid; i < 191; i += 128)
            rbs[i] = g_RB[(t * 64 - q0 + i - 127 + SEQ - 1) * NHEADS + h];
        __syncthreads();

        const char* kp = smraw + (t & 1) * KSTAGE;
        const char* vp = kp + 18432;

        // ---- S = Q @ K^T (both halves share every K fragment) ----
        float s[2][8][4];
        #pragma unroll
        for (int hf = 0; hf < 2; hf++)
            #pragma unroll
            for (int nt = 0; nt < 8; nt++)
                #pragma unroll
                for (int e = 0; e < 4; e++) s[hf][nt][e] = 0.0f;

        #pragma unroll
        for (int ks = 0; ks < 4; ks++) {
            #pragma unroll
            for (int nt = 0; nt < 8; nt++) {
                uint32_t off = (nt * 8 + grow) * KROWB + ks * 32 + gc * 2;
                uint32_t bh_[2], bl_[2];
                bh_[0] = *(const uint32_t*)(kp + off);
                bh_[1] = *(const uint32_t*)(kp + off + 16);
                bl_[0] = *(const uint32_t*)(kp + 9216 + off);
                bl_[1] = *(const uint32_t*)(kp + 9216 + off + 16);
                mma_f16(s[0][nt], qh[0][ks], bh_);
                mma_f16(s[0][nt], qh[0][ks], bl_);
                mma_f16(s[0][nt], ql[0][ks], bh_);
                mma_f16(s[1][nt], qh[1][ks], bh_);
                mma_f16(s[1][nt], qh[1][ks], bl_);
                mma_f16(s[1][nt], ql[1][ks], bh_);
            }
        }

        // ---- bias + online softmax per half ----
        #pragma unroll
        for (int hf = 0; hf < 2; hf++) {
            const int rb0 = 127 - (w * 32 + hf * 16 + grow);
            #pragma unroll
            for (int nt = 0; nt < 8; nt++) {
                int cb = nt * 8 + gc;
                s[hf][nt][0] += rbs[cb + rb0];
                s[hf][nt][1] += rbs[cb + 1 + rb0];
                s[hf][nt][2] += rbs[cb + rb0 - 8];
                s[hf][nt][3] += rbs[cb + 1 + rb0 - 8];
            }
            float tm0 = -3.0e38f, tm1 = -3.0e38f;
            #pragma unroll
            for (int nt = 0; nt < 8; nt++) {
                tm0 = fmaxf(tm0, fmaxf(s[hf][nt][0], s[hf][nt][1]));
                tm1 = fmaxf(tm1, fmaxf(s[hf][nt][2], s[hf][nt][3]));
            }
            tm0 = fmaxf(tm0, __shfl_xor_sync(0xffffffffu, tm0, 1));
            tm0 = fmaxf(tm0, __shfl_xor_sync(0xffffffffu, tm0, 2));
            tm1 = fmaxf(tm1, __shfl_xor_sync(0xffffffffu, tm1, 1));
            tm1 = fmaxf(tm1, __shfl_xor_sync(0xffffffffu, tm1, 2));
            float nm0 = fmaxf(m[hf][0], tm0), nm1 = fmaxf(m[hf][1], tm1);
            float sc0 = __expf(m[hf][0] - nm0), sc1 = __expf(m[hf][1] - nm1);
            float ls0 = 0.0f, ls1 = 0.0f;
            #pragma unroll
            for (int nt = 0; nt < 8; nt++) {
                s[hf][nt][0] = __expf(s[hf][nt][0] - nm0); ls0 += s[hf][nt][0];
                s[hf][nt][1] = __expf(s[hf][nt][1] - nm0); ls0 += s[hf][nt][1];
                s[hf][nt][2] = __expf(s[hf][nt][2] - nm1); ls1 += s[hf][nt][2];
                s[hf][nt][3] = __expf(s[hf][nt][3] - nm1); ls1 += s[hf][nt][3];
            }
            ls0 += __shfl_xor_sync(0xffffffffu, ls0, 1);
            ls0 += __shfl_xor_sync(0xffffffffu, ls0, 2);
            ls1 += __shfl_xor_sync(0xffffffffu, ls1, 1);
            ls1 += __shfl_xor_sync(0xffffffffu, ls1, 2);
            l[hf][0] = l[hf][0] * sc0 + ls0;
            l[hf][1] = l[hf][1] * sc1 + ls1;
            m[hf][0] = nm0;  m[hf][1] = nm1;
            #pragma unroll
            for (int nt = 0; nt < 8; nt++) {
                o[hf][nt][0] *= sc0; o[hf][nt][1] *= sc0;
                o[hf][nt][2] *= sc1; o[hf][nt][3] *= sc1;
            }
        }

        // ---- O += P @ V (both halves share every V fragment) ----
        #pragma unroll
        for (int ks = 0; ks < 4; ks++) {
            uint32_t ph[2][4], pl[2][4];
            #pragma unroll
            for (int hf = 0; hf < 2; hf++) {
                split2(s[hf][2*ks][0],   s[hf][2*ks][1],   ph[hf][0], pl[hf][0]);
                split2(s[hf][2*ks][2],   s[hf][2*ks][3],   ph[hf][1], pl[hf][1]);
                split2(s[hf][2*ks+1][0], s[hf][2*ks+1][1], ph[hf][2], pl[hf][2]);
                split2(s[hf][2*ks+1][2], s[hf][2*ks+1][3], ph[hf][3], pl[hf][3]);
            }
            #pragma unroll
            for (int nt = 0; nt < 8; nt++) {
                uint32_t off = (nt * 8 + grow) * KROWB + ks * 32 + gc * 2;
                uint32_t vh_[2], vl_[2];
                vh_[0] = *(const uint32_t*)(vp + off);
                vh_[1] = *(const uint32_t*)(vp + off + 16);
                vl_[0] = *(const uint32_t*)(vp + 9216 + off);
                vl_[1] = *(const uint32_t*)(vp + 9216 + off + 16);
                mma_f16(o[0][nt], ph[0], vh_);
                mma_f16(o[0][nt], ph[0], vl_);
                mma_f16(o[0][nt], pl[0], vh_);
                mma_f16(o[1][nt], ph[1], vh_);
                mma_f16(o[1][nt], ph[1], vl_);
                mma_f16(o[1][nt], pl[1], vh_);
            }
        }
    }

    // ---- epilogue: normalize, split, store ctx hi/lo ----
    #pragma unroll
    for (int hf = 0; hf < 2; hf++) {
        float i0 = 1.0f / l[hf][0], i1 = 1.0f / l[hf][1];
        long tok0 = (long)b * SEQ + q0 + w * 32 + hf * 16 + grow;
        #pragma unroll
        for (int nt = 0; nt < 8; nt++) {
            long col = h * DKV + nt * 8 + gc;
            uint32_t hh, ll;
            split2(o[hf][nt][0] * i0, o[hf][nt][1] * i0, hh, ll);
            *(uint32_t*)(Chi + tok0 * INNER + col) = hh;
            *(uint32_t*)(Clo + tok0 * INNER + col) = ll;
            split2(o[hf][nt][2] * i1, o[hf][nt][3] * i1, hh, ll);
            *(uint32_t*)(Chi + (tok0 + 8) * INNER + col) = hh;
            *(uint32_t*)(Clo + (tok0 + 8) * INNER + col) = ll;
        }
    }
}

// =============================================================
// Host launcher
// =============================================================
extern "C" void kernel_launch(void* const* d_in, const int* in_sizes, int n_in,
                              void* d_out, int out_size)
{
    const float* X   = (const float*)d_in[0];
    const float* wq  = (const float*)d_in[1];
    const float* wk  = (const float*)d_in[2];
    const float* wv  = (const float*)d_in[3];
    const float* wo  = (const float*)d_in[4];
    const float* rbt = (const float*)d_in[5];
    float* out = (float*)d_out;

    __half *Xhi, *Xlo, *Whi, *Wlo, *Qhi, *Qlo, *Khi, *Klo, *Vthi, *Vtlo, *Chi, *Clo;
    cudaGetSymbolAddress((void**)&Xhi,  g_Xhi);   cudaGetSymbolAddress((void**)&Xlo,  g_Xlo);
    cudaGetSymbolAddress((void**)&Whi,  g_Whi);   cudaGetSymbolAddress((void**)&Wlo,  g_Wlo);
    cudaGetSymbolAddress((void**)&Qhi,  g_Qhi);   cudaGetSymbolAddress((void**)&Qlo,  g_Qlo);
    cudaGetSymbolAddress((void**)&Khi,  g_Khi);   cudaGetSymbolAddress((void**)&Klo,  g_Klo);
    cudaGetSymbolAddress((void**)&Vthi, g_Vthi);  cudaGetSymbolAddress((void**)&Vtlo, g_Vtlo);
    cudaGetSymbolAddress((void**)&Chi,  g_Chi);   cudaGetSymbolAddress((void**)&Clo,  g_Clo);

    const long WOFF = (long)DMODEL * INNER;

    // preprocessing
    bias_table_kernel<<<(RBR * NHEADS + 255) / 256, 256>>>(rbt);
    split_kernel<<<(NTOK * DMODEL / 4 + 255) / 256, 256>>>(
        (const float4*)X, Xhi, Xlo, NTOK * DMODEL / 4);
    dim3 tb(32, 8), tg(32, 32);
    transpose_split_kernel<<<tg, tb>>>(wq, Whi + 0 * WOFF, Wlo + 0 * WOFF);
    transpose_split_kernel<<<tg, tb>>>(wk, Whi + 1 * WOFF, Wlo + 1 * WOFF);
    transpose_split_kernel<<<tg, tb>>>(wv, Whi + 2 * WOFF, Wlo + 2 * WOFF);
    transpose_split_kernel<<<tg, tb>>>(wo, Whi + 3 * WOFF, Wlo + 3 * WOFF);

    // fp16-split projections
    cudaFuncSetAttribute(hgemm_kernel<0>, cudaFuncAttributeMaxDynamicSharedMemorySize, HGEMM_SMEM);
    cudaFuncSetAttribute(hgemm_kernel<1>, cudaFuncAttributeMaxDynamicSharedMemorySize, HGEMM_SMEM);
    cudaFuncSetAttribute(hgemm_kernel<2>, cudaFuncAttributeMaxDynamicSharedMemorySize, HGEMM_SMEM);
    dim3 gg(INNER / 128, NTOK / 128);   // (8, 32)
    hgemm_kernel<0><<<gg, 256, HGEMM_SMEM>>>(Xhi, Xlo, Whi + 0*WOFF, Wlo + 0*WOFF, Qhi, Qlo, nullptr);
    hgemm_kernel<0><<<gg, 256, HGEMM_SMEM>>>(Xhi, Xlo, Whi + 1*WOFF, Wlo + 1*WOFF, Khi, Klo, nullptr);
    hgemm_kernel<1><<<gg, 256, HGEMM_SMEM>>>(Xhi, Xlo, Whi + 2*WOFF, Wlo + 2*WOFF, Vthi, Vtlo, nullptr);

    // attention (warp tile 32q x 64k, 4 warps)
    cudaFuncSetAttribute(attn_kernel, cudaFuncAttributeMaxDynamicSharedMemorySize, ATT_SMEM);
    attn_kernel<<<dim3(SEQ / 128, BATCH * NHEADS), 128, ATT_SMEM>>>(
        Qhi, Qlo, Khi, Klo, Vthi, Vtlo, Chi, Clo);

    // output projection (float out)
    hgemm_kernel<2><<<gg, 256, HGEMM_SMEM>>>(Chi, Clo, Whi + 3*WOFF, Wlo + 3*WOFF,
                                             nullptr, nullptr, out);
}

// round 6
// speedup vs baseline: 3.1723x; 1.2466x over previous
#include <cuda_runtime.h>
#include <cuda_fp16.h>
#include <math.h>
#include <stdint.h>

#define BATCH   2
#define SEQ     2048
#define DMODEL  1024
#define NHEADS  16
#define DKV     64
#define INNER   1024
#define NTOK    (BATCH*SEQ)          // 4096
#define RBR     (2*SEQ-1)            // 4095

// -------- scratch (device globals: no allocation allowed) --------
__device__ __half g_Xhi[NTOK*DMODEL],  g_Xlo[NTOK*DMODEL];
__device__ __half g_Whi[4*DMODEL*INNER], g_Wlo[4*DMODEL*INNER];
__device__ __half g_Qhi[NTOK*INNER],  g_Qlo[NTOK*INNER];
__device__ __half g_Khi[NTOK*INNER],  g_Klo[NTOK*INNER];
__device__ __half g_Vthi[NTOK*INNER], g_Vtlo[NTOK*INNER];   // transposed [n][token]
__device__ __half g_Chi[NTOK*INNER],  g_Clo[NTOK*INNER];
__device__ float  g_RB[RBR*NHEADS];

// ============================================================
// helpers
// ============================================================
__device__ __forceinline__ uint32_t smem_u32(const void* p) {
    uint32_t a;
    asm("{ .reg .u64 t; cvta.to.shared.u64 t, %1; cvt.u32.u64 %0, t; }" : "=r"(a) : "l"(p));
    return a;
}
__device__ __forceinline__ void cp_async16(uint32_t dst, const void* src) {
    asm volatile("cp.async.cg.shared.global [%0], [%1], 16;\n" :: "r"(dst), "l"(src) : "memory");
}
#define CP_ASYNC_COMMIT() asm volatile("cp.async.commit_group;\n" ::: "memory")
#define CP_ASYNC_WAIT(n)  asm volatile("cp.async.wait_group %0;\n" :: "n"(n) : "memory")

__device__ __forceinline__ void ldmatrix_x4(uint32_t* r, uint32_t addr) {
    asm volatile("ldmatrix.sync.aligned.m8n8.x4.shared.b16 {%0,%1,%2,%3}, [%4];"
                 : "=r"(r[0]), "=r"(r[1]), "=r"(r[2]), "=r"(r[3]) : "r"(addr));
}
__device__ __forceinline__ void mma_f16(float* d, const uint32_t* a, const uint32_t* b) {
    asm volatile(
        "mma.sync.aligned.m16n8k16.row.col.f32.f16.f16.f32 "
        "{%0,%1,%2,%3}, {%4,%5,%6,%7}, {%8,%9}, {%0,%1,%2,%3};"
        : "+f"(d[0]), "+f"(d[1]), "+f"(d[2]), "+f"(d[3])
        : "r"(a[0]), "r"(a[1]), "r"(a[2]), "r"(a[3]), "r"(b[0]), "r"(b[1]));
}
__device__ __forceinline__ void split2(float f0, float f1, uint32_t& hi, uint32_t& lo) {
    __half h0 = __float2half_rn(f0), h1 = __float2half_rn(f1);
    __half l0 = __float2half_rn(f0 - __half2float(h0));
    __half l1 = __float2half_rn(f1 - __half2float(h1));
    hi = (uint32_t)__half_as_ushort(h0) | ((uint32_t)__half_as_ushort(h1) << 16);
    lo = (uint32_t)__half_as_ushort(l0) | ((uint32_t)__half_as_ushort(l1) << 16);
}
__device__ __forceinline__ uint32_t pack_half2(float f0, float f1) {
    __half2 h = __floats2half2_rn(f0, f1);
    return *(uint32_t*)&h;
}

// =============================================================
// Pre-processing
// =============================================================
__global__ void split_kernel(const float4* __restrict__ in,
                             __half* __restrict__ hi, __half* __restrict__ lo, int n4)
{
    int i = blockIdx.x * blockDim.x + threadIdx.x;
    if (i < n4) {
        float4 v = in[i];
        uint32_t h0, l0, h1, l1;
        split2(v.x, v.y, h0, l0);
        split2(v.z, v.w, h1, l1);
        *(uint2*)(hi + 4l * i) = make_uint2(h0, h1);
        *(uint2*)(lo + 4l * i) = make_uint2(l0, l1);
    }
}

__global__ void transpose_split_kernel(const float* __restrict__ in,
                                       __half* __restrict__ hi, __half* __restrict__ lo)
{
    __shared__ float tile[32][33];
    int bx = blockIdx.x * 32, by = blockIdx.y * 32;
    int x = bx + threadIdx.x;
    #pragma unroll
    for (int i = 0; i < 32; i += 8)
        tile[threadIdx.y + i][threadIdx.x] = in[(by + threadIdx.y + i) * DMODEL + x];
    __syncthreads();
    x = by + threadIdx.x;
    #pragma unroll
    for (int i = 0; i < 32; i += 8) {
        float v = tile[threadIdx.x][threadIdx.y + i];
        __half h = __float2half_rn(v);
        __half l = __float2half_rn(v - __half2float(h));
        long idx = (long)(bx + threadIdx.y + i) * DMODEL + x;
        hi[idx] = h;
        lo[idx] = l;
    }
}

__global__ void bias_table_kernel(const float* __restrict__ table)
{
    int idx = blockIdx.x * blockDim.x + threadIdx.x;
    if (idx >= RBR * NHEADS) return;
    int rel = idx / NHEADS - (SEQ - 1);
    int h   = idx % NHEADS;
    int bucket = (rel > 0) ? 16 : 0;
    int rp = rel < 0 ? -rel : rel;
    int v;
    if (rp < 8) {
        v = rp;
    } else {
        float f = logf((float)rp * 0.125f) / 2.772588722239781f * 8.0f;
        v = 8 + (int)f;
        if (v > 15) v = 15;
    }
    g_RB[idx] = table[(bucket + v) * NHEADS + h];
}

// =============================================================
// fp16-split GEMM: C = A @ B^T, A split, B hi(+optional lo).
// BL=true : 3-MMA (ah*bh + ah*bl + al*bh)  ~fp32
// BL=false: 2-MMA (ah*bh + al*bh)          (drops A*b_lo term)
// =============================================================
#define HPAD 24
#define HTILE (128 * HPAD)
#define HGEMM_SMEM (8 * HTILE * 2)

template<int MODE, bool BL>
__global__ __launch_bounds__(256)
void hgemm_kernel(const __half* __restrict__ Ahi, const __half* __restrict__ Alo,
                  const __half* __restrict__ Bhi, const __half* __restrict__ Blo,
                  __half* __restrict__ Chi, __half* __restrict__ Clo,
                  float* __restrict__ Cf)
{
    extern __shared__ __half hsm[];
    const int tid  = threadIdx.x;
    const int wid  = tid >> 5;
    const int lane = tid & 31;
    const int wr   = wid & 1;
    const int wc   = wid >> 1;
    const long bm  = blockIdx.y * 128;
    const long bn  = blockIdx.x * 128;
    const uint32_t s0 = smem_u32(hsm);

    float acc[4][4][4];
    #pragma unroll
    for (int i = 0; i < 4; i++)
        #pragma unroll
        for (int j = 0; j < 4; j++)
            #pragma unroll
            for (int k = 0; k < 4; k++) acc[i][j][k] = 0.0f;

    auto load_tiles = [&](int it, int stage) {
        int k0 = it * 16;
        int row = tid >> 1, c = tid & 1;
        uint32_t off = stage * (HTILE * 2) + row * (HPAD * 2) + c * 16;
        long asrc = (bm + row) * (long)DMODEL + k0 + c * 8;
        long bsrc = (bn + row) * (long)DMODEL + k0 + c * 8;
        cp_async16(s0 + off,         Ahi + asrc);
        cp_async16(s0 + 12288 + off, Alo + asrc);
        cp_async16(s0 + 24576 + off, Bhi + bsrc);
        if (BL) cp_async16(s0 + 36864 + off, Blo + bsrc);
        CP_ASYNC_COMMIT();
    };

    const int lrow  = lane & 15;
    const int lcolB = (lane >= 16) ? 16 : 0;

    load_tiles(0, 0);

    for (int it = 0; it < DMODEL / 16; it++) {
        const int buf = it & 1;
        if (it + 1 < DMODEL / 16) { load_tiles(it + 1, buf ^ 1); CP_ASYNC_WAIT(1); }
        else                      { CP_ASYNC_WAIT(0); }
        __syncthreads();

        const uint32_t ah = s0 + buf * (HTILE * 2);
        const uint32_t al = ah + 12288;
        const __half*  bh = hsm + buf * HTILE + 12288;
        const __half*  bl = hsm + buf * HTILE + 18432;

        uint32_t afh[4][4], afl[4][4];
        #pragma unroll
        for (int mt = 0; mt < 4; mt++) {
            int m = wr * 64 + mt * 16 + lrow;
            ldmatrix_x4(afh[mt], ah + m * (HPAD * 2) + lcolB);
            ldmatrix_x4(afl[mt], al + m * (HPAD * 2) + lcolB);
        }
        uint32_t bfh[4][2], bfl[4][2];
        #pragma unroll
        for (int nt = 0; nt < 4; nt++) {
            int n = wc * 32 + nt * 8 + (lane >> 2);
            int o = n * HPAD + (lane & 3) * 2;
            bfh[nt][0] = *(const uint32_t*)(bh + o);
            bfh[nt][1] = *(const uint32_t*)(bh + o + 8);
            if (BL) {
                bfl[nt][0] = *(const uint32_t*)(bl + o);
                bfl[nt][1] = *(const uint32_t*)(bl + o + 8);
            }
        }
        #pragma unroll
        for (int mt = 0; mt < 4; mt++)
            #pragma unroll
            for (int nt = 0; nt < 4; nt++) {
                mma_f16(acc[mt][nt], afh[mt], bfh[nt]);
                if (BL) mma_f16(acc[mt][nt], afh[mt], bfl[nt]);
                mma_f16(acc[mt][nt], afl[mt], bfh[nt]);
            }
        __syncthreads();
    }

    #pragma unroll
    for (int mt = 0; mt < 4; mt++) {
        long m0 = bm + wr * 64 + mt * 16 + (lane >> 2);
        #pragma unroll
        for (int nt = 0; nt < 4; nt++) {
            long n0 = bn + wc * 32 + nt * 8 + (lane & 3) * 2;
            float* a = acc[mt][nt];
            if (MODE == 2) {
                *(float2*)(Cf + m0 * INNER + n0)       = make_float2(a[0], a[1]);
                *(float2*)(Cf + (m0 + 8) * INNER + n0) = make_float2(a[2], a[3]);
            } else if (MODE == 0) {
                uint32_t h, l;
                split2(a[0], a[1], h, l);
                *(uint32_t*)(Chi + m0 * INNER + n0) = h;
                *(uint32_t*)(Clo + m0 * INNER + n0) = l;
                split2(a[2], a[3], h, l);
                *(uint32_t*)(Chi + (m0 + 8) * INNER + n0) = h;
                *(uint32_t*)(Clo + (m0 + 8) * INNER + n0) = l;
            } else {
                #pragma unroll
                for (int e = 0; e < 4; e++) {
                    long m = m0 + ((e >= 2) ? 8 : 0);
                    long n = n0 + (e & 1);
                    __half h = __float2half_rn(a[e]);
                    __half l = __float2half_rn(a[e] - __half2float(h));
                    Chi[n * NTOK + m] = h;
                    Clo[n * NTOK + m] = l;
                }
            }
        }
    }
}

// =============================================================
// fp16-split flash attention v3.
// 4 warps x 32q. QK: 2-MMA (K hi only). PV: 2-MMA (P hi only,
// V split). Stage = Khi + Vhi + Vlo = 27648 B, double-buffered.
// Q staging region aliases stage 1 (consumed before first reuse).
// =============================================================
#define KSTAGE 27648                 // Khi, Vhi, Vlo x 9216 bytes
#define QOFF   27648                 // Q hi/lo staging (36864 B), aliases stage1
#define RBOFF  (QOFF + 36864)        // 64512
#define ATT_SMEM (RBOFF + 191*4)
#define KROWB 144                    // 64 halfs + 16B pad per row

__global__ __launch_bounds__(128, 2)
void attn_kernel(const __half* __restrict__ Qhi, const __half* __restrict__ Qlo,
                 const __half* __restrict__ Khi,
                 const __half* __restrict__ Vthi, const __half* __restrict__ Vtlo,
                 __half* __restrict__ Chi, __half* __restrict__ Clo)
{
    extern __shared__ char smraw[];
    float* rbs = (float*)(smraw + RBOFF);
    const int tid  = threadIdx.x;
    const int w    = tid >> 5;
    const int lane = tid & 31;
    const int bh   = blockIdx.y;
    const int b    = bh >> 4;
    const int h    = bh & 15;
    const int q0   = blockIdx.x * 128;
    const uint32_t sb = smem_u32(smraw);
    const int grow = lane >> 2;
    const int gc   = (lane & 3) * 2;

    auto load_kv = [&](int t, int stage) {
        int k0 = t * 64;
        uint32_t sbase = sb + stage * KSTAGE;
        #pragma unroll
        for (int i = 0; i < 12; i++) {
            int id  = tid + i * 128;
            int sel = id >> 9;            // 0 Khi, 1 Vhi, 2 Vlo
            int wi  = id & 511;
            int row = wi >> 3, c = wi & 7;
            uint32_t dst = sbase + sel * 9216 + row * KROWB + c * 16;
            const __half* src;
            if (sel == 0) {
                src = Khi + (long)(b * SEQ + k0 + row) * INNER + h * DKV + c * 8;
            } else {
                const __half* base = (sel == 2) ? Vtlo : Vthi;
                src = base + (long)(h * DKV + row) * NTOK + b * SEQ + k0 + c * 8;
            }
            cp_async16(dst, src);
        }
        CP_ASYNC_COMMIT();
    };

    // ---- prologue: Q (hi+lo, 128 rows) -> QOFF region; KV tile 0 -> stage0 ----
    #pragma unroll
    for (int i = 0; i < 16; i++) {
        int id  = tid + i * 128;
        int sel = id >> 10;               // 0 hi, 1 lo
        int wi  = id & 1023;
        int row = wi >> 3, c = wi & 7;
        uint32_t dst = sb + QOFF + sel * 18432 + row * KROWB + c * 16;
        const __half* src = (sel ? Qlo : Qhi) +
                            (long)(b * SEQ + q0 + row) * INNER + h * DKV + c * 8;
        cp_async16(dst, src);
    }
    load_kv(0, 0);
    CP_ASYNC_WAIT(0);
    __syncthreads();

    // Q fragments for both 16-row halves (persist whole kernel)
    uint32_t qh[2][4][4], ql[2][4][4];
    {
        uint32_t qbh = sb + QOFF;
        uint32_t qbl = qbh + 18432;
        int cofs = (lane >= 16) ? 16 : 0;
        #pragma unroll
        for (int hf = 0; hf < 2; hf++) {
            int r = w * 32 + hf * 16 + (lane & 15);
            #pragma unroll
            for (int ks = 0; ks < 4; ks++) {
                ldmatrix_x4(qh[hf][ks], qbh + r * KROWB + ks * 32 + cofs);
                ldmatrix_x4(ql[hf][ks], qbl + r * KROWB + ks * 32 + cofs);
            }
        }
    }

    float m[2][2], l[2][2];
    float o[2][8][4];
    #pragma unroll
    for (int hf = 0; hf < 2; hf++) {
        m[hf][0] = m[hf][1] = -3.0e38f;
        l[hf][0] = l[hf][1] = 0.0f;
        #pragma unroll
        for (int nt = 0; nt < 8; nt++)
            #pragma unroll
            for (int e = 0; e < 4; e++) o[hf][nt][e] = 0.0f;
    }

    for (int t = 0; t < SEQ / 64; t++) {
        __syncthreads();   // prior reads of both stages (and Q region) complete
        if (t + 1 < SEQ / 64) { load_kv(t + 1, (t + 1) & 1); CP_ASYNC_WAIT(1); }
        else                  { CP_ASYNC_WAIT(0); }
        for (int i = tid; i < 191; i += 128)
            rbs[i] = g_RB[(t * 64 - q0 + i - 127 + SEQ - 1) * NHEADS + h];
        __syncthreads();

        const char* kp = smraw + (t & 1) * KSTAGE;     // Khi
        const char* vh = kp + 9216;                    // Vhi
        const char* vl = kp + 18432;                   // Vlo

        // ---- S = Q @ K^T: 2-MMA (qh*kh + ql*kh), both halves share kh ----
        float s[2][8][4];
        #pragma unroll
        for (int hf = 0; hf < 2; hf++)
            #pragma unroll
            for (int nt = 0; nt < 8; nt++)
                #pragma unroll
                for (int e = 0; e < 4; e++) s[hf][nt][e] = 0.0f;

        #pragma unroll
        for (int ks = 0; ks < 4; ks++) {
            #pragma unroll
            for (int nt = 0; nt < 8; nt++) {
                uint32_t off = (nt * 8 + grow) * KROWB + ks * 32 + gc * 2;
                uint32_t bh_[2];
                bh_[0] = *(const uint32_t*)(kp + off);
                bh_[1] = *(const uint32_t*)(kp + off + 16);
                mma_f16(s[0][nt], qh[0][ks], bh_);
                mma_f16(s[0][nt], ql[0][ks], bh_);
                mma_f16(s[1][nt], qh[1][ks], bh_);
                mma_f16(s[1][nt], ql[1][ks], bh_);
            }
        }

        // ---- bias + online softmax per half ----
        #pragma unroll
        for (int hf = 0; hf < 2; hf++) {
            const int rb0 = 127 - (w * 32 + hf * 16 + grow);
            #pragma unroll
            for (int nt = 0; nt < 8; nt++) {
                int cb = nt * 8 + gc;
                s[hf][nt][0] += rbs[cb + rb0];
                s[hf][nt][1] += rbs[cb + 1 + rb0];
                s[hf][nt][2] += rbs[cb + rb0 - 8];
                s[hf][nt][3] += rbs[cb + 1 + rb0 - 8];
            }
            float tm0 = -3.0e38f, tm1 = -3.0e38f;
            #pragma unroll
            for (int nt = 0; nt < 8; nt++) {
                tm0 = fmaxf(tm0, fmaxf(s[hf][nt][0], s[hf][nt][1]));
                tm1 = fmaxf(tm1, fmaxf(s[hf][nt][2], s[hf][nt][3]));
            }
            tm0 = fmaxf(tm0, __shfl_xor_sync(0xffffffffu, tm0, 1));
            tm0 = fmaxf(tm0, __shfl_xor_sync(0xffffffffu, tm0, 2));
            tm1 = fmaxf(tm1, __shfl_xor_sync(0xffffffffu, tm1, 1));
            tm1 = fmaxf(tm1, __shfl_xor_sync(0xffffffffu, tm1, 2));
            float nm0 = fmaxf(m[hf][0], tm0), nm1 = fmaxf(m[hf][1], tm1);
            float sc0 = __expf(m[hf][0] - nm0), sc1 = __expf(m[hf][1] - nm1);
            float ls0 = 0.0f, ls1 = 0.0f;
            #pragma unroll
            for (int nt = 0; nt < 8; nt++) {
                s[hf][nt][0] = __expf(s[hf][nt][0] - nm0); ls0 += s[hf][nt][0];
                s[hf][nt][1] = __expf(s[hf][nt][1] - nm0); ls0 += s[hf][nt][1];
                s[hf][nt][2] = __expf(s[hf][nt][2] - nm1); ls1 += s[hf][nt][2];
                s[hf][nt][3] = __expf(s[hf][nt][3] - nm1); ls1 += s[hf][nt][3];
            }
            ls0 += __shfl_xor_sync(0xffffffffu, ls0, 1);
            ls0 += __shfl_xor_sync(0xffffffffu, ls0, 2);
            ls1 += __shfl_xor_sync(0xffffffffu, ls1, 1);
            ls1 += __shfl_xor_sync(0xffffffffu, ls1, 2);
            l[hf][0] = l[hf][0] * sc0 + ls0;
            l[hf][1] = l[hf][1] * sc1 + ls1;
            m[hf][0] = nm0;  m[hf][1] = nm1;
            #pragma unroll
            for (int nt = 0; nt < 8; nt++) {
                o[hf][nt][0] *= sc0; o[hf][nt][1] *= sc0;
                o[hf][nt][2] *= sc1; o[hf][nt][3] *= sc1;
            }
        }

        // ---- O += P @ V: 2-MMA (ph*vh + ph*vl), both halves share V ----
        #pragma unroll
        for (int ks = 0; ks < 4; ks++) {
            uint32_t ph[2][4];
            #pragma unroll
            for (int hf = 0; hf < 2; hf++) {
                ph[hf][0] = pack_half2(s[hf][2*ks][0],   s[hf][2*ks][1]);
                ph[hf][1] = pack_half2(s[hf][2*ks][2],   s[hf][2*ks][3]);
                ph[hf][2] = pack_half2(s[hf][2*ks+1][0], s[hf][2*ks+1][1]);
                ph[hf][3] = pack_half2(s[hf][2*ks+1][2], s[hf][2*ks+1][3]);
            }
            #pragma unroll
            for (int nt = 0; nt < 8; nt++) {
                uint32_t off = (nt * 8 + grow) * KROWB + ks * 32 + gc * 2;
                uint32_t vh_[2], vl_[2];
                vh_[0] = *(const uint32_t*)(vh + off);
                vh_[1] = *(const uint32_t*)(vh + off + 16);
                vl_[0] = *(const uint32_t*)(vl + off);
                vl_[1] = *(const uint32_t*)(vl + off + 16);
                mma_f16(o[0][nt], ph[0], vh_);
                mma_f16(o[0][nt], ph[0], vl_);
                mma_f16(o[1][nt], ph[1], vh_);
                mma_f16(o[1][nt], ph[1], vl_);
            }
        }
    }

    // ---- epilogue: normalize, split, store ctx hi/lo ----
    #pragma unroll
    for (int hf = 0; hf < 2; hf++) {
        float i0 = 1.0f / l[hf][0], i1 = 1.0f / l[hf][1];
        long tok0 = (long)b * SEQ + q0 + w * 32 + hf * 16 + grow;
        #pragma unroll
        for (int nt = 0; nt < 8; nt++) {
            long col = h * DKV + nt * 8 + gc;
            uint32_t hh, ll;
            split2(o[hf][nt][0] * i0, o[hf][nt][1] * i0, hh, ll);
            *(uint32_t*)(Chi + tok0 * INNER + col) = hh;
            *(uint32_t*)(Clo + tok0 * INNER + col) = ll;
            split2(o[hf][nt][2] * i1, o[hf][nt][3] * i1, hh, ll);
            *(uint32_t*)(Chi + (tok0 + 8) * INNER + col) = hh;
            *(uint32_t*)(Clo + (tok0 + 8) * INNER + col) = ll;
        }
    }
}

// =============================================================
// Host launcher
// =============================================================
extern "C" void kernel_launch(void* const* d_in, const int* in_sizes, int n_in,
                              void* d_out, int out_size)
{
    const float* X   = (const float*)d_in[0];
    const float* wq  = (const float*)d_in[1];
    const float* wk  = (const float*)d_in[2];
    const float* wv  = (const float*)d_in[3];
    const float* wo  = (const float*)d_in[4];
    const float* rbt = (const float*)d_in[5];
    float* out = (float*)d_out;

    __half *Xhi, *Xlo, *Whi, *Wlo, *Qhi, *Qlo, *Khi, *Klo, *Vthi, *Vtlo, *Chi, *Clo;
    cudaGetSymbolAddress((void**)&Xhi,  g_Xhi);   cudaGetSymbolAddress((void**)&Xlo,  g_Xlo);
    cudaGetSymbolAddress((void**)&Whi,  g_Whi);   cudaGetSymbolAddress((void**)&Wlo,  g_Wlo);
    cudaGetSymbolAddress((void**)&Qhi,  g_Qhi);   cudaGetSymbolAddress((void**)&Qlo,  g_Qlo);
    cudaGetSymbolAddress((void**)&Khi,  g_Khi);   cudaGetSymbolAddress((void**)&Klo,  g_Klo);
    cudaGetSymbolAddress((void**)&Vthi, g_Vthi);  cudaGetSymbolAddress((void**)&Vtlo, g_Vtlo);
    cudaGetSymbolAddress((void**)&Chi,  g_Chi);   cudaGetSymbolAddress((void**)&Clo,  g_Clo);

    const long WOFF = (long)DMODEL * INNER;

    // preprocessing
    bias_table_kernel<<<(RBR * NHEADS + 255) / 256, 256>>>(rbt);
    split_kernel<<<(NTOK * DMODEL / 4 + 255) / 256, 256>>>(
        (const float4*)X, Xhi, Xlo, NTOK * DMODEL / 4);
    dim3 tb(32, 8), tg(32, 32);
    transpose_split_kernel<<<tg, tb>>>(wq, Whi + 0 * WOFF, Wlo + 0 * WOFF);
    transpose_split_kernel<<<tg, tb>>>(wk, Whi + 1 * WOFF, Wlo + 1 * WOFF);
    transpose_split_kernel<<<tg, tb>>>(wv, Whi + 2 * WOFF, Wlo + 2 * WOFF);
    transpose_split_kernel<<<tg, tb>>>(wo, Whi + 3 * WOFF, Wlo + 3 * WOFF);

    // projections: Q,K 2-MMA (weight-lo dropped); V,O 3-MMA
    cudaFuncSetAttribute((const void*)hgemm_kernel<0,false>, cudaFuncAttributeMaxDynamicSharedMemorySize, HGEMM_SMEM);
    cudaFuncSetAttribute((const void*)hgemm_kernel<1,true>,  cudaFuncAttributeMaxDynamicSharedMemorySize, HGEMM_SMEM);
    cudaFuncSetAttribute((const void*)hgemm_kernel<2,true>,  cudaFuncAttributeMaxDynamicSharedMemorySize, HGEMM_SMEM);
    dim3 gg(INNER / 128, NTOK / 128);   // (8, 32)
    hgemm_kernel<0,false><<<gg, 256, HGEMM_SMEM>>>(Xhi, Xlo, Whi + 0*WOFF, Wlo + 0*WOFF, Qhi, Qlo, nullptr);
    hgemm_kernel<0,false><<<gg, 256, HGEMM_SMEM>>>(Xhi, Xlo, Whi + 1*WOFF, Wlo + 1*WOFF, Khi, Klo, nullptr);
    hgemm_kernel<1,true ><<<gg, 256, HGEMM_SMEM>>>(Xhi, Xlo, Whi + 2*WOFF, Wlo + 2*WOFF, Vthi, Vtlo, nullptr);

    // attention
    cudaFuncSetAttribute(attn_kernel, cudaFuncAttributeMaxDynamicSharedMemorySize, ATT_SMEM);
    attn_kernel<<<dim3(SEQ / 128, BATCH * NHEADS), 128, ATT_SMEM>>>(
        Qhi, Qlo, Khi, Vthi, Vtlo, Chi, Clo);

    // output projection (float out, 3-MMA)
    hgemm_kernel<2,true><<<gg, 256, HGEMM_SMEM>>>(Chi, Clo, Whi + 3*WOFF, Wlo + 3*WOFF,
                                                  nullptr, nullptr, out);
}

// round 7
// speedup vs baseline: 3.4581x; 1.0901x over previous
#include <cuda_runtime.h>
#include <cuda_fp16.h>
#include <math.h>
#include <stdint.h>

#define BATCH   2
#define SEQ     2048
#define DMODEL  1024
#define NHEADS  16
#define DKV     64
#define INNER   1024
#define NTOK    (BATCH*SEQ)          // 4096
#define RBR     (2*SEQ-1)            // 4095

// -------- scratch (device globals: no allocation allowed) --------
__device__ __half g_Xhi[NTOK*DMODEL],  g_Xlo[NTOK*DMODEL];
__device__ __half g_Whi[4*DMODEL*INNER], g_Wlo[4*DMODEL*INNER];
__device__ __half g_Qhi[NTOK*INNER],  g_Qlo[NTOK*INNER];
__device__ __half g_Khi[NTOK*INNER],  g_Klo[NTOK*INNER];
__device__ __half g_Vthi[NTOK*INNER], g_Vtlo[NTOK*INNER];   // transposed [n][token]
__device__ __half g_Chi[NTOK*INNER],  g_Clo[NTOK*INNER];
__device__ float  g_RB[RBR*NHEADS];

// ============================================================
// helpers
// ============================================================
__device__ __forceinline__ uint32_t smem_u32(const void* p) {
    uint32_t a;
    asm("{ .reg .u64 t; cvta.to.shared.u64 t, %1; cvt.u32.u64 %0, t; }" : "=r"(a) : "l"(p));
    return a;
}
__device__ __forceinline__ void cp_async16(uint32_t dst, const void* src) {
    asm volatile("cp.async.cg.shared.global [%0], [%1], 16;\n" :: "r"(dst), "l"(src) : "memory");
}
#define CP_ASYNC_COMMIT() asm volatile("cp.async.commit_group;\n" ::: "memory")
#define CP_ASYNC_WAIT(n)  asm volatile("cp.async.wait_group %0;\n" :: "n"(n) : "memory")

__device__ __forceinline__ void ldmatrix_x4(uint32_t* r, uint32_t addr) {
    asm volatile("ldmatrix.sync.aligned.m8n8.x4.shared.b16 {%0,%1,%2,%3}, [%4];"
                 : "=r"(r[0]), "=r"(r[1]), "=r"(r[2]), "=r"(r[3]) : "r"(addr));
}
__device__ __forceinline__ void mma_f16(float* d, const uint32_t* a, const uint32_t* b) {
    asm volatile(
        "mma.sync.aligned.m16n8k16.row.col.f32.f16.f16.f32 "
        "{%0,%1,%2,%3}, {%4,%5,%6,%7}, {%8,%9}, {%0,%1,%2,%3};"
        : "+f"(d[0]), "+f"(d[1]), "+f"(d[2]), "+f"(d[3])
        : "r"(a[0]), "r"(a[1]), "r"(a[2]), "r"(a[3]), "r"(b[0]), "r"(b[1]));
}
__device__ __forceinline__ void split2(float f0, float f1, uint32_t& hi, uint32_t& lo) {
    __half h0 = __float2half_rn(f0), h1 = __float2half_rn(f1);
    __half l0 = __float2half_rn(f0 - __half2float(h0));
    __half l1 = __float2half_rn(f1 - __half2float(h1));
    hi = (uint32_t)__half_as_ushort(h0) | ((uint32_t)__half_as_ushort(h1) << 16);
    lo = (uint32_t)__half_as_ushort(l0) | ((uint32_t)__half_as_ushort(l1) << 16);
}
__device__ __forceinline__ uint32_t pack_half2(float f0, float f1) {
    __half2 h = __floats2half2_rn(f0, f1);
    return *(uint32_t*)&h;
}

// =============================================================
// Pre-processing
// =============================================================
__global__ void split_kernel(const float4* __restrict__ in,
                             __half* __restrict__ hi, __half* __restrict__ lo, int n4)
{
    int i = blockIdx.x * blockDim.x + threadIdx.x;
    if (i < n4) {
        float4 v = in[i];
        uint32_t h0, l0, h1, l1;
        split2(v.x, v.y, h0, l0);
        split2(v.z, v.w, h1, l1);
        *(uint2*)(hi + 4l * i) = make_uint2(h0, h1);
        *(uint2*)(lo + 4l * i) = make_uint2(l0, l1);
    }
}

// fused: all 4 weight transposes in one launch (z selects matrix)
__global__ void transpose_split4_kernel(const float* __restrict__ w0,
                                        const float* __restrict__ w1,
                                        const float* __restrict__ w2,
                                        const float* __restrict__ w3,
                                        __half* __restrict__ hi_base,
                                        __half* __restrict__ lo_base)
{
    __shared__ float tile[32][33];
    const float* in;
    switch (blockIdx.z) {
        case 0: in = w0; break;
        case 1: in = w1; break;
        case 2: in = w2; break;
        default: in = w3; break;
    }
    __half* hi = hi_base + (long)blockIdx.z * DMODEL * INNER;
    __half* lo = lo_base + (long)blockIdx.z * DMODEL * INNER;

    int bx = blockIdx.x * 32, by = blockIdx.y * 32;
    int x = bx + threadIdx.x;
    #pragma unroll
    for (int i = 0; i < 32; i += 8)
        tile[threadIdx.y + i][threadIdx.x] = in[(by + threadIdx.y + i) * DMODEL + x];
    __syncthreads();
    x = by + threadIdx.x;
    #pragma unroll
    for (int i = 0; i < 32; i += 8) {
        float v = tile[threadIdx.x][threadIdx.y + i];
        __half h = __float2half_rn(v);
        __half l = __float2half_rn(v - __half2float(h));
        long idx = (long)(bx + threadIdx.y + i) * DMODEL + x;
        hi[idx] = h;
        lo[idx] = l;
    }
}

__global__ void bias_table_kernel(const float* __restrict__ table)
{
    int idx = blockIdx.x * blockDim.x + threadIdx.x;
    if (idx >= RBR * NHEADS) return;
    int rel = idx / NHEADS - (SEQ - 1);
    int h   = idx % NHEADS;
    int bucket = (rel > 0) ? 16 : 0;
    int rp = rel < 0 ? -rel : rel;
    int v;
    if (rp < 8) {
        v = rp;
    } else {
        float f = logf((float)rp * 0.125f) / 2.772588722239781f * 8.0f;
        v = 8 + (int)f;
        if (v > 15) v = 15;
    }
    g_RB[idx] = table[(bucket + v) * NHEADS + h];
}

// =============================================================
// Fused QKV projection. Grid (24, 32): bx/8 = matrix (0 Q, 1 K,
// 2 V), bx%8 = n-tile. Q,K: 2-MMA, hi/lo out. V: 3-MMA,
// transposed hi/lo out. Identical per-tile numerics to round 6.
// =============================================================
#define HPAD 24
#define HTILE (128 * HPAD)
#define HGEMM_SMEM (8 * HTILE * 2)

__global__ __launch_bounds__(256)
void qkv_kernel(const __half* __restrict__ Xhi, const __half* __restrict__ Xlo,
                const __half* __restrict__ Whi_base, const __half* __restrict__ Wlo_base,
                __half* __restrict__ Qhi, __half* __restrict__ Qlo,
                __half* __restrict__ Khi, __half* __restrict__ Klo,
                __half* __restrict__ Vthi, __half* __restrict__ Vtlo)
{
    extern __shared__ __half hsm[];
    const int mat  = blockIdx.x >> 3;         // 0 Q, 1 K, 2 V
    const bool isV = (mat == 2);
    const __half* Bhi = Whi_base + (long)mat * DMODEL * INNER;
    const __half* Blo = Wlo_base + (long)mat * DMODEL * INNER;

    const int tid  = threadIdx.x;
    const int wid  = tid >> 5;
    const int lane = tid & 31;
    const int wr   = wid & 1;
    const int wc   = wid >> 1;
    const long bm  = blockIdx.y * 128;
    const long bn  = (blockIdx.x & 7) * 128;
    const uint32_t s0 = smem_u32(hsm);

    float acc[4][4][4];
    #pragma unroll
    for (int i = 0; i < 4; i++)
        #pragma unroll
        for (int j = 0; j < 4; j++)
            #pragma unroll
            for (int k = 0; k < 4; k++) acc[i][j][k] = 0.0f;

    auto load_tiles = [&](int it, int stage) {
        int k0 = it * 16;
        int row = tid >> 1, c = tid & 1;
        uint32_t off = stage * (HTILE * 2) + row * (HPAD * 2) + c * 16;
        long asrc = (bm + row) * (long)DMODEL + k0 + c * 8;
        long bsrc = (bn + row) * (long)DMODEL + k0 + c * 8;
        cp_async16(s0 + off,         Xhi + asrc);
        cp_async16(s0 + 12288 + off, Xlo + asrc);
        cp_async16(s0 + 24576 + off, Bhi + bsrc);
        if (isV) cp_async16(s0 + 36864 + off, Blo + bsrc);
        CP_ASYNC_COMMIT();
    };

    const int lrow  = lane & 15;
    const int lcolB = (lane >= 16) ? 16 : 0;

    load_tiles(0, 0);

    for (int it = 0; it < DMODEL / 16; it++) {
        const int buf = it & 1;
        if (it + 1 < DMODEL / 16) { load_tiles(it + 1, buf ^ 1); CP_ASYNC_WAIT(1); }
        else                      { CP_ASYNC_WAIT(0); }
        __syncthreads();

        const uint32_t ah = s0 + buf * (HTILE * 2);
        const uint32_t al = ah + 12288;
        const __half*  bh = hsm + buf * HTILE + 12288;
        const __half*  bl = hsm + buf * HTILE + 18432;

        uint32_t afh[4][4], afl[4][4];
        #pragma unroll
        for (int mt = 0; mt < 4; mt++) {
            int m = wr * 64 + mt * 16 + lrow;
            ldmatrix_x4(afh[mt], ah + m * (HPAD * 2) + lcolB);
            ldmatrix_x4(afl[mt], al + m * (HPAD * 2) + lcolB);
        }
        uint32_t bfh[4][2], bfl[4][2];
        #pragma unroll
        for (int nt = 0; nt < 4; nt++) {
            int n = wc * 32 + nt * 8 + (lane >> 2);
            int o = n * HPAD + (lane & 3) * 2;
            bfh[nt][0] = *(const uint32_t*)(bh + o);
            bfh[nt][1] = *(const uint32_t*)(bh + o + 8);
            if (isV) {
                bfl[nt][0] = *(const uint32_t*)(bl + o);
                bfl[nt][1] = *(const uint32_t*)(bl + o + 8);
            }
        }
        if (isV) {
            #pragma unroll
            for (int mt = 0; mt < 4; mt++)
                #pragma unroll
                for (int nt = 0; nt < 4; nt++) {
                    mma_f16(acc[mt][nt], afh[mt], bfh[nt]);
                    mma_f16(acc[mt][nt], afh[mt], bfl[nt]);
                    mma_f16(acc[mt][nt], afl[mt], bfh[nt]);
                }
        } else {
            #pragma unroll
            for (int mt = 0; mt < 4; mt++)
                #pragma unroll
                for (int nt = 0; nt < 4; nt++) {
                    mma_f16(acc[mt][nt], afh[mt], bfh[nt]);
                    mma_f16(acc[mt][nt], afl[mt], bfh[nt]);
                }
        }
        __syncthreads();
    }

    // epilogue
    __half* Chi = (mat == 0) ? Qhi : (mat == 1) ? Khi : Vthi;
    __half* Clo = (mat == 0) ? Qlo : (mat == 1) ? Klo : Vtlo;
    #pragma unroll
    for (int mt = 0; mt < 4; mt++) {
        long m0 = bm + wr * 64 + mt * 16 + (lane >> 2);
        #pragma unroll
        for (int nt = 0; nt < 4; nt++) {
            long n0 = bn + wc * 32 + nt * 8 + (lane & 3) * 2;
            float* a = acc[mt][nt];
            if (!isV) {
                uint32_t h, l;
                split2(a[0], a[1], h, l);
                *(uint32_t*)(Chi + m0 * INNER + n0) = h;
                *(uint32_t*)(Clo + m0 * INNER + n0) = l;
                split2(a[2], a[3], h, l);
                *(uint32_t*)(Chi + (m0 + 8) * INNER + n0) = h;
                *(uint32_t*)(Clo + (m0 + 8) * INNER + n0) = l;
            } else {
                #pragma unroll
                for (int e = 0; e < 4; e++) {
                    long m = m0 + ((e >= 2) ? 8 : 0);
                    long n = n0 + (e & 1);
                    __half h = __float2half_rn(a[e]);
                    __half l = __float2half_rn(a[e] - __half2float(h));
                    Chi[n * NTOK + m] = h;
                    Clo[n * NTOK + m] = l;
                }
            }
        }
    }
}

// =============================================================
// O-projection GEMM (3-MMA, float out) — as round 6.
// =============================================================
__global__ __launch_bounds__(256)
void oproj_kernel(const __half* __restrict__ Ahi, const __half* __restrict__ Alo,
                  const __half* __restrict__ Bhi, const __half* __restrict__ Blo,
                  float* __restrict__ Cf)
{
    extern __shared__ __half hsm[];
    const int tid  = threadIdx.x;
    const int wid  = tid >> 5;
    const int lane = tid & 31;
    const int wr   = wid & 1;
    const int wc   = wid >> 1;
    const long bm  = blockIdx.y * 128;
    const long bn  = blockIdx.x * 128;
    const uint32_t s0 = smem_u32(hsm);

    float acc[4][4][4];
    #pragma unroll
    for (int i = 0; i < 4; i++)
        #pragma unroll
        for (int j = 0; j < 4; j++)
            #pragma unroll
            for (int k = 0; k < 4; k++) acc[i][j][k] = 0.0f;

    auto load_tiles = [&](int it, int stage) {
        int k0 = it * 16;
        int row = tid >> 1, c = tid & 1;
        uint32_t off = stage * (HTILE * 2) + row * (HPAD * 2) + c * 16;
        long asrc = (bm + row) * (long)DMODEL + k0 + c * 8;
        long bsrc = (bn + row) * (long)DMODEL + k0 + c * 8;
        cp_async16(s0 + off,         Ahi + asrc);
        cp_async16(s0 + 12288 + off, Alo + asrc);
        cp_async16(s0 + 24576 + off, Bhi + bsrc);
        cp_async16(s0 + 36864 + off, Blo + bsrc);
        CP_ASYNC_COMMIT();
    };

    const int lrow  = lane & 15;
    const int lcolB = (lane >= 16) ? 16 : 0;

    load_tiles(0, 0);

    for (int it = 0; it < DMODEL / 16; it++) {
        const int buf = it & 1;
        if (it + 1 < DMODEL / 16) { load_tiles(it + 1, buf ^ 1); CP_ASYNC_WAIT(1); }
        else                      { CP_ASYNC_WAIT(0); }
        __syncthreads();

        const uint32_t ah = s0 + buf * (HTILE * 2);
        const uint32_t al = ah + 12288;
        const __half*  bh = hsm + buf * HTILE + 12288;
        const __half*  bl = hsm + buf * HTILE + 18432;

        uint32_t afh[4][4], afl[4][4];
        #pragma unroll
        for (int mt = 0; mt < 4; mt++) {
            int m = wr * 64 + mt * 16 + lrow;
            ldmatrix_x4(afh[mt], ah + m * (HPAD * 2) + lcolB);
            ldmatrix_x4(afl[mt], al + m * (HPAD * 2) + lcolB);
        }
        uint32_t bfh[4][2], bfl[4][2];
        #pragma unroll
        for (int nt = 0; nt < 4; nt++) {
            int n = wc * 32 + nt * 8 + (lane >> 2);
            int o = n * HPAD + (lane & 3) * 2;
            bfh[nt][0] = *(const uint32_t*)(bh + o);
            bfh[nt][1] = *(const uint32_t*)(bh + o + 8);
            bfl[nt][0] = *(const uint32_t*)(bl + o);
            bfl[nt][1] = *(const uint32_t*)(bl + o + 8);
        }
        #pragma unroll
        for (int mt = 0; mt < 4; mt++)
            #pragma unroll
            for (int nt = 0; nt < 4; nt++) {
                mma_f16(acc[mt][nt], afh[mt], bfh[nt]);
                mma_f16(acc[mt][nt], afh[mt], bfl[nt]);
                mma_f16(acc[mt][nt], afl[mt], bfh[nt]);
            }
        __syncthreads();
    }

    #pragma unroll
    for (int mt = 0; mt < 4; mt++) {
        long m0 = bm + wr * 64 + mt * 16 + (lane >> 2);
        #pragma unroll
        for (int nt = 0; nt < 4; nt++) {
            long n0 = bn + wc * 32 + nt * 8 + (lane & 3) * 2;
            float* a = acc[mt][nt];
            *(float2*)(Cf + m0 * INNER + n0)       = make_float2(a[0], a[1]);
            *(float2*)(Cf + (m0 + 8) * INNER + n0) = make_float2(a[2], a[3]);
        }
    }
}

// =============================================================
// fp16-split flash attention (identical numerics to round 6).
// =============================================================
#define KSTAGE 27648                 // Khi, Vhi, Vlo x 9216 bytes
#define QOFF   27648                 // Q hi/lo staging, aliases stage1
#define RBOFF  (QOFF + 36864)
#define ATT_SMEM (RBOFF + 191*4)
#define KROWB 144

__global__ __launch_bounds__(128, 2)
void attn_kernel(const __half* __restrict__ Qhi, const __half* __restrict__ Qlo,
                 const __half* __restrict__ Khi,
                 const __half* __restrict__ Vthi, const __half* __restrict__ Vtlo,
                 __half* __restrict__ Chi, __half* __restrict__ Clo)
{
    extern __shared__ char smraw[];
    float* rbs = (float*)(smraw + RBOFF);
    const int tid  = threadIdx.x;
    const int w    = tid >> 5;
    const int lane = tid & 31;
    const int bh   = blockIdx.y;
    const int b    = bh >> 4;
    const int h    = bh & 15;
    const int q0   = blockIdx.x * 128;
    const uint32_t sb = smem_u32(smraw);
    const int grow = lane >> 2;
    const int gc   = (lane & 3) * 2;

    auto load_kv = [&](int t, int stage) {
        int k0 = t * 64;
        uint32_t sbase = sb + stage * KSTAGE;
        #pragma unroll
        for (int i = 0; i < 12; i++) {
            int id  = tid + i * 128;
            int sel = id >> 9;
            int wi  = id & 511;
            int row = wi >> 3, c = wi & 7;
            uint32_t dst = sbase + sel * 9216 + row * KROWB + c * 16;
            const __half* src;
            if (sel == 0) {
                src = Khi + (long)(b * SEQ + k0 + row) * INNER + h * DKV + c * 8;
            } else {
                const __half* base = (sel == 2) ? Vtlo : Vthi;
                src = base + (long)(h * DKV + row) * NTOK + b * SEQ + k0 + c * 8;
            }
            cp_async16(dst, src);
        }
        CP_ASYNC_COMMIT();
    };

    #pragma unroll
    for (int i = 0; i < 16; i++) {
        int id  = tid + i * 128;
        int sel = id >> 10;
        int wi  = id & 1023;
        int row = wi >> 3, c = wi & 7;
        uint32_t dst = sb + QOFF + sel * 18432 + row * KROWB + c * 16;
        const __half* src = (sel ? Qlo : Qhi) +
                            (long)(b * SEQ + q0 + row) * INNER + h * DKV + c * 8;
        cp_async16(dst, src);
    }
    load_kv(0, 0);
    CP_ASYNC_WAIT(0);
    __syncthreads();

    uint32_t qh[2][4][4], ql[2][4][4];
    {
        uint32_t qbh = sb + QOFF;
        uint32_t qbl = qbh + 18432;
        int cofs = (lane >= 16) ? 16 : 0;
        #pragma unroll
        for (int hf = 0; hf < 2; hf++) {
            int r = w * 32 + hf * 16 + (lane & 15);
            #pragma unroll
            for (int ks = 0; ks < 4; ks++) {
                ldmatrix_x4(qh[hf][ks], qbh + r * KROWB + ks * 32 + cofs);
                ldmatrix_x4(ql[hf][ks], qbl + r * KROWB + ks * 32 + cofs);
            }
        }
    }

    float m[2][2], l[2][2];
    float o[2][8][4];
    #pragma unroll
    for (int hf = 0; hf < 2; hf++) {
        m[hf][0] = m[hf][1] = -3.0e38f;
        l[hf][0] = l[hf][1] = 0.0f;
        #pragma unroll
        for (int nt = 0; nt < 8; nt++)
            #pragma unroll
            for (int e = 0; e < 4; e++) o[hf][nt][e] = 0.0f;
    }

    for (int t = 0; t < SEQ / 64; t++) {
        __syncthreads();
        if (t + 1 < SEQ / 64) { load_kv(t + 1, (t + 1) & 1); CP_ASYNC_WAIT(1); }
        else                  { CP_ASYNC_WAIT(0); }
        for (int i = tid; i < 191; i += 128)
            rbs[i] = g_RB[(t * 64 - q0 + i - 127 + SEQ - 1) * NHEADS + h];
        __syncthreads();

        const char* kp = smraw + (t & 1) * KSTAGE;
        const char* vh = kp + 9216;
        const char* vl = kp + 18432;

        float s[2][8][4];
        #pragma unroll
        for (int hf = 0; hf < 2; hf++)
            #pragma unroll
            for (int nt = 0; nt < 8; nt++)
                #pragma unroll
                for (int e = 0; e < 4; e++) s[hf][nt][e] = 0.0f;

        #pragma unroll
        for (int ks = 0; ks < 4; ks++) {
            #pragma unroll
            for (int nt = 0; nt < 8; nt++) {
                uint32_t off = (nt * 8 + grow) * KROWB + ks * 32 + gc * 2;
                uint32_t bh_[2];
                bh_[0] = *(const uint32_t*)(kp + off);
                bh_[1] = *(const uint32_t*)(kp + off + 16);
                mma_f16(s[0][nt], qh[0][ks], bh_);
                mma_f16(s[0][nt], ql[0][ks], bh_);
                mma_f16(s[1][nt], qh[1][ks], bh_);
                mma_f16(s[1][nt], ql[1][ks], bh_);
            }
        }

        #pragma unroll
        for (int hf = 0; hf < 2; hf++) {
            const int rb0 = 127 - (w * 32 + hf * 16 + grow);
            #pragma unroll
            for (int nt = 0; nt < 8; nt++) {
                int cb = nt * 8 + gc;
                s[hf][nt][0] += rbs[cb + rb0];
                s[hf][nt][1] += rbs[cb + 1 + rb0];
                s[hf][nt][2] += rbs[cb + rb0 - 8];
                s[hf][nt][3] += rbs[cb + 1 + rb0 - 8];
            }
            float tm0 = -3.0e38f, tm1 = -3.0e38f;
            #pragma unroll
            for (int nt = 0; nt < 8; nt++) {
                tm0 = fmaxf(tm0, fmaxf(s[hf][nt][0], s[hf][nt][1]));
                tm1 = fmaxf(tm1, fmaxf(s[hf][nt][2], s[hf][nt][3]));
            }
            tm0 = fmaxf(tm0, __shfl_xor_sync(0xffffffffu, tm0, 1));
            tm0 = fmaxf(tm0, __shfl_xor_sync(0xffffffffu, tm0, 2));
            tm1 = fmaxf(tm1, __shfl_xor_sync(0xffffffffu, tm1, 1));
            tm1 = fmaxf(tm1, __shfl_xor_sync(0xffffffffu, tm1, 2));
            float nm0 = fmaxf(m[hf][0], tm0), nm1 = fmaxf(m[hf][1], tm1);
            float sc0 = __expf(m[hf][0] - nm0), sc1 = __expf(m[hf][1] - nm1);
            float ls0 = 0.0f, ls1 = 0.0f;
            #pragma unroll
            for (int nt = 0; nt < 8; nt++) {
                s[hf][nt][0] = __expf(s[hf][nt][0] - nm0); ls0 += s[hf][nt][0];
                s[hf][nt][1] = __expf(s[hf][nt][1] - nm0); ls0 += s[hf][nt][1];
                s[hf][nt][2] = __expf(s[hf][nt][2] - nm1); ls1 += s[hf][nt][2];
                s[hf][nt][3] = __expf(s[hf][nt][3] - nm1); ls1 += s[hf][nt][3];
            }
            ls0 += __shfl_xor_sync(0xffffffffu, ls0, 1);
            ls0 += __shfl_xor_sync(0xffffffffu, ls0, 2);
            ls1 += __shfl_xor_sync(0xffffffffu, ls1, 1);
            ls1 += __shfl_xor_sync(0xffffffffu, ls1, 2);
            l[hf][0] = l[hf][0] * sc0 + ls0;
            l[hf][1] = l[hf][1] * sc1 + ls1;
            m[hf][0] = nm0;  m[hf][1] = nm1;
            #pragma unroll
            for (int nt = 0; nt < 8; nt++) {
                o[hf][nt][0] *= sc0; o[hf][nt][1] *= sc0;
                o[hf][nt][2] *= sc1; o[hf][nt][3] *= sc1;
            }
        }

        #pragma unroll
        for (int ks = 0; ks < 4; ks++) {
            uint32_t ph[2][4];
            #pragma unroll
            for (int hf = 0; hf < 2; hf++) {
                ph[hf][0] = pack_half2(s[hf][2*ks][0],   s[hf][2*ks][1]);
                ph[hf][1] = pack_half2(s[hf][2*ks][2],   s[hf][2*ks][3]);
                ph[hf][2] = pack_half2(s[hf][2*ks+1][0], s[hf][2*ks+1][1]);
                ph[hf][3] = pack_half2(s[hf][2*ks+1][2], s[hf][2*ks+1][3]);
            }
            #pragma unroll
            for (int nt = 0; nt < 8; nt++) {
                uint32_t off = (nt * 8 + grow) * KROWB + ks * 32 + gc * 2;
                uint32_t vh_[2], vl_[2];
                vh_[0] = *(const uint32_t*)(vh + off);
                vh_[1] = *(const uint32_t*)(vh + off + 16);
                vl_[0] = *(const uint32_t*)(vl + off);
                vl_[1] = *(const uint32_t*)(vl + off + 16);
                mma_f16(o[0][nt], ph[0], vh_);
                mma_f16(o[0][nt], ph[0], vl_);
                mma_f16(o[1][nt], ph[1], vh_);
                mma_f16(o[1][nt], ph[1], vl_);
            }
        }
    }

    #pragma unroll
    for (int hf = 0; hf < 2; hf++) {
        float i0 = 1.0f / l[hf][0], i1 = 1.0f / l[hf][1];
        long tok0 = (long)b * SEQ + q0 + w * 32 + hf * 16 + grow;
        #pragma unroll
        for (int nt = 0; nt < 8; nt++) {
            long col = h * DKV + nt * 8 + gc;
            uint32_t hh, ll;
            split2(o[hf][nt][0] * i0, o[hf][nt][1] * i0, hh, ll);
            *(uint32_t*)(Chi + tok0 * INNER + col) = hh;
            *(uint32_t*)(Clo + tok0 * INNER + col) = ll;
            split2(o[hf][nt][2] * i1, o[hf][nt][3] * i1, hh, ll);
            *(uint32_t*)(Chi + (tok0 + 8) * INNER + col) = hh;
            *(uint32_t*)(Clo + (tok0 + 8) * INNER + col) = ll;
        }
    }
}

// =============================================================
// Host launcher
// =============================================================
extern "C" void kernel_launch(void* const* d_in, const int* in_sizes, int n_in,
                              void* d_out, int out_size)
{
    const float* X   = (const float*)d_in[0];
    const float* wq  = (const float*)d_in[1];
    const float* wk  = (const float*)d_in[2];
    const float* wv  = (const float*)d_in[3];
    const float* wo  = (const float*)d_in[4];
    const float* rbt = (const float*)d_in[5];
    float* out = (float*)d_out;

    __half *Xhi, *Xlo, *Whi, *Wlo, *Qhi, *Qlo, *Khi, *Klo, *Vthi, *Vtlo, *Chi, *Clo;
    cudaGetSymbolAddress((void**)&Xhi,  g_Xhi);   cudaGetSymbolAddress((void**)&Xlo,  g_Xlo);
    cudaGetSymbolAddress((void**)&Whi,  g_Whi);   cudaGetSymbolAddress((void**)&Wlo,  g_Wlo);
    cudaGetSymbolAddress((void**)&Qhi,  g_Qhi);   cudaGetSymbolAddress((void**)&Qlo,  g_Qlo);
    cudaGetSymbolAddress((void**)&Khi,  g_Khi);   cudaGetSymbolAddress((void**)&Klo,  g_Klo);
    cudaGetSymbolAddress((void**)&Vthi, g_Vthi);  cudaGetSymbolAddress((void**)&Vtlo, g_Vtlo);
    cudaGetSymbolAddress((void**)&Chi,  g_Chi);   cudaGetSymbolAddress((void**)&Clo,  g_Clo);

    const long WOFF = (long)DMODEL * INNER;

    // preprocessing (3 launches)
    bias_table_kernel<<<(RBR * NHEADS + 255) / 256, 256>>>(rbt);
    split_kernel<<<(NTOK * DMODEL / 4 + 255) / 256, 256>>>(
        (const float4*)X, Xhi, Xlo, NTOK * DMODEL / 4);
    transpose_split4_kernel<<<dim3(32, 32, 4), dim3(32, 8)>>>(wq, wk, wv, wo, Whi, Wlo);

    // fused QKV projections (one launch, 768 CTAs)
    cudaFuncSetAttribute(qkv_kernel, cudaFuncAttributeMaxDynamicSharedMemorySize, HGEMM_SMEM);
    qkv_kernel<<<dim3(24, 32), 256, HGEMM_SMEM>>>(Xhi, Xlo, Whi, Wlo,
                                                  Qhi, Qlo, Khi, Klo, Vthi, Vtlo);

    // attention
    cudaFuncSetAttribute(attn_kernel, cudaFuncAttributeMaxDynamicSharedMemorySize, ATT_SMEM);
    attn_kernel<<<dim3(SEQ / 128, BATCH * NHEADS), 128, ATT_SMEM>>>(
        Qhi, Qlo, Khi, Vthi, Vtlo, Chi, Clo);

    // output projection (float out, 3-MMA)
    cudaFuncSetAttribute(oproj_kernel, cudaFuncAttributeMaxDynamicSharedMemorySize, HGEMM_SMEM);
    oproj_kernel<<<dim3(DMODEL / 128, NTOK / 128), 256, HGEMM_SMEM>>>(
        Chi, Clo, Whi + 3 * WOFF, Wlo + 3 * WOFF, out);
}

// round 8
// speedup vs baseline: 3.5395x; 1.0235x over previous
#include <cuda_runtime.h>
#include <cuda_fp16.h>
#include <math.h>
#include <stdint.h>

#define BATCH   2
#define SEQ     2048
#define DMODEL  1024
#define NHEADS  16
#define DKV     64
#define INNER   1024
#define NTOK    (BATCH*SEQ)          // 4096
#define RBR     (2*SEQ-1)            // 4095

// -------- scratch (device globals: no allocation allowed) --------
__device__ __half g_Xhi[NTOK*DMODEL],  g_Xlo[NTOK*DMODEL];
__device__ __half g_Whi[4*DMODEL*INNER], g_Wlo[4*DMODEL*INNER];
__device__ __half g_Qhi[NTOK*INNER],  g_Qlo[NTOK*INNER];
__device__ __half g_Khi[NTOK*INNER],  g_Klo[NTOK*INNER];
__device__ __half g_Vthi[NTOK*INNER], g_Vtlo[NTOK*INNER];   // transposed [n][token]
__device__ __half g_Chi[NTOK*INNER],  g_Clo[NTOK*INNER];
__device__ float  g_RB[RBR*NHEADS];

// ============================================================
// helpers
// ============================================================
__device__ __forceinline__ uint32_t smem_u32(const void* p) {
    uint32_t a;
    asm("{ .reg .u64 t; cvta.to.shared.u64 t, %1; cvt.u32.u64 %0, t; }" : "=r"(a) : "l"(p));
    return a;
}
__device__ __forceinline__ void cp_async16(uint32_t dst, const void* src) {
    asm volatile("cp.async.cg.shared.global [%0], [%1], 16;\n" :: "r"(dst), "l"(src) : "memory");
}
#define CP_ASYNC_COMMIT() asm volatile("cp.async.commit_group;\n" ::: "memory")
#define CP_ASYNC_WAIT(n)  asm volatile("cp.async.wait_group %0;\n" :: "n"(n) : "memory")

__device__ __forceinline__ void ldmatrix_x4(uint32_t* r, uint32_t addr) {
    asm volatile("ldmatrix.sync.aligned.m8n8.x4.shared.b16 {%0,%1,%2,%3}, [%4];"
                 : "=r"(r[0]), "=r"(r[1]), "=r"(r[2]), "=r"(r[3]) : "r"(addr));
}
__device__ __forceinline__ void mma_f16(float* d, const uint32_t* a, const uint32_t* b) {
    asm volatile(
        "mma.sync.aligned.m16n8k16.row.col.f32.f16.f16.f32 "
        "{%0,%1,%2,%3}, {%4,%5,%6,%7}, {%8,%9}, {%0,%1,%2,%3};"
        : "+f"(d[0]), "+f"(d[1]), "+f"(d[2]), "+f"(d[3])
        : "r"(a[0]), "r"(a[1]), "r"(a[2]), "r"(a[3]), "r"(b[0]), "r"(b[1]));
}
__device__ __forceinline__ void split2(float f0, float f1, uint32_t& hi, uint32_t& lo) {
    __half h0 = __float2half_rn(f0), h1 = __float2half_rn(f1);
    __half l0 = __float2half_rn(f0 - __half2float(h0));
    __half l1 = __float2half_rn(f1 - __half2float(h1));
    hi = (uint32_t)__half_as_ushort(h0) | ((uint32_t)__half_as_ushort(h1) << 16);
    lo = (uint32_t)__half_as_ushort(l0) | ((uint32_t)__half_as_ushort(l1) << 16);
}
__device__ __forceinline__ uint32_t pack_half2(float f0, float f1) {
    __half2 h = __floats2half2_rn(f0, f1);
    return *(uint32_t*)&h;
}

// =============================================================
// Pre-processing
// =============================================================
__global__ void split_kernel(const float4* __restrict__ in,
                             __half* __restrict__ hi, __half* __restrict__ lo, int n4)
{
    int i = blockIdx.x * blockDim.x + threadIdx.x;
    if (i < n4) {
        float4 v = in[i];
        uint32_t h0, l0, h1, l1;
        split2(v.x, v.y, h0, l0);
        split2(v.z, v.w, h1, l1);
        *(uint2*)(hi + 4l * i) = make_uint2(h0, h1);
        *(uint2*)(lo + 4l * i) = make_uint2(l0, l1);
    }
}

__global__ void transpose_split4_kernel(const float* __restrict__ w0,
                                        const float* __restrict__ w1,
                                        const float* __restrict__ w2,
                                        const float* __restrict__ w3,
                                        __half* __restrict__ hi_base,
                                        __half* __restrict__ lo_base)
{
    __shared__ float tile[32][33];
    const float* in;
    switch (blockIdx.z) {
        case 0: in = w0; break;
        case 1: in = w1; break;
        case 2: in = w2; break;
        default: in = w3; break;
    }
    __half* hi = hi_base + (long)blockIdx.z * DMODEL * INNER;
    __half* lo = lo_base + (long)blockIdx.z * DMODEL * INNER;

    int bx = blockIdx.x * 32, by = blockIdx.y * 32;
    int x = bx + threadIdx.x;
    #pragma unroll
    for (int i = 0; i < 32; i += 8)
        tile[threadIdx.y + i][threadIdx.x] = in[(by + threadIdx.y + i) * DMODEL + x];
    __syncthreads();
    x = by + threadIdx.x;
    #pragma unroll
    for (int i = 0; i < 32; i += 8) {
        float v = tile[threadIdx.x][threadIdx.y + i];
        __half h = __float2half_rn(v);
        __half l = __float2half_rn(v - __half2float(h));
        long idx = (long)(bx + threadIdx.y + i) * DMODEL + x;
        hi[idx] = h;
        lo[idx] = l;
    }
}

__global__ void bias_table_kernel(const float* __restrict__ table)
{
    int idx = blockIdx.x * blockDim.x + threadIdx.x;
    if (idx >= RBR * NHEADS) return;
    int rel = idx / NHEADS - (SEQ - 1);
    int h   = idx % NHEADS;
    int bucket = (rel > 0) ? 16 : 0;
    int rp = rel < 0 ? -rel : rel;
    int v;
    if (rp < 8) {
        v = rp;
    } else {
        float f = logf((float)rp * 0.125f) / 2.772588722239781f * 8.0f;
        v = 8 + (int)f;
        if (v > 15) v = 15;
    }
    g_RB[idx] = table[(bucket + v) * NHEADS + h];
}

// =============================================================
// GEMM plumbing: 4-stage cp.async ring, one __syncthreads/iter.
// Stage layout: stage s at s*24576 B; Ahi +0, Alo +6144,
// Bhi +12288, Blo +18432.
// =============================================================
#define HPAD 24
#define HTILE (128 * HPAD)            // halfs per tile (3072)
#define TILE_B 6144                   // bytes per tile
#define STAGE_B 24576                 // bytes per stage (4 tiles)
#define NSTAGE 4
#define HGEMM_SMEM (NSTAGE * STAGE_B) // 98304
#define NITER (DMODEL / 16)           // 64

// =============================================================
// Fused QKV projection. Grid (24, 32): bx/8 = matrix (0 Q, 1 K,
// 2 V). Q,K: 2-MMA, hi/lo out. V: 3-MMA, transposed hi/lo out.
// Identical per-tile numerics to round 7.
// =============================================================
__global__ __launch_bounds__(256)
void qkv_kernel(const __half* __restrict__ Xhi, const __half* __restrict__ Xlo,
                const __half* __restrict__ Whi_base, const __half* __restrict__ Wlo_base,
                __half* __restrict__ Qhi, __half* __restrict__ Qlo,
                __half* __restrict__ Khi, __half* __restrict__ Klo,
                __half* __restrict__ Vthi, __half* __restrict__ Vtlo)
{
    extern __shared__ __half hsm[];
    const int mat  = blockIdx.x >> 3;         // 0 Q, 1 K, 2 V
    const bool isV = (mat == 2);
    const __half* Bhi = Whi_base + (long)mat * DMODEL * INNER;
    const __half* Blo = Wlo_base + (long)mat * DMODEL * INNER;

    const int tid  = threadIdx.x;
    const int wid  = tid >> 5;
    const int lane = tid & 31;
    const int wr   = wid & 1;
    const int wc   = wid >> 1;
    const long bm  = blockIdx.y * 128;
    const long bn  = (blockIdx.x & 7) * 128;
    const uint32_t s0 = smem_u32(hsm);

    float acc[4][4][4];
    #pragma unroll
    for (int i = 0; i < 4; i++)
        #pragma unroll
        for (int j = 0; j < 4; j++)
            #pragma unroll
            for (int k = 0; k < 4; k++) acc[i][j][k] = 0.0f;

    auto load_tiles = [&](int it, int stage) {
        int k0 = it * 16;
        int row = tid >> 1, c = tid & 1;
        uint32_t off = stage * STAGE_B + row * (HPAD * 2) + c * 16;
        long asrc = (bm + row) * (long)DMODEL + k0 + c * 8;
        long bsrc = (bn + row) * (long)DMODEL + k0 + c * 8;
        cp_async16(s0 + off,              Xhi + asrc);
        cp_async16(s0 + TILE_B + off,     Xlo + asrc);
        cp_async16(s0 + 2 * TILE_B + off, Bhi + bsrc);
        if (isV) cp_async16(s0 + 3 * TILE_B + off, Blo + bsrc);
        CP_ASYNC_COMMIT();
    };

    const int lrow  = lane & 15;
    const int lcolB = (lane >= 16) ? 16 : 0;

    load_tiles(0, 0);
    load_tiles(1, 1);
    load_tiles(2, 2);

    for (int it = 0; it < NITER; it++) {
        const int buf = it & 3;
        CP_ASYNC_WAIT(2);
        __syncthreads();
        if (it + 3 < NITER) load_tiles(it + 3, (it + 3) & 3);
        else                CP_ASYNC_COMMIT();   // keep group arithmetic exact

        const uint32_t ah = s0 + buf * STAGE_B;
        const uint32_t al = ah + TILE_B;
        const __half*  bh = hsm + (buf * STAGE_B + 2 * TILE_B) / 2;
        const __half*  bl = hsm + (buf * STAGE_B + 3 * TILE_B) / 2;

        uint32_t afh[4][4], afl[4][4];
        #pragma unroll
        for (int mt = 0; mt < 4; mt++) {
            int m = wr * 64 + mt * 16 + lrow;
            ldmatrix_x4(afh[mt], ah + m * (HPAD * 2) + lcolB);
            ldmatrix_x4(afl[mt], al + m * (HPAD * 2) + lcolB);
        }
        uint32_t bfh[4][2], bfl[4][2];
        #pragma unroll
        for (int nt = 0; nt < 4; nt++) {
            int n = wc * 32 + nt * 8 + (lane >> 2);
            int o = n * HPAD + (lane & 3) * 2;
            bfh[nt][0] = *(const uint32_t*)(bh + o);
            bfh[nt][1] = *(const uint32_t*)(bh + o + 8);
            if (isV) {
                bfl[nt][0] = *(const uint32_t*)(bl + o);
                bfl[nt][1] = *(const uint32_t*)(bl + o + 8);
            }
        }
        if (isV) {
            #pragma unroll
            for (int mt = 0; mt < 4; mt++)
                #pragma unroll
                for (int nt = 0; nt < 4; nt++) {
                    mma_f16(acc[mt][nt], afh[mt], bfh[nt]);
                    mma_f16(acc[mt][nt], afh[mt], bfl[nt]);
                    mma_f16(acc[mt][nt], afl[mt], bfh[nt]);
                }
        } else {
            #pragma unroll
            for (int mt = 0; mt < 4; mt++)
                #pragma unroll
                for (int nt = 0; nt < 4; nt++) {
                    mma_f16(acc[mt][nt], afh[mt], bfh[nt]);
                    mma_f16(acc[mt][nt], afl[mt], bfh[nt]);
                }
        }
    }

    // epilogue
    __half* Chi = (mat == 0) ? Qhi : (mat == 1) ? Khi : Vthi;
    __half* Clo = (mat == 0) ? Qlo : (mat == 1) ? Klo : Vtlo;
    #pragma unroll
    for (int mt = 0; mt < 4; mt++) {
        long m0 = bm + wr * 64 + mt * 16 + (lane >> 2);
        #pragma unroll
        for (int nt = 0; nt < 4; nt++) {
            long n0 = bn + wc * 32 + nt * 8 + (lane & 3) * 2;
            float* a = acc[mt][nt];
            if (!isV) {
                uint32_t h, l;
                split2(a[0], a[1], h, l);
                *(uint32_t*)(Chi + m0 * INNER + n0) = h;
                *(uint32_t*)(Clo + m0 * INNER + n0) = l;
                split2(a[2], a[3], h, l);
                *(uint32_t*)(Chi + (m0 + 8) * INNER + n0) = h;
                *(uint32_t*)(Clo + (m0 + 8) * INNER + n0) = l;
            } else {
                #pragma unroll
                for (int e = 0; e < 4; e++) {
                    long m = m0 + ((e >= 2) ? 8 : 0);
                    long n = n0 + (e & 1);
                    __half h = __float2half_rn(a[e]);
                    __half l = __float2half_rn(a[e] - __half2float(h));
                    Chi[n * NTOK + m] = h;
                    Clo[n * NTOK + m] = l;
                }
            }
        }
    }
}

// =============================================================
// O-projection GEMM (3-MMA, float out), same 4-stage ring.
// =============================================================
__global__ __launch_bounds__(256)
void oproj_kernel(const __half* __restrict__ Ahi, const __half* __restrict__ Alo,
                  const __half* __restrict__ Bhi, const __half* __restrict__ Blo,
                  float* __restrict__ Cf)
{
    extern __shared__ __half hsm[];
    const int tid  = threadIdx.x;
    const int wid  = tid >> 5;
    const int lane = tid & 31;
    const int wr   = wid & 1;
    const int wc   = wid >> 1;
    const long bm  = blockIdx.y * 128;
    const long bn  = blockIdx.x * 128;
    const uint32_t s0 = smem_u32(hsm);

    float acc[4][4][4];
    #pragma unroll
    for (int i = 0; i < 4; i++)
        #pragma unroll
        for (int j = 0; j < 4; j++)
            #pragma unroll
            for (int k = 0; k < 4; k++) acc[i][j][k] = 0.0f;

    auto load_tiles = [&](int it, int stage) {
        int k0 = it * 16;
        int row = tid >> 1, c = tid & 1;
        uint32_t off = stage * STAGE_B + row * (HPAD * 2) + c * 16;
        long asrc = (bm + row) * (long)DMODEL + k0 + c * 8;
        long bsrc = (bn + row) * (long)DMODEL + k0 + c * 8;
        cp_async16(s0 + off,              Ahi + asrc);
        cp_async16(s0 + TILE_B + off,     Alo + asrc);
        cp_async16(s0 + 2 * TILE_B + off, Bhi + bsrc);
        cp_async16(s0 + 3 * TILE_B + off, Blo + bsrc);
        CP_ASYNC_COMMIT();
    };

    const int lrow  = lane & 15;
    const int lcolB = (lane >= 16) ? 16 : 0;

    load_tiles(0, 0);
    load_tiles(1, 1);
    load_tiles(2, 2);

    for (int it = 0; it < NITER; it++) {
        const int buf = it & 3;
        CP_ASYNC_WAIT(2);
        __syncthreads();
        if (it + 3 < NITER) load_tiles(it + 3, (it + 3) & 3);
        else                CP_ASYNC_COMMIT();

        const uint32_t ah = s0 + buf * STAGE_B;
        const uint32_t al = ah + TILE_B;
        const __half*  bh = hsm + (buf * STAGE_B + 2 * TILE_B) / 2;
        const __half*  bl = hsm + (buf * STAGE_B + 3 * TILE_B) / 2;

        uint32_t afh[4][4], afl[4][4];
        #pragma unroll
        for (int mt = 0; mt < 4; mt++) {
            int m = wr * 64 + mt * 16 + lrow;
            ldmatrix_x4(afh[mt], ah + m * (HPAD * 2) + lcolB);
            ldmatrix_x4(afl[mt], al + m * (HPAD * 2) + lcolB);
        }
        uint32_t bfh[4][2], bfl[4][2];
        #pragma unroll
        for (int nt = 0; nt < 4; nt++) {
            int n = wc * 32 + nt * 8 + (lane >> 2);
            int o = n * HPAD + (lane & 3) * 2;
            bfh[nt][0] = *(const uint32_t*)(bh + o);
            bfh[nt][1] = *(const uint32_t*)(bh + o + 8);
            bfl[nt][0] = *(const uint32_t*)(bl + o);
            bfl[nt][1] = *(const uint32_t*)(bl + o + 8);
        }
        #pragma unroll
        for (int mt = 0; mt < 4; mt++)
            #pragma unroll
            for (int nt = 0; nt < 4; nt++) {
                mma_f16(acc[mt][nt], afh[mt], bfh[nt]);
                mma_f16(acc[mt][nt], afh[mt], bfl[nt]);
                mma_f16(acc[mt][nt], afl[mt], bfh[nt]);
            }
    }

    #pragma unroll
    for (int mt = 0; mt < 4; mt++) {
        long m0 = bm + wr * 64 + mt * 16 + (lane >> 2);
        #pragma unroll
        for (int nt = 0; nt < 4; nt++) {
            long n0 = bn + wc * 32 + nt * 8 + (lane & 3) * 2;
            float* a = acc[mt][nt];
            *(float2*)(Cf + m0 * INNER + n0)       = make_float2(a[0], a[1]);
            *(float2*)(Cf + (m0 + 8) * INNER + n0) = make_float2(a[2], a[3]);
        }
    }
}

// =============================================================
// fp16-split flash attention (identical to round 7).
// =============================================================
#define KSTAGE 27648                 // Khi, Vhi, Vlo x 9216 bytes
#define QOFF   27648                 // Q hi/lo staging, aliases stage1
#define RBOFF  (QOFF + 36864)
#define ATT_SMEM (RBOFF + 191*4)
#define KROWB 144

__global__ __launch_bounds__(128, 2)
void attn_kernel(const __half* __restrict__ Qhi, const __half* __restrict__ Qlo,
                 const __half* __restrict__ Khi,
                 const __half* __restrict__ Vthi, const __half* __restrict__ Vtlo,
                 __half* __restrict__ Chi, __half* __restrict__ Clo)
{
    extern __shared__ char smraw[];
    float* rbs = (float*)(smraw + RBOFF);
    const int tid  = threadIdx.x;
    const int w    = tid >> 5;
    const int lane = tid & 31;
    const int bh   = blockIdx.y;
    const int b    = bh >> 4;
    const int h    = bh & 15;
    const int q0   = blockIdx.x * 128;
    const uint32_t sb = smem_u32(smraw);
    const int grow = lane >> 2;
    const int gc   = (lane & 3) * 2;

    auto load_kv = [&](int t, int stage) {
        int k0 = t * 64;
        uint32_t sbase = sb + stage * KSTAGE;
        #pragma unroll
        for (int i = 0; i < 12; i++) {
            int id  = tid + i * 128;
            int sel = id >> 9;
            int wi  = id & 511;
            int row = wi >> 3, c = wi & 7;
            uint32_t dst = sbase + sel * 9216 + row * KROWB + c * 16;
            const __half* src;
            if (sel == 0) {
                src = Khi + (long)(b * SEQ + k0 + row) * INNER + h * DKV + c * 8;
            } else {
                const __half* base = (sel == 2) ? Vtlo : Vthi;
                src = base + (long)(h * DKV + row) * NTOK + b * SEQ + k0 + c * 8;
            }
            cp_async16(dst, src);
        }
        CP_ASYNC_COMMIT();
    };

    #pragma unroll
    for (int i = 0; i < 16; i++) {
        int id  = tid + i * 128;
        int sel = id >> 10;
        int wi  = id & 1023;
        int row = wi >> 3, c = wi & 7;
        uint32_t dst = sb + QOFF + sel * 18432 + row * KROWB + c * 16;
        const __half* src = (sel ? Qlo : Qhi) +
                            (long)(b * SEQ + q0 + row) * INNER + h * DKV + c * 8;
        cp_async16(dst, src);
    }
    load_kv(0, 0);
    CP_ASYNC_WAIT(0);
    __syncthreads();

    uint32_t qh[2][4][4], ql[2][4][4];
    {
        uint32_t qbh = sb + QOFF;
        uint32_t qbl = qbh + 18432;
        int cofs = (lane >= 16) ? 16 : 0;
        #pragma unroll
        for (int hf = 0; hf < 2; hf++) {
            int r = w * 32 + hf * 16 + (lane & 15);
            #pragma unroll
            for (int ks = 0; ks < 4; ks++) {
                ldmatrix_x4(qh[hf][ks], qbh + r * KROWB + ks * 32 + cofs);
                ldmatrix_x4(ql[hf][ks], qbl + r * KROWB + ks * 32 + cofs);
            }
        }
    }

    float m[2][2], l[2][2];
    float o[2][8][4];
    #pragma unroll
    for (int hf = 0; hf < 2; hf++) {
        m[hf][0] = m[hf][1] = -3.0e38f;
        l[hf][0] = l[hf][1] = 0.0f;
        #pragma unroll
        for (int nt = 0; nt < 8; nt++)
            #pragma unroll
            for (int e = 0; e < 4; e++) o[hf][nt][e] = 0.0f;
    }

    for (int t = 0; t < SEQ / 64; t++) {
        __syncthreads();
        if (t + 1 < SEQ / 64) { load_kv(t + 1, (t + 1) & 1); CP_ASYNC_WAIT(1); }
        else                  { CP_ASYNC_WAIT(0); }
        for (int i = tid; i < 191; i += 128)
            rbs[i] = g_RB[(t * 64 - q0 + i - 127 + SEQ - 1) * NHEADS + h];
        __syncthreads();

        const char* kp = smraw + (t & 1) * KSTAGE;
        const char* vh = kp + 9216;
        const char* vl = kp + 18432;

        float s[2][8][4];
        #pragma unroll
        for (int hf = 0; hf < 2; hf++)
            #pragma unroll
            for (int nt = 0; nt < 8; nt++)
                #pragma unroll
                for (int e = 0; e < 4; e++) s[hf][nt][e] = 0.0f;

        #pragma unroll
        for (int ks = 0; ks < 4; ks++) {
            #pragma unroll
            for (int nt = 0; nt < 8; nt++) {
                uint32_t off = (nt * 8 + grow) * KROWB + ks * 32 + gc * 2;
                uint32_t bh_[2];
                bh_[0] = *(const uint32_t*)(kp + off);
                bh_[1] = *(const uint32_t*)(kp + off + 16);
                mma_f16(s[0][nt], qh[0][ks], bh_);
                mma_f16(s[0][nt], ql[0][ks], bh_);
                mma_f16(s[1][nt], qh[1][ks], bh_);
                mma_f16(s[1][nt], ql[1][ks], bh_);
            }
        }

        #pragma unroll
        for (int hf = 0; hf < 2; hf++) {
            const int rb0 = 127 - (w * 32 + hf * 16 + grow);
            #pragma unroll
            for (int nt = 0; nt < 8; nt++) {
                int cb = nt * 8 + gc;
                s[hf][nt][0] += rbs[cb + rb0];
                s[hf][nt][1] += rbs[cb + 1 + rb0];
                s[hf][nt][2] += rbs[cb + rb0 - 8];
                s[hf][nt][3] += rbs[cb + 1 + rb0 - 8];
            }
            float tm0 = -3.0e38f, tm1 = -3.0e38f;
            #pragma unroll
            for (int nt = 0; nt < 8; nt++) {
                tm0 = fmaxf(tm0, fmaxf(s[hf][nt][0], s[hf][nt][1]));
                tm1 = fmaxf(tm1, fmaxf(s[hf][nt][2], s[hf][nt][3]));
            }
            tm0 = fmaxf(tm0, __shfl_xor_sync(0xffffffffu, tm0, 1));
            tm0 = fmaxf(tm0, __shfl_xor_sync(0xffffffffu, tm0, 2));
            tm1 = fmaxf(tm1, __shfl_xor_sync(0xffffffffu, tm1, 1));
            tm1 = fmaxf(tm1, __shfl_xor_sync(0xffffffffu, tm1, 2));
            float nm0 = fmaxf(m[hf][0], tm0), nm1 = fmaxf(m[hf][1], tm1);
            float sc0 = __expf(m[hf][0] - nm0), sc1 = __expf(m[hf][1] - nm1);
            float ls0 = 0.0f, ls1 = 0.0f;
            #pragma unroll
            for (int nt = 0; nt < 8; nt++) {
                s[hf][nt][0] = __expf(s[hf][nt][0] - nm0); ls0 += s[hf][nt][0];
                s[hf][nt][1] = __expf(s[hf][nt][1] - nm0); ls0 += s[hf][nt][1];
                s[hf][nt][2] = __expf(s[hf][nt][2] - nm1); ls1 += s[hf][nt][2];
                s[hf][nt][3] = __expf(s[hf][nt][3] - nm1); ls1 += s[hf][nt][3];
            }
            ls0 += __shfl_xor_sync(0xffffffffu, ls0, 1);
            ls0 += __shfl_xor_sync(0xffffffffu, ls0, 2);
            ls1 += __shfl_xor_sync(0xffffffffu, ls1, 1);
            ls1 += __shfl_xor_sync(0xffffffffu, ls1, 2);
            l[hf][0] = l[hf][0] * sc0 + ls0;
            l[hf][1] = l[hf][1] * sc1 + ls1;
            m[hf][0] = nm0;  m[hf][1] = nm1;
            #pragma unroll
            for (int nt = 0; nt < 8; nt++) {
                o[hf][nt][0] *= sc0; o[hf][nt][1] *= sc0;
                o[hf][nt][2] *= sc1; o[hf][nt][3] *= sc1;
            }
        }

        #pragma unroll
        for (int ks = 0; ks < 4; ks++) {
            uint32_t ph[2][4];
            #pragma unroll
            for (int hf = 0; hf < 2; hf++) {
                ph[hf][0] = pack_half2(s[hf][2*ks][0],   s[hf][2*ks][1]);
                ph[hf][1] = pack_half2(s[hf][2*ks][2],   s[hf][2*ks][3]);
                ph[hf][2] = pack_half2(s[hf][2*ks+1][0], s[hf][2*ks+1][1]);
                ph[hf][3] = pack_half2(s[hf][2*ks+1][2], s[hf][2*ks+1][3]);
            }
            #pragma unroll
            for (int nt = 0; nt < 8; nt++) {
                uint32_t off = (nt * 8 + grow) * KROWB + ks * 32 + gc * 2;
                uint32_t vh_[2], vl_[2];
                vh_[0] = *(const uint32_t*)(vh + off);
                vh_[1] = *(const uint32_t*)(vh + off + 16);
                vl_[0] = *(const uint32_t*)(vl + off);
                vl_[1] = *(const uint32_t*)(vl + off + 16);
                mma_f16(o[0][nt], ph[0], vh_);
                mma_f16(o[0][nt], ph[0], vl_);
                mma_f16(o[1][nt], ph[1], vh_);
                mma_f16(o[1][nt], ph[1], vl_);
            }
        }
    }

    #pragma unroll
    for (int hf = 0; hf < 2; hf++) {
        float i0 = 1.0f / l[hf][0], i1 = 1.0f / l[hf][1];
        long tok0 = (long)b * SEQ + q0 + w * 32 + hf * 16 + grow;
        #pragma unroll
        for (int nt = 0; nt < 8; nt++) {
            long col = h * DKV + nt * 8 + gc;
            uint32_t hh, ll;
            split2(o[hf][nt][0] * i0, o[hf][nt][1] * i0, hh, ll);
            *(uint32_t*)(Chi + tok0 * INNER + col) = hh;
            *(uint32_t*)(Clo + tok0 * INNER + col) = ll;
            split2(o[hf][nt][2] * i1, o[hf][nt][3] * i1, hh, ll);
            *(uint32_t*)(Chi + (tok0 + 8) * INNER + col) = hh;
            *(uint32_t*)(Clo + (tok0 + 8) * INNER + col) = ll;
        }
    }
}

// =============================================================
// Host launcher
// =============================================================
extern "C" void kernel_launch(void* const* d_in, const int* in_sizes, int n_in,
                              void* d_out, int out_size)
{
    const float* X   = (const float*)d_in[0];
    const float* wq  = (const float*)d_in[1];
    const float* wk  = (const float*)d_in[2];
    const float* wv  = (const float*)d_in[3];
    const float* wo  = (const float*)d_in[4];
    const float* rbt = (const float*)d_in[5];
    float* out = (float*)d_out;

    __half *Xhi, *Xlo, *Whi, *Wlo, *Qhi, *Qlo, *Khi, *Klo, *Vthi, *Vtlo, *Chi, *Clo;
    cudaGetSymbolAddress((void**)&Xhi,  g_Xhi);   cudaGetSymbolAddress((void**)&Xlo,  g_Xlo);
    cudaGetSymbolAddress((void**)&Whi,  g_Whi);   cudaGetSymbolAddress((void**)&Wlo,  g_Wlo);
    cudaGetSymbolAddress((void**)&Qhi,  g_Qhi);   cudaGetSymbolAddress((void**)&Qlo,  g_Qlo);
    cudaGetSymbolAddress((void**)&Khi,  g_Khi);   cudaGetSymbolAddress((void**)&Klo,  g_Klo);
    cudaGetSymbolAddress((void**)&Vthi, g_Vthi);  cudaGetSymbolAddress((void**)&Vtlo, g_Vtlo);
    cudaGetSymbolAddress((void**)&Chi,  g_Chi);   cudaGetSymbolAddress((void**)&Clo,  g_Clo);

    const long WOFF = (long)DMODEL * INNER;

    // preprocessing (3 launches)
    bias_table_kernel<<<(RBR * NHEADS + 255) / 256, 256>>>(rbt);
    split_kernel<<<(NTOK * DMODEL / 4 + 255) / 256, 256>>>(
        (const float4*)X, Xhi, Xlo, NTOK * DMODEL / 4);
    transpose_split4_kernel<<<dim3(32, 32, 4), dim3(32, 8)>>>(wq, wk, wv, wo, Whi, Wlo);

    // fused QKV projections
    cudaFuncSetAttribute(qkv_kernel, cudaFuncAttributeMaxDynamicSharedMemorySize, HGEMM_SMEM);
    qkv_kernel<<<dim3(24, 32), 256, HGEMM_SMEM>>>(Xhi, Xlo, Whi, Wlo,
                                                  Qhi, Qlo, Khi, Klo, Vthi, Vtlo);

    // attention
    cudaFuncSetAttribute(attn_kernel, cudaFuncAttributeMaxDynamicSharedMemorySize, ATT_SMEM);
    attn_kernel<<<dim3(SEQ / 128, BATCH * NHEADS), 128, ATT_SMEM>>>(
        Qhi, Qlo, Khi, Vthi, Vtlo, Chi, Clo);

    // output projection
    cudaFuncSetAttribute(oproj_kernel, cudaFuncAttributeMaxDynamicSharedMemorySize, HGEMM_SMEM);
    oproj_kernel<<<dim3(DMODEL / 128, NTOK / 128), 256, HGEMM_SMEM>>>(
        Chi, Clo, Whi + 3 * WOFF, Wlo + 3 * WOFF, out);
}

// round 9
// speedup vs baseline: 3.8144x; 1.0776x over previous
#include <cuda_runtime.h>
#include <cuda_fp16.h>
#include <math.h>
#include <stdint.h>

#define BATCH   2
#define SEQ     2048
#define DMODEL  1024
#define NHEADS  16
#define DKV     64
#define INNER   1024
#define NTOK    (BATCH*SEQ)          // 4096
#define RBR     (2*SEQ-1)            // 4095

// -------- scratch (device globals: no allocation allowed) --------
__device__ __half g_Xhi[NTOK*DMODEL],  g_Xlo[NTOK*DMODEL];
__device__ __half g_Whi[4*DMODEL*INNER], g_Wlo[4*DMODEL*INNER];
__device__ __half g_Qhi[NTOK*INNER],  g_Qlo[NTOK*INNER];
__device__ __half g_Khi[NTOK*INNER],  g_Klo[NTOK*INNER];
__device__ __half g_Vthi[NTOK*INNER], g_Vtlo[NTOK*INNER];   // transposed [n][token]
__device__ __half g_Chi[NTOK*INNER],  g_Clo[NTOK*INNER];
__device__ float  g_RB[RBR*NHEADS];

// ============================================================
// helpers
// ============================================================
__device__ __forceinline__ uint32_t smem_u32(const void* p) {
    uint32_t a;
    asm("{ .reg .u64 t; cvta.to.shared.u64 t, %1; cvt.u32.u64 %0, t; }" : "=r"(a) : "l"(p));
    return a;
}
__device__ __forceinline__ void cp_async16(uint32_t dst, const void* src) {
    asm volatile("cp.async.cg.shared.global [%0], [%1], 16;\n" :: "r"(dst), "l"(src) : "memory");
}
#define CP_ASYNC_COMMIT() asm volatile("cp.async.commit_group;\n" ::: "memory")
#define CP_ASYNC_WAIT(n)  asm volatile("cp.async.wait_group %0;\n" :: "n"(n) : "memory")

__device__ __forceinline__ void ldmatrix_x4(uint32_t* r, uint32_t addr) {
    asm volatile("ldmatrix.sync.aligned.m8n8.x4.shared.b16 {%0,%1,%2,%3}, [%4];"
                 : "=r"(r[0]), "=r"(r[1]), "=r"(r[2]), "=r"(r[3]) : "r"(addr));
}
__device__ __forceinline__ void mma_f16(float* d, const uint32_t* a, const uint32_t* b) {
    asm volatile(
        "mma.sync.aligned.m16n8k16.row.col.f32.f16.f16.f32 "
        "{%0,%1,%2,%3}, {%4,%5,%6,%7}, {%8,%9}, {%0,%1,%2,%3};"
        : "+f"(d[0]), "+f"(d[1]), "+f"(d[2]), "+f"(d[3])
        : "r"(a[0]), "r"(a[1]), "r"(a[2]), "r"(a[3]), "r"(b[0]), "r"(b[1]));
}
__device__ __forceinline__ void split2(float f0, float f1, uint32_t& hi, uint32_t& lo) {
    __half h0 = __float2half_rn(f0), h1 = __float2half_rn(f1);
    __half l0 = __float2half_rn(f0 - __half2float(h0));
    __half l1 = __float2half_rn(f1 - __half2float(h1));
    hi = (uint32_t)__half_as_ushort(h0) | ((uint32_t)__half_as_ushort(h1) << 16);
    lo = (uint32_t)__half_as_ushort(l0) | ((uint32_t)__half_as_ushort(l1) << 16);
}
__device__ __forceinline__ uint32_t pack_half2(float f0, float f1) {
    __half2 h = __floats2half2_rn(f0, f1);
    return *(uint32_t*)&h;
}

// =============================================================
// Pre-processing
// =============================================================
__global__ void split_kernel(const float4* __restrict__ in,
                             __half* __restrict__ hi, __half* __restrict__ lo, int n4)
{
    int i = blockIdx.x * blockDim.x + threadIdx.x;
    if (i < n4) {
        float4 v = in[i];
        uint32_t h0, l0, h1, l1;
        split2(v.x, v.y, h0, l0);
        split2(v.z, v.w, h1, l1);
        *(uint2*)(hi + 4l * i) = make_uint2(h0, h1);
        *(uint2*)(lo + 4l * i) = make_uint2(l0, l1);
    }
}

__global__ void transpose_split4_kernel(const float* __restrict__ w0,
                                        const float* __restrict__ w1,
                                        const float* __restrict__ w2,
                                        const float* __restrict__ w3,
                                        __half* __restrict__ hi_base,
                                        __half* __restrict__ lo_base)
{
    __shared__ float tile[32][33];
    const float* in;
    switch (blockIdx.z) {
        case 0: in = w0; break;
        case 1: in = w1; break;
        case 2: in = w2; break;
        default: in = w3; break;
    }
    __half* hi = hi_base + (long)blockIdx.z * DMODEL * INNER;
    __half* lo = lo_base + (long)blockIdx.z * DMODEL * INNER;

    int bx = blockIdx.x * 32, by = blockIdx.y * 32;
    int x = bx + threadIdx.x;
    #pragma unroll
    for (int i = 0; i < 32; i += 8)
        tile[threadIdx.y + i][threadIdx.x] = in[(by + threadIdx.y + i) * DMODEL + x];
    __syncthreads();
    x = by + threadIdx.x;
    #pragma unroll
    for (int i = 0; i < 32; i += 8) {
        float v = tile[threadIdx.x][threadIdx.y + i];
        __half h = __float2half_rn(v);
        __half l = __float2half_rn(v - __half2float(h));
        long idx = (long)(bx + threadIdx.y + i) * DMODEL + x;
        hi[idx] = h;
        lo[idx] = l;
    }
}

__global__ void bias_table_kernel(const float* __restrict__ table)
{
    int idx = blockIdx.x * blockDim.x + threadIdx.x;
    if (idx >= RBR * NHEADS) return;
    int rel = idx / NHEADS - (SEQ - 1);
    int h   = idx % NHEADS;
    int bucket = (rel > 0) ? 16 : 0;
    int rp = rel < 0 ? -rel : rel;
    int v;
    if (rp < 8) {
        v = rp;
    } else {
        float f = logf((float)rp * 0.125f) / 2.772588722239781f * 8.0f;
        v = 8 + (int)f;
        if (v > 15) v = 15;
    }
    g_RB[idx] = table[(bucket + v) * NHEADS + h];
}

// =============================================================
// GEMM plumbing: 4-stage cp.async ring, 128 threads / 4 warps,
// warp tile 64x64 (mt 4 x nt 8). Same per-acc numerics as R8.
// Stage: Ahi +0, Alo +6144, Bhi +12288, Blo +18432.
// =============================================================
#define HPAD 24
#define TILE_B 6144
#define STAGE_B 24576
#define NSTAGE 4
#define HGEMM_SMEM (NSTAGE * STAGE_B) // 98304
#define NITER (DMODEL / 16)           // 64

// =============================================================
// Fused QKV projection. Grid (24, 32), 128 threads.
// =============================================================
__global__ __launch_bounds__(128)
void qkv_kernel(const __half* __restrict__ Xhi, const __half* __restrict__ Xlo,
                const __half* __restrict__ Whi_base, const __half* __restrict__ Wlo_base,
                __half* __restrict__ Qhi, __half* __restrict__ Qlo,
                __half* __restrict__ Khi, __half* __restrict__ Klo,
                __half* __restrict__ Vthi, __half* __restrict__ Vtlo)
{
    extern __shared__ __half hsm[];
    const int mat  = blockIdx.x >> 3;         // 0 Q, 1 K, 2 V
    const bool isV = (mat == 2);
    const __half* Bhi = Whi_base + (long)mat * DMODEL * INNER;
    const __half* Blo = Wlo_base + (long)mat * DMODEL * INNER;

    const int tid  = threadIdx.x;
    const int wid  = tid >> 5;
    const int lane = tid & 31;
    const int wr   = wid & 1;                 // 2 x 64 rows
    const int wc   = wid >> 1;                // 2 x 64 cols
    const long bm  = blockIdx.y * 128;
    const long bn  = (blockIdx.x & 7) * 128;
    const uint32_t s0 = smem_u32(hsm);

    float acc[4][8][4];
    #pragma unroll
    for (int i = 0; i < 4; i++)
        #pragma unroll
        for (int j = 0; j < 8; j++)
            #pragma unroll
            for (int k = 0; k < 4; k++) acc[i][j][k] = 0.0f;

    auto load_tiles = [&](int it, int stage) {
        int k0 = it * 16;
        uint32_t sbase = s0 + stage * STAGE_B;
        #pragma unroll
        for (int i = 0; i < 6; i++) {
            int id  = tid + i * 128;          // 0..767
            int sel = id >> 8;                // 0 Ahi, 1 Alo, 2 Bhi
            int wi  = id & 255;
            int row = wi >> 1, c = wi & 1;
            uint32_t off = sel * TILE_B + row * (HPAD * 2) + c * 16;
            long ao = (bm + row) * (long)DMODEL + k0 + c * 8;
            long bo = (bn + row) * (long)DMODEL + k0 + c * 8;
            const __half* src = (sel == 0) ? Xhi + ao : (sel == 1) ? Xlo + ao : Bhi + bo;
            cp_async16(sbase + off, src);
        }
        if (isV) {
            #pragma unroll
            for (int i = 0; i < 2; i++) {
                int wi  = tid + i * 128;
                int row = wi >> 1, c = wi & 1;
                uint32_t off = 3 * TILE_B + row * (HPAD * 2) + c * 16;
                cp_async16(sbase + off, Blo + (bn + row) * (long)DMODEL + k0 + c * 8);
            }
        }
        CP_ASYNC_COMMIT();
    };

    const int lrow  = lane & 15;
    const int lcolA = (lane >= 16) ? 16 : 0;
    const int brow  = (lane & 7) + ((lane & 16) ? 8 : 0);
    const int bcol  = (lane & 8) ? 16 : 0;

    load_tiles(0, 0);
    load_tiles(1, 1);
    load_tiles(2, 2);

    for (int it = 0; it < NITER; it++) {
        const int buf = it & 3;
        CP_ASYNC_WAIT(2);
        __syncthreads();
        if (it + 3 < NITER) load_tiles(it + 3, (it + 3) & 3);
        else                CP_ASYNC_COMMIT();

        const uint32_t ah  = s0 + buf * STAGE_B;
        const uint32_t al  = ah + TILE_B;
        const uint32_t bhB = ah + 2 * TILE_B;
        const uint32_t blB = ah + 3 * TILE_B;

        uint32_t afh[4][4], afl[4][4];
        #pragma unroll
        for (int mt = 0; mt < 4; mt++) {
            int m = wr * 64 + mt * 16 + lrow;
            ldmatrix_x4(afh[mt], ah + m * (HPAD * 2) + lcolA);
            ldmatrix_x4(afl[mt], al + m * (HPAD * 2) + lcolA);
        }
        // B frags via ldmatrix: pair p covers nt=2p (regs 0,1) and nt=2p+1 (regs 2,3)
        uint32_t bfh[4][4], bfl[4][4];
        #pragma unroll
        for (int p = 0; p < 4; p++) {
            int n = wc * 64 + p * 16 + brow;
            ldmatrix_x4(bfh[p], bhB + n * (HPAD * 2) + bcol);
            if (isV) ldmatrix_x4(bfl[p], blB + n * (HPAD * 2) + bcol);
        }
        if (isV) {
            #pragma unroll
            for (int mt = 0; mt < 4; mt++)
                #pragma unroll
                for (int p = 0; p < 4; p++)
                    #pragma unroll
                    for (int sub = 0; sub < 2; sub++) {
                        float* a = acc[mt][2 * p + sub];
                        mma_f16(a, afh[mt], &bfh[p][sub * 2]);
                        mma_f16(a, afh[mt], &bfl[p][sub * 2]);
                        mma_f16(a, afl[mt], &bfh[p][sub * 2]);
                    }
        } else {
            #pragma unroll
            for (int mt = 0; mt < 4; mt++)
                #pragma unroll
                for (int p = 0; p < 4; p++)
                    #pragma unroll
                    for (int sub = 0; sub < 2; sub++) {
                        float* a = acc[mt][2 * p + sub];
                        mma_f16(a, afh[mt], &bfh[p][sub * 2]);
                        mma_f16(a, afl[mt], &bfh[p][sub * 2]);
                    }
        }
    }

    // epilogue
    __half* Chi = (mat == 0) ? Qhi : (mat == 1) ? Khi : Vthi;
    __half* Clo = (mat == 0) ? Qlo : (mat == 1) ? Klo : Vtlo;
    #pragma unroll
    for (int mt = 0; mt < 4; mt++) {
        long m0 = bm + wr * 64 + mt * 16 + (lane >> 2);
        #pragma unroll
        for (int nt = 0; nt < 8; nt++) {
            long n0 = bn + wc * 64 + nt * 8 + (lane & 3) * 2;
            float* a = acc[mt][nt];
            if (!isV) {
                uint32_t h, l;
                split2(a[0], a[1], h, l);
                *(uint32_t*)(Chi + m0 * INNER + n0) = h;
                *(uint32_t*)(Clo + m0 * INNER + n0) = l;
                split2(a[2], a[3], h, l);
                *(uint32_t*)(Chi + (m0 + 8) * INNER + n0) = h;
                *(uint32_t*)(Clo + (m0 + 8) * INNER + n0) = l;
            } else {
                #pragma unroll
                for (int e = 0; e < 4; e++) {
                    long m = m0 + ((e >= 2) ? 8 : 0);
                    long n = n0 + (e & 1);
                    __half h = __float2half_rn(a[e]);
                    __half l = __float2half_rn(a[e] - __half2float(h));
                    Chi[n * NTOK + m] = h;
                    Clo[n * NTOK + m] = l;
                }
            }
        }
    }
}

// =============================================================
// O-projection GEMM (3-MMA, float out), same structure.
// =============================================================
__global__ __launch_bounds__(128)
void oproj_kernel(const __half* __restrict__ Ahi, const __half* __restrict__ Alo,
                  const __half* __restrict__ Bhi, const __half* __restrict__ Blo,
                  float* __restrict__ Cf)
{
    extern __shared__ __half hsm[];
    const int tid  = threadIdx.x;
    const int wid  = tid >> 5;
    const int lane = tid & 31;
    const int wr   = wid & 1;
    const int wc   = wid >> 1;
    const long bm  = blockIdx.y * 128;
    const long bn  = blockIdx.x * 128;
    const uint32_t s0 = smem_u32(hsm);

    float acc[4][8][4];
    #pragma unroll
    for (int i = 0; i < 4; i++)
        #pragma unroll
        for (int j = 0; j < 8; j++)
            #pragma unroll
            for (int k = 0; k < 4; k++) acc[i][j][k] = 0.0f;

    auto load_tiles = [&](int it, int stage) {
        int k0 = it * 16;
        uint32_t sbase = s0 + stage * STAGE_B;
        #pragma unroll
        for (int i = 0; i < 8; i++) {
            int id  = tid + i * 128;          // 0..1023
            int sel = id >> 8;                // 0 Ahi, 1 Alo, 2 Bhi, 3 Blo
            int wi  = id & 255;
            int row = wi >> 1, c = wi & 1;
            uint32_t off = sel * TILE_B + row * (HPAD * 2) + c * 16;
            long ao = (bm + row) * (long)DMODEL + k0 + c * 8;
            long bo = (bn + row) * (long)DMODEL + k0 + c * 8;
            const __half* src = (sel == 0) ? Ahi + ao : (sel == 1) ? Alo + ao
                              : (sel == 2) ? Bhi + bo : Blo + bo;
            cp_async16(sbase + off, src);
        }
        CP_ASYNC_COMMIT();
    };

    const int lrow  = lane & 15;
    const int lcolA = (lane >= 16) ? 16 : 0;
    const int brow  = (lane & 7) + ((lane & 16) ? 8 : 0);
    const int bcol  = (lane & 8) ? 16 : 0;

    load_tiles(0, 0);
    load_tiles(1, 1);
    load_tiles(2, 2);

    for (int it = 0; it < NITER; it++) {
        const int buf = it & 3;
        CP_ASYNC_WAIT(2);
        __syncthreads();
        if (it + 3 < NITER) load_tiles(it + 3, (it + 3) & 3);
        else                CP_ASYNC_COMMIT();

        const uint32_t ah  = s0 + buf * STAGE_B;
        const uint32_t al  = ah + TILE_B;
        const uint32_t bhB = ah + 2 * TILE_B;
        const uint32_t blB = ah + 3 * TILE_B;

        uint32_t afh[4][4], afl[4][4];
        #pragma unroll
        for (int mt = 0; mt < 4; mt++) {
            int m = wr * 64 + mt * 16 + lrow;
            ldmatrix_x4(afh[mt], ah + m * (HPAD * 2) + lcolA);
            ldmatrix_x4(afl[mt], al + m * (HPAD * 2) + lcolA);
        }
        uint32_t bfh[4][4], bfl[4][4];
        #pragma unroll
        for (int p = 0; p < 4; p++) {
            int n = wc * 64 + p * 16 + brow;
            ldmatrix_x4(bfh[p], bhB + n * (HPAD * 2) + bcol);
            ldmatrix_x4(bfl[p], blB + n * (HPAD * 2) + bcol);
        }
        #pragma unroll
        for (int mt = 0; mt < 4; mt++)
            #pragma unroll
            for (int p = 0; p < 4; p++)
                #pragma unroll
                for (int sub = 0; sub < 2; sub++) {
                    float* a = acc[mt][2 * p + sub];
                    mma_f16(a, afh[mt], &bfh[p][sub * 2]);
                    mma_f16(a, afh[mt], &bfl[p][sub * 2]);
                    mma_f16(a, afl[mt], &bfh[p][sub * 2]);
                }
    }

    #pragma unroll
    for (int mt = 0; mt < 4; mt++) {
        long m0 = bm + wr * 64 + mt * 16 + (lane >> 2);
        #pragma unroll
        for (int nt = 0; nt < 8; nt++) {
            long n0 = bn + wc * 64 + nt * 8 + (lane & 3) * 2;
            float* a = acc[mt][nt];
            *(float2*)(Cf + m0 * INNER + n0)       = make_float2(a[0], a[1]);
            *(float2*)(Cf + (m0 + 8) * INNER + n0) = make_float2(a[2], a[3]);
        }
    }
}

// =============================================================
// fp16-split flash attention (identical to round 8).
// =============================================================
#define KSTAGE 27648
#define QOFF   27648
#define RBOFF  (QOFF + 36864)
#define ATT_SMEM (RBOFF + 191*4)
#define KROWB 144

__global__ __launch_bounds__(128, 2)
void attn_kernel(const __half* __restrict__ Qhi, const __half* __restrict__ Qlo,
                 const __half* __restrict__ Khi,
                 const __half* __restrict__ Vthi, const __half* __restrict__ Vtlo,
                 __half* __restrict__ Chi, __half* __restrict__ Clo)
{
    extern __shared__ char smraw[];
    float* rbs = (float*)(smraw + RBOFF);
    const int tid  = threadIdx.x;
    const int w    = tid >> 5;
    const int lane = tid & 31;
    const int bh   = blockIdx.y;
    const int b    = bh >> 4;
    const int h    = bh & 15;
    const int q0   = blockIdx.x * 128;
    const uint32_t sb = smem_u32(smraw);
    const int grow = lane >> 2;
    const int gc   = (lane & 3) * 2;

    auto load_kv = [&](int t, int stage) {
        int k0 = t * 64;
        uint32_t sbase = sb + stage * KSTAGE;
        #pragma unroll
        for (int i = 0; i < 12; i++) {
            int id  = tid + i * 128;
            int sel = id >> 9;
            int wi  = id & 511;
            int row = wi >> 3, c = wi & 7;
            uint32_t dst = sbase + sel * 9216 + row * KROWB + c * 16;
            const __half* src;
            if (sel == 0) {
                src = Khi + (long)(b * SEQ + k0 + row) * INNER + h * DKV + c * 8;
            } else {
                const __half* base = (sel == 2) ? Vtlo : Vthi;
                src = base + (long)(h * DKV + row) * NTOK + b * SEQ + k0 + c * 8;
            }
            cp_async16(dst, src);
        }
        CP_ASYNC_COMMIT();
    };

    #pragma unroll
    for (int i = 0; i < 16; i++) {
        int id  = tid + i * 128;
        int sel = id >> 10;
        int wi  = id & 1023;
        int row = wi >> 3, c = wi & 7;
        uint32_t dst = sb + QOFF + sel * 18432 + row * KROWB + c * 16;
        const __half* src = (sel ? Qlo : Qhi) +
                            (long)(b * SEQ + q0 + row) * INNER + h * DKV + c * 8;
        cp_async16(dst, src);
    }
    load_kv(0, 0);
    CP_ASYNC_WAIT(0);
    __syncthreads();

    uint32_t qh[2][4][4], ql[2][4][4];
    {
        uint32_t qbh = sb + QOFF;
        uint32_t qbl = qbh + 18432;
        int cofs = (lane >= 16) ? 16 : 0;
        #pragma unroll
        for (int hf = 0; hf < 2; hf++) {
            int r = w * 32 + hf * 16 + (lane & 15);
            #pragma unroll
            for (int ks = 0; ks < 4; ks++) {
                ldmatrix_x4(qh[hf][ks], qbh + r * KROWB + ks * 32 + cofs);
                ldmatrix_x4(ql[hf][ks], qbl + r * KROWB + ks * 32 + cofs);
            }
        }
    }

    float m[2][2], l[2][2];
    float o[2][8][4];
    #pragma unroll
    for (int hf = 0; hf < 2; hf++) {
        m[hf][0] = m[hf][1] = -3.0e38f;
        l[hf][0] = l[hf][1] = 0.0f;
        #pragma unroll
        for (int nt = 0; nt < 8; nt++)
            #pragma unroll
            for (int e = 0; e < 4; e++) o[hf][nt][e] = 0.0f;
    }

    for (int t = 0; t < SEQ / 64; t++) {
        __syncthreads();
        if (t + 1 < SEQ / 64) { load_kv(t + 1, (t + 1) & 1); CP_ASYNC_WAIT(1); }
        else                  { CP_ASYNC_WAIT(0); }
        for (int i = tid; i < 191; i += 128)
            rbs[i] = g_RB[(t * 64 - q0 + i - 127 + SEQ - 1) * NHEADS + h];
        __syncthreads();

        const char* kp = smraw + (t & 1) * KSTAGE;
        const char* vh = kp + 9216;
        const char* vl = kp + 18432;

        float s[2][8][4];
        #pragma unroll
        for (int hf = 0; hf < 2; hf++)
            #pragma unroll
            for (int nt = 0; nt < 8; nt++)
                #pragma unroll
                for (int e = 0; e < 4; e++) s[hf][nt][e] = 0.0f;

        #pragma unroll
        for (int ks = 0; ks < 4; ks++) {
            #pragma unroll
            for (int nt = 0; nt < 8; nt++) {
                uint32_t off = (nt * 8 + grow) * KROWB + ks * 32 + gc * 2;
                uint32_t bh_[2];
                bh_[0] = *(const uint32_t*)(kp + off);
                bh_[1] = *(const uint32_t*)(kp + off + 16);
                mma_f16(s[0][nt], qh[0][ks], bh_);
                mma_f16(s[0][nt], ql[0][ks], bh_);
                mma_f16(s[1][nt], qh[1][ks], bh_);
                mma_f16(s[1][nt], ql[1][ks], bh_);
            }
        }

        #pragma unroll
        for (int hf = 0; hf < 2; hf++) {
            const int rb0 = 127 - (w * 32 + hf * 16 + grow);
            #pragma unroll
            for (int nt = 0; nt < 8; nt++) {
                int cb = nt * 8 + gc;
                s[hf][nt][0] += rbs[cb + rb0];
                s[hf][nt][1] += rbs[cb + 1 + rb0];
                s[hf][nt][2] += rbs[cb + rb0 - 8];
                s[hf][nt][3] += rbs[cb + 1 + rb0 - 8];
            }
            float tm0 = -3.0e38f, tm1 = -3.0e38f;
            #pragma unroll
            for (int nt = 0; nt < 8; nt++) {
                tm0 = fmaxf(tm0, fmaxf(s[hf][nt][0], s[hf][nt][1]));
                tm1 = fmaxf(tm1, fmaxf(s[hf][nt][2], s[hf][nt][3]));
            }
            tm0 = fmaxf(tm0, __shfl_xor_sync(0xffffffffu, tm0, 1));
            tm0 = fmaxf(tm0, __shfl_xor_sync(0xffffffffu, tm0, 2));
            tm1 = fmaxf(tm1, __shfl_xor_sync(0xffffffffu, tm1, 1));
            tm1 = fmaxf(tm1, __shfl_xor_sync(0xffffffffu, tm1, 2));
            float nm0 = fmaxf(m[hf][0], tm0), nm1 = fmaxf(m[hf][1], tm1);
            float sc0 = __expf(m[hf][0] - nm0), sc1 = __expf(m[hf][1] - nm1);
            float ls0 = 0.0f, ls1 = 0.0f;
            #pragma unroll
            for (int nt = 0; nt < 8; nt++) {
                s[hf][nt][0] = __expf(s[hf][nt][0] - nm0); ls0 += s[hf][nt][0];
                s[hf][nt][1] = __expf(s[hf][nt][1] - nm0); ls0 += s[hf][nt][1];
                s[hf][nt][2] = __expf(s[hf][nt][2] - nm1); ls1 += s[hf][nt][2];
                s[hf][nt][3] = __expf(s[hf][nt][3] - nm1); ls1 += s[hf][nt][3];
            }
            ls0 += __shfl_xor_sync(0xffffffffu, ls0, 1);
            ls0 += __shfl_xor_sync(0xffffffffu, ls0, 2);
            ls1 += __shfl_xor_sync(0xffffffffu, ls1, 1);
            ls1 += __shfl_xor_sync(0xffffffffu, ls1, 2);
            l[hf][0] = l[hf][0] * sc0 + ls0;
            l[hf][1] = l[hf][1] * sc1 + ls1;
            m[hf][0] = nm0;  m[hf][1] = nm1;
            #pragma unroll
            for (int nt = 0; nt < 8; nt++) {
                o[hf][nt][0] *= sc0; o[hf][nt][1] *= sc0;
                o[hf][nt][2] *= sc1; o[hf][nt][3] *= sc1;
            }
        }

        #pragma unroll
        for (int ks = 0; ks < 4; ks++) {
            uint32_t ph[2][4];
            #pragma unroll
            for (int hf = 0; hf < 2; hf++) {
                ph[hf][0] = pack_half2(s[hf][2*ks][0],   s[hf][2*ks][1]);
                ph[hf][1] = pack_half2(s[hf][2*ks][2],   s[hf][2*ks][3]);
                ph[hf][2] = pack_half2(s[hf][2*ks+1][0], s[hf][2*ks+1][1]);
                ph[hf][3] = pack_half2(s[hf][2*ks+1][2], s[hf][2*ks+1][3]);
            }
            #pragma unroll
            for (int nt = 0; nt < 8; nt++) {
                uint32_t off = (nt * 8 + grow) * KROWB + ks * 32 + gc * 2;
                uint32_t vh_[2], vl_[2];
                vh_[0] = *(const uint32_t*)(vh + off);
                vh_[1] = *(const uint32_t*)(vh + off + 16);
                vl_[0] = *(const uint32_t*)(vl + off);
                vl_[1] = *(const uint32_t*)(vl + off + 16);
                mma_f16(o[0][nt], ph[0], vh_);
                mma_f16(o[0][nt], ph[0], vl_);
                mma_f16(o[1][nt], ph[1], vh_);
                mma_f16(o[1][nt], ph[1], vl_);
            }
        }
    }

    #pragma unroll
    for (int hf = 0; hf < 2; hf++) {
        float i0 = 1.0f / l[hf][0], i1 = 1.0f / l[hf][1];
        long tok0 = (long)b * SEQ + q0 + w * 32 + hf * 16 + grow;
        #pragma unroll
        for (int nt = 0; nt < 8; nt++) {
            long col = h * DKV + nt * 8 + gc;
            uint32_t hh, ll;
            split2(o[hf][nt][0] * i0, o[hf][nt][1] * i0, hh, ll);
            *(uint32_t*)(Chi + tok0 * INNER + col) = hh;
            *(uint32_t*)(Clo + tok0 * INNER + col) = ll;
            split2(o[hf][nt][2] * i1, o[hf][nt][3] * i1, hh, ll);
            *(uint32_t*)(Chi + (tok0 + 8) * INNER + col) = hh;
            *(uint32_t*)(Clo + (tok0 + 8) * INNER + col) = ll;
        }
    }
}

// =============================================================
// Host launcher
// =============================================================
extern "C" void kernel_launch(void* const* d_in, const int* in_sizes, int n_in,
                              void* d_out, int out_size)
{
    const float* X   = (const float*)d_in[0];
    const float* wq  = (const float*)d_in[1];
    const float* wk  = (const float*)d_in[2];
    const float* wv  = (const float*)d_in[3];
    const float* wo  = (const float*)d_in[4];
    const float* rbt = (const float*)d_in[5];
    float* out = (float*)d_out;

    __half *Xhi, *Xlo, *Whi, *Wlo, *Qhi, *Qlo, *Khi, *Klo, *Vthi, *Vtlo, *Chi, *Clo;
    cudaGetSymbolAddress((void**)&Xhi,  g_Xhi);   cudaGetSymbolAddress((void**)&Xlo,  g_Xlo);
    cudaGetSymbolAddress((void**)&Whi,  g_Whi);   cudaGetSymbolAddress((void**)&Wlo,  g_Wlo);
    cudaGetSymbolAddress((void**)&Qhi,  g_Qhi);   cudaGetSymbolAddress((void**)&Qlo,  g_Qlo);
    cudaGetSymbolAddress((void**)&Khi,  g_Khi);   cudaGetSymbolAddress((void**)&Klo,  g_Klo);
    cudaGetSymbolAddress((void**)&Vthi, g_Vthi);  cudaGetSymbolAddress((void**)&Vtlo, g_Vtlo);
    cudaGetSymbolAddress((void**)&Chi,  g_Chi);   cudaGetSymbolAddress((void**)&Clo,  g_Clo);

    const long WOFF = (long)DMODEL * INNER;

    // preprocessing
    bias_table_kernel<<<(RBR * NHEADS + 255) / 256, 256>>>(rbt);
    split_kernel<<<(NTOK * DMODEL / 4 + 255) / 256, 256>>>(
        (const float4*)X, Xhi, Xlo, NTOK * DMODEL / 4);
    transpose_split4_kernel<<<dim3(32, 32, 4), dim3(32, 8)>>>(wq, wk, wv, wo, Whi, Wlo);

    // fused QKV projections (128 threads, 64x64 warp tiles)
    cudaFuncSetAttribute(qkv_kernel, cudaFuncAttributeMaxDynamicSharedMemorySize, HGEMM_SMEM);
    qkv_kernel<<<dim3(24, 32), 128, HGEMM_SMEM>>>(Xhi, Xlo, Whi, Wlo,
                                                  Qhi, Qlo, Khi, Klo, Vthi, Vtlo);

    // attention
    cudaFuncSetAttribute(attn_kernel, cudaFuncAttributeMaxDynamicSharedMemorySize, ATT_SMEM);
    attn_kernel<<<dim3(SEQ / 128, BATCH * NHEADS), 128, ATT_SMEM>>>(
        Qhi, Qlo, Khi, Vthi, Vtlo, Chi, Clo);

    // output projection
    cudaFuncSetAttribute(oproj_kernel, cudaFuncAttributeMaxDynamicSharedMemorySize, HGEMM_SMEM);
    oproj_kernel<<<dim3(DMODEL / 128, NTOK / 128), 128, HGEMM_SMEM>>>(
        Chi, Clo, Whi + 3 * WOFF, Wlo + 3 * WOFF, out);
}